// round 8
// baseline (speedup 1.0000x reference)
#include <cuda_runtime.h>
#include <math.h>

#define S_LEN 16
#define BSZ   64
#define NN    10000
#define LL    128
#define DMSG  129
#define DH    257
#define SCALE 0.08838834764831844f  // 1/sqrt(128)
#define TILE_N 50
#define NP    200                    // NN / TILE_N
#define XR    260                    // padded X rows
#define GR    512                    // packed gate rows
#define NBLK  148
#define NTHR  256
#define NWARP (NBLK * 8)             // 1184

// ---------------- device state ----------------------------------------------------
__device__ float g_mem[NN * LL];
__device__ int   g_dirty[NN];
__device__ float g_X[XR * 128];
__device__ float g_Gp[GR * XR];
__device__ float g_bias[GR];
__device__ float g_gates[GR * 128];
__device__ float g_ck[BSZ * DH];
__device__ float g_qbk[BSZ];
__device__ float g_memdot[NN];
__device__ float4 g_part[BSZ * NP];
__device__ float g_cv[DH];
__device__ float g_cvc;
__device__ float g_enc0[LL];
__device__ unsigned g_count;
__device__ volatile unsigned g_gen;

// ---------------- grid-wide software barrier (all CTAs resident) ------------------
__device__ __forceinline__ void gsync() {
    __threadfence();
    __syncthreads();
    if (threadIdx.x == 0) {
        unsigned gen = g_gen;
        if (atomicAdd(&g_count, 1) == NBLK - 1) {
            g_count = 0;
            __threadfence();
            g_gen = gen + 1;
        } else {
            while (g_gen == gen) { }
            __threadfence();
        }
    }
    __syncthreads();
}

// ---------------- GRU epilogue from gates column ----------------------------------
__device__ __forceinline__ float gru_cell(int c, int j) {
    float srz = g_gates[j * 128 + c];
    float szz = g_gates[(128 + j) * 128 + c];
    float gin = g_gates[(256 + j) * 128 + c];
    float ghn = g_gates[(384 + j) * 128 + c];
    float h   = g_X[(DMSG + j) * 128 + c];
    float r = 1.0f / (1.0f + __expf(-(srz + g_bias[j])));
    float z = 1.0f / (1.0f + __expf(-(szz + g_bias[128 + j])));
    float n = tanhf(fmaf(r, ghn + g_bias[384 + j], gin + g_bias[256 + j]));
    return fmaf(z, h - n, n);
}

// ---------------- prep: build X column for cell c of step sp (warp) ---------------
__device__ __forceinline__ void prep_warp(
        int sp, int c, int lane,
        const float* __restrict__ x, const float* __restrict__ t,
        const int* __restrict__ src, const int* __restrict__ tgt,
        const float* __restrict__ time_w, const float* __restrict__ time_b) {
    int b = c & 63, is_t = c >> 6;
    int node = (is_t ? tgt : src)[sp * BSZ + b];
    long base = ((long)(sp * BSZ + b)) * NN + node;
    float tv = __ldg(t + base);
    if (lane == 0) g_X[c] = __ldg(x + base);
#pragma unroll
    for (int j = 0; j < 4; j++) {
        int l = j * 32 + lane;
        g_X[(1 + l) * 128 + c] = cosf(fmaf(tv, __ldg(time_w + l), __ldg(time_b + l)));
        g_X[(DMSG + l) * 128 + c] = g_mem[node * LL + l];
    }
}

// ---------------- combine: merge NP softmax partials for batch b (warp) -----------
__device__ __forceinline__ void combine_warp(float* __restrict__ out, int cs, int b, int lane) {
    float m = -1e30f, Z = 0.0f, V = 0.0f;
    for (int i = lane; i < NP; i += 32) {
        float4 p = g_part[b * NP + i];
        if (p.x > m) {
            float sc = __expf(m - p.x);
            Z = fmaf(Z, sc, p.y);
            V = fmaf(V, sc, p.z);
            m = p.x;
        } else {
            float e = __expf(p.x - m);
            Z = fmaf(p.y, e, Z);
            V = fmaf(p.z, e, V);
        }
    }
#pragma unroll
    for (int o = 16; o; o >>= 1) {
        float om = __shfl_xor_sync(0xffffffffu, m, o);
        float oZ = __shfl_xor_sync(0xffffffffu, Z, o);
        float oV = __shfl_xor_sync(0xffffffffu, V, o);
        float M = fmaxf(m, om);
        float e1 = __expf(m - M), e2 = __expf(om - M);
        Z = fmaf(Z, e1, oZ * e2);
        V = fmaf(V, e1, oV * e2);
        m = M;
    }
    if (lane == 0) out[cs * BSZ + b] = V / Z + g_cvc;
}

// ---------------- gates GEMM: 2 rows x 128 cells per warp -------------------------
__device__ __forceinline__ void gemm2(int j0, int lane) {
    int D4, xoff;
    if (j0 < 256)      { D4 = 65; xoff = 0; }
    else if (j0 < 384) { D4 = 33; xoff = 0; }
    else               { D4 = 32; xoff = DMSG; }

    const float4* gp0 = (const float4*)(g_Gp + (j0 + 0) * XR);
    const float4* gp1 = (const float4*)(g_Gp + (j0 + 1) * XR);
    const float4* xp  = (const float4*)(g_X + xoff * 128) + lane;

    float4 a0 = {0, 0, 0, 0}, a1 = {0, 0, 0, 0};
#pragma unroll 4
    for (int q = 0; q < D4; q++) {
        float4 w0 = __ldg(gp0 + q);
        float4 w1 = __ldg(gp1 + q);
        float4 x0 = __ldg(xp + (4 * q + 0) * 32);
        float4 x1 = __ldg(xp + (4 * q + 1) * 32);
        float4 x2 = __ldg(xp + (4 * q + 2) * 32);
        float4 x3 = __ldg(xp + (4 * q + 3) * 32);
#define F4(acc, ws) \
        acc.x = fmaf(ws.x, x0.x, acc.x); acc.y = fmaf(ws.x, x0.y, acc.y); \
        acc.z = fmaf(ws.x, x0.z, acc.z); acc.w = fmaf(ws.x, x0.w, acc.w); \
        acc.x = fmaf(ws.y, x1.x, acc.x); acc.y = fmaf(ws.y, x1.y, acc.y); \
        acc.z = fmaf(ws.y, x1.z, acc.z); acc.w = fmaf(ws.y, x1.w, acc.w); \
        acc.x = fmaf(ws.z, x2.x, acc.x); acc.y = fmaf(ws.z, x2.y, acc.y); \
        acc.z = fmaf(ws.z, x2.z, acc.z); acc.w = fmaf(ws.z, x2.w, acc.w); \
        acc.x = fmaf(ws.w, x3.x, acc.x); acc.y = fmaf(ws.w, x3.y, acc.y); \
        acc.z = fmaf(ws.w, x3.z, acc.z); acc.w = fmaf(ws.w, x3.w, acc.w);
        F4(a0, w0) F4(a1, w1)
#undef F4
    }
    ((float4*)(g_gates + (j0 + 0) * 128))[lane] = a0;
    ((float4*)(g_gates + (j0 + 1) * 128))[lane] = a1;
}

// ---------------- scores task: one (tile, b) per warp ------------------------------
__device__ __forceinline__ void scores_task(
        int tile, int b, int lane, int s,
        const float* __restrict__ x, const float* __restrict__ t,
        const int* __restrict__ mask,
        const float tw[4], const float tc[4], const float cvd[4], float cv0) {
    int n0 = tile * TILE_N;
    long base = ((long)(s * BSZ + b)) * NN;

    int nA = n0 + lane;
    int nB = n0 + 32 + ((lane < 18) ? lane : 17);
    float tA = __ldg(t + base + nA),    tB = __ldg(t + base + nB);
    int   mA = __ldg(mask + base + nA), mB = __ldg(mask + base + nB);
    float xA = __ldg(x + base + nA),    xB = __ldg(x + base + nB);
    int   dA = g_dirty[nA],             dB = g_dirty[nB];
    float mdA = g_memdot[nA],           mdB = g_memdot[nB];

    float ckd[4], ckm[4];
#pragma unroll
    for (int j = 0; j < 4; j++) {
        int l = j * 32 + lane;
        ckd[j] = g_ck[b * DH + 1 + LL + l];
        ckm[j] = g_ck[b * DH + 1 + l];
    }
    float ck0 = g_ck[b * DH];
    float qbk = g_qbk[b];

    float m = -1e30f, Z = 0.0f, V1 = 0.0f;
    float acc0 = 0.f, acc1 = 0.f, acc2 = 0.f, acc3 = 0.f;

#pragma unroll 2
    for (int r = 0; r < TILE_N; r++) {
        bool grpA = (r < 32);
        int idx = grpA ? r : (r - 32);
        int mr = __shfl_sync(0xffffffffu, grpA ? mA : mB, idx);
        if (!mr) continue;
        float tv = __shfl_sync(0xffffffffu, grpA ? tA : tB, idx);
        int dirty = __shfl_sync(0xffffffffu, grpA ? dA : dB, idx);

        float cw0 = __cosf(fmaf(tv, tw[0], tc[0]));
        float cw1 = __cosf(fmaf(tv, tw[1], tc[1]));
        float cw2 = __cosf(fmaf(tv, tw[2], tc[2]));
        float cw3 = __cosf(fmaf(tv, tw[3], tc[3]));
        float sp = ckd[0] * cw0;
        sp = fmaf(ckd[1], cw1, sp);
        sp = fmaf(ckd[2], cw2, sp);
        sp = fmaf(ckd[3], cw3, sp);
        if (dirty) {
            const float* mr_ = g_mem + (long)(n0 + r) * LL;
            sp = fmaf(ckm[0], __ldg(mr_ + lane), sp);
            sp = fmaf(ckm[1], __ldg(mr_ + 32 + lane), sp);
            sp = fmaf(ckm[2], __ldg(mr_ + 64 + lane), sp);
            sp = fmaf(ckm[3], __ldg(mr_ + 96 + lane), sp);
        }
#pragma unroll
        for (int o = 16; o; o >>= 1) sp += __shfl_xor_sync(0xffffffffu, sp, o);

        float xr  = __shfl_sync(0xffffffffu, grpA ? xA : xB, idx);
        float mdr = __shfl_sync(0xffffffffu, grpA ? mdA : mdB, idx);
        float sc = fmaf(ck0, xr, sp) + qbk;
        float val = fmaf(cv0, xr, mdr);

        if (sc > m) {
            float sca = __expf(m - sc);
            Z = fmaf(Z, sca, 1.0f);
            V1 = fmaf(V1, sca, val);
            acc0 = fmaf(acc0, sca, cw0);
            acc1 = fmaf(acc1, sca, cw1);
            acc2 = fmaf(acc2, sca, cw2);
            acc3 = fmaf(acc3, sca, cw3);
            m = sc;
        } else {
            float e = __expf(sc - m);
            Z += e;
            V1 = fmaf(e, val, V1);
            acc0 = fmaf(e, cw0, acc0);
            acc1 = fmaf(e, cw1, acc1);
            acc2 = fmaf(e, cw2, acc2);
            acc3 = fmaf(e, cw3, acc3);
        }
    }

    float w = cvd[0] * acc0;
    w = fmaf(cvd[1], acc1, w);
    w = fmaf(cvd[2], acc2, w);
    w = fmaf(cvd[3], acc3, w);
#pragma unroll
    for (int o = 16; o; o >>= 1) w += __shfl_xor_sync(0xffffffffu, w, o);

    if (lane == 0)
        g_part[b * NP + tile] = make_float4(m, Z, V1 + w, 0.0f);
}

// ---------------- the persistent kernel -------------------------------------------
__global__ void __launch_bounds__(NTHR) k_persist(
        const float* __restrict__ x, const float* __restrict__ t,
        const int* __restrict__ src, const int* __restrict__ tgt,
        const int* __restrict__ mask,
        const float* __restrict__ time_w, const float* __restrict__ time_b,
        const float* __restrict__ W_ih, const float* __restrict__ W_hh,
        const float* __restrict__ b_ih, const float* __restrict__ b_hh,
        const float* __restrict__ Wq, const float* __restrict__ bq,
        const float* __restrict__ Wk, const float* __restrict__ bk,
        const float* __restrict__ Wv, const float* __restrict__ bv,
        const float* __restrict__ W_out, const float* __restrict__ b_out,
        float* __restrict__ out) {
    __shared__ int s_nodes[128];
    __shared__ float s_red[4];
    __shared__ float s_th[DH];
    __shared__ float s_qp[2][LL];
    __shared__ float s_q[LL];
    __shared__ int s_win;

    int tid = threadIdx.x;
    int lane = tid & 31, wid = tid >> 5;
    int gw = blockIdx.x * 8 + wid;
    int gtid = blockIdx.x * NTHR + tid;
    const int nthr = NBLK * NTHR;

    // ================= init phase =================
    for (int i = gtid; i < NN * LL; i += nthr) g_mem[i] = 0.0f;
    for (int i = gtid; i < NN; i += nthr) { g_dirty[i] = 0; g_memdot[i] = 0.0f; }
    for (int i = gtid; i < XR * 128; i += nthr) g_X[i] = 0.0f;
    for (int i = gtid; i < GR * XR; i += nthr) {
        int j = i / XR, d = i - j * XR;
        float v = 0.0f;
        if (j < 256) {
            if (d < DMSG) v = W_ih[j * DMSG + d];
            else if (d < 257) v = W_hh[j * LL + (d - DMSG)];
        } else if (j < 384) {
            if (d < DMSG) v = W_ih[j * DMSG + d];
        } else {
            if (d < LL) v = W_hh[(j - 128) * LL + d];
        }
        g_Gp[i] = v;
    }
    for (int i = gtid; i < GR; i += nthr) {
        float v;
        if (i < 256) v = b_ih[i] + b_hh[i];
        else if (i < 384) v = b_ih[i];
        else v = b_hh[i - 128];
        g_bias[i] = v;
    }
    for (int d = gw; d < DH; d += NWARP) {
        float a = 0.0f;
        const float* wr = Wv + d * LL;
#pragma unroll
        for (int ch = 0; ch < 4; ch++)
            a = fmaf(__ldg(wr + ch * 32 + lane), __ldg(W_out + ch * 32 + lane), a);
#pragma unroll
        for (int o = 16; o; o >>= 1) a += __shfl_xor_sync(0xffffffffu, a, o);
        if (lane == 0) g_cv[d] = a;
    }
    if (gw == 300) {
        float a = 0.0f;
#pragma unroll
        for (int ch = 0; ch < 4; ch++)
            a = fmaf(__ldg(bv + ch * 32 + lane), __ldg(W_out + ch * 32 + lane), a);
#pragma unroll
        for (int o = 16; o; o >>= 1) a += __shfl_xor_sync(0xffffffffu, a, o);
        if (lane == 0) g_cvc = a + b_out[0];
    }
    for (int i = gtid; i < LL; i += nthr) g_enc0[i] = cosf(time_b[i]);
    gsync();

    // step-0 X prep
    if (gw < 128) prep_warp(0, gw, lane, x, t, src, tgt, time_w, time_b);
    gsync();

    // hoisted per-lane constants (valid after init)
    float tw[4], tc[4], cvd[4];
#pragma unroll
    for (int j = 0; j < 4; j++) {
        int l = j * 32 + lane;
        tw[j] = __ldg(time_w + l);
        tc[j] = __ldg(time_b + l);
        cvd[j] = g_cv[1 + LL + l];
    }
    float cv0 = g_cv[0];

    // ================= step loop =================
    for (int s = 0; s < S_LEN; s++) {
        // ---- phase 1: gates GEMM + combine(s-1) ----
        if (gw < 256) gemm2(gw * 2, lane);
        else if (gw < 320) { if (s > 0) combine_warp(out, s - 1, gw - 256, lane); }
        gsync();

        // ---- phase 2: scatter epilogue + qck ----
        for (int bt = blockIdx.x; bt < 192; bt += NBLK) {
            __syncthreads();
            if (tid < 128)
                s_nodes[tid] = (tid < BSZ) ? src[s * BSZ + tid] : tgt[s * BSZ + (tid - BSZ)];
            __syncthreads();

            if (bt < 128) {
                int c = bt;
                int my = s_nodes[c];
                bool loser = (tid < 128) && (tid > c) && (s_nodes[tid] == my);
                bool skip = __syncthreads_or(loser);
                if (!skip) {
                    if (tid < 128) {
                        float v = gru_cell(c, tid);
                        g_mem[my * LL + tid] = v;
                        float a = v * g_cv[1 + tid];
#pragma unroll
                        for (int o = 16; o; o >>= 1) a += __shfl_xor_sync(0xffffffffu, a, o);
                        if ((tid & 31) == 0) s_red[tid >> 5] = a;
                    }
                    __syncthreads();
                    if (tid == 0) {
                        g_memdot[my] = s_red[0] + s_red[1] + s_red[2] + s_red[3];
                        g_dirty[my] = 1;
                    }
                }
            } else {
                int b = bt - 128;
                int mynode = s_nodes[BSZ + b];
                if (tid == 0) s_win = BSZ + b;
                __syncthreads();
                if (tid < 128 && s_nodes[tid] == mynode) atomicMax(&s_win, tid);
                __syncthreads();
                int cwin = s_win;

                if (tid == 0) s_th[0] = x[((long)(s * BSZ + b)) * NN + mynode];
                if (tid < LL) {
                    s_th[1 + tid] = gru_cell(cwin, tid);
                    s_th[1 + LL + tid] = g_enc0[tid];
                }
                __syncthreads();
                {
                    int l = tid & 127, half = tid >> 7;
                    int d0 = half * 128, d1 = half ? DH : 128;
                    float a0 = 0.f, a1 = 0.f, a2 = 0.f, a3 = 0.f;
                    int d = d0;
                    for (; d + 3 < d1; d += 4) {
                        a0 = fmaf(s_th[d],     __ldg(Wq + (d    ) * LL + l), a0);
                        a1 = fmaf(s_th[d + 1], __ldg(Wq + (d + 1) * LL + l), a1);
                        a2 = fmaf(s_th[d + 2], __ldg(Wq + (d + 2) * LL + l), a2);
                        a3 = fmaf(s_th[d + 3], __ldg(Wq + (d + 3) * LL + l), a3);
                    }
                    for (; d < d1; d++) a0 = fmaf(s_th[d], __ldg(Wq + d * LL + l), a0);
                    s_qp[half][l] = (a0 + a1) + (a2 + a3);
                }
                __syncthreads();
                if (tid < LL) s_q[tid] = s_qp[0][tid] + s_qp[1][tid] + bq[tid];
                __syncthreads();

                for (int d = wid; d < DH; d += 8) {
                    float a = 0.0f;
                    const float* wr = Wk + d * LL;
#pragma unroll
                    for (int ch = 0; ch < 4; ch++)
                        a = fmaf(__ldg(wr + ch * 32 + lane), s_q[ch * 32 + lane], a);
#pragma unroll
                    for (int o = 16; o; o >>= 1) a += __shfl_xor_sync(0xffffffffu, a, o);
                    if (lane == 0) g_ck[b * DH + d] = SCALE * a;
                }
                if (tid == 0) {
                    float a = 0.0f;
                    for (int l = 0; l < LL; l++) a = fmaf(s_q[l], bk[l], a);
                    g_qbk[b] = SCALE * a;
                }
            }
        }
        gsync();

        // ---- phase 3: scores + prep(s+1) ----
        {
            int lim = 12800 + ((s + 1 < S_LEN) ? 128 : 0);
            for (int wt = gw; wt < lim; wt += NWARP) {
                if (wt < 12800)
                    scores_task(wt >> 6, wt & 63, lane, s, x, t, mask, tw, tc, cvd, cv0);
                else
                    prep_warp(s + 1, wt - 12800, lane, x, t, src, tgt, time_w, time_b);
            }
        }
        gsync();
    }

    // final combine for step 15
    if (gw >= 256 && gw < 320) combine_warp(out, S_LEN - 1, gw - 256, lane);
}

// ---------------- host --------------------------------------------------------------
extern "C" void kernel_launch(void* const* d_in, const int* in_sizes, int n_in,
                              void* d_out, int out_size) {
    const float* x       = (const float*)d_in[0];
    const float* t       = (const float*)d_in[1];
    const int*   src     = (const int*)d_in[2];
    const int*   tgt     = (const int*)d_in[3];
    const int*   mask    = (const int*)d_in[4];
    const float* time_w  = (const float*)d_in[5];
    const float* time_b  = (const float*)d_in[6];
    const float* W_ih    = (const float*)d_in[7];
    const float* W_hh    = (const float*)d_in[8];
    const float* b_ih    = (const float*)d_in[9];
    const float* b_hh    = (const float*)d_in[10];
    const float* Wq      = (const float*)d_in[11];
    const float* bq      = (const float*)d_in[12];
    const float* Wk      = (const float*)d_in[13];
    const float* bk      = (const float*)d_in[14];
    const float* Wv      = (const float*)d_in[15];
    const float* bv      = (const float*)d_in[16];
    const float* W_out   = (const float*)d_in[17];
    const float* b_out   = (const float*)d_in[18];

    k_persist<<<NBLK, NTHR>>>(x, t, src, tgt, mask, time_w, time_b,
                              W_ih, W_hh, b_ih, b_hh, Wq, bq, Wk, bk,
                              Wv, bv, W_out, b_out, (float*)d_out);
}

// round 9
// speedup vs baseline: 2.7843x; 2.7843x over previous
#include <cuda_runtime.h>
#include <math.h>

#define S_LEN 16
#define BSZ   64
#define NN    10000
#define LL    128
#define DMSG  129
#define DH    257
#define SCALE 0.08838834764831844f
#define XR    260
#define GR    512
#define NBLK  148
#define NTHR  512
#define NWARP (NBLK * 16)      // 2368
#define ND2   2048
#define KCH   16               // Chebyshev nodes / coeffs (degree 15)
#define NTILE 32
#define TSZ   320
#define PI_F  3.14159265358979f

// ---------------- device state ----------------------------------------------------
__device__ float g_X[XR * 128];
__device__ float g_Gp[GR * XR];
__device__ float g_bias[GR];
__device__ float g_gates[GR * 128];
__device__ float g_ck[BSZ * DH];
__device__ float g_qbk[BSZ];
__device__ float g_memdot[NN];
__device__ int   g_dmap[NN];           // node -> dirty index (-1 clean)
__device__ int   g_dcount;
__device__ float g_dmemT[LL * ND2];    // transposed dirty memory [l][dIdx]
__device__ float g_sdot[BSZ * ND2];    // ckm[b] . mem[dirty]
__device__ float g_cosk[KCH * LL];     // cos(t_k w_l + c_l)
__device__ float g_Tm[KCH * KCH];      // Chebyshev transform
__device__ float g_cf[BSZ * KCH];      // per-b score-poly coeffs
__device__ float g_cg[KCH];            // value-poly coeffs (step-invariant)
__device__ float4 g_part[BSZ * NTILE];
__device__ float g_cv[DH];
__device__ float g_cvc;
__device__ float g_enc0[LL];
__device__ unsigned g_count;
__device__ volatile unsigned g_gen;

// ---------------- grid barrier -----------------------------------------------------
__device__ __forceinline__ void gsync() {
    __threadfence();
    __syncthreads();
    if (threadIdx.x == 0) {
        unsigned gen = g_gen;
        if (atomicAdd(&g_count, 1) == NBLK - 1) {
            g_count = 0;
            __threadfence();
            g_gen = gen + 1;
        } else {
            while (g_gen == gen) { }
            __threadfence();
        }
    }
    __syncthreads();
}

// ---------------- GRU epilogue ------------------------------------------------------
__device__ __forceinline__ float gru_cell(int c, int j) {
    float srz = g_gates[j * 128 + c];
    float szz = g_gates[(128 + j) * 128 + c];
    float gin = g_gates[(256 + j) * 128 + c];
    float ghn = g_gates[(384 + j) * 128 + c];
    float h   = g_X[(DMSG + j) * 128 + c];
    float r = 1.0f / (1.0f + __expf(-(srz + g_bias[j])));
    float z = 1.0f / (1.0f + __expf(-(szz + g_bias[128 + j])));
    float n = tanhf(fmaf(r, ghn + g_bias[384 + j], gin + g_bias[256 + j]));
    return fmaf(z, h - n, n);
}

// ---------------- prep: build X column for cell c of step sp (one warp) -------------
__device__ __forceinline__ void prep_warp(
        int sp, int c, int lane,
        const float* __restrict__ x, const float* __restrict__ t,
        const int* __restrict__ src, const int* __restrict__ tgt,
        const float* __restrict__ time_w, const float* __restrict__ time_b) {
    int b = c & 63, is_t = c >> 6;
    int node = (is_t ? tgt : src)[sp * BSZ + b];
    long base = ((long)(sp * BSZ + b)) * NN + node;
    float tv = __ldg(t + base);
    if (lane == 0) g_X[c] = __ldg(x + base);
    int dm = g_dmap[node];
#pragma unroll
    for (int j = 0; j < 4; j++) {
        int l = j * 32 + lane;
        g_X[(1 + l) * 128 + c] = cosf(fmaf(tv, __ldg(time_w + l), __ldg(time_b + l)));
        float h = (dm >= 0) ? g_dmemT[l * ND2 + dm] : 0.0f;
        g_X[(DMSG + l) * 128 + c] = h;
    }
}

// ---------------- lane-state softmax merge ------------------------------------------
__device__ __forceinline__ void merge_mzv(float& m, float& Z, float& V) {
#pragma unroll
    for (int o = 16; o; o >>= 1) {
        float om = __shfl_xor_sync(0xffffffffu, m, o);
        float oZ = __shfl_xor_sync(0xffffffffu, Z, o);
        float oV = __shfl_xor_sync(0xffffffffu, V, o);
        float M = fmaxf(m, om);
        float e1 = __expf(m - M), e2 = __expf(om - M);
        Z = fmaf(Z, e1, oZ * e2);
        V = fmaf(V, e1, oV * e2);
        m = M;
    }
}

// ---------------- combine: merge NTILE partials for batch b (one warp) --------------
__device__ __forceinline__ void combine_warp(float* __restrict__ out, int cs, int b, int lane) {
    float4 p = g_part[b * NTILE + lane];   // NTILE == 32
    float m = p.x, Z = p.y, V = p.z;
    merge_mzv(m, Z, V);
    if (lane == 0) out[cs * BSZ + b] = V / Z + g_cvc;
}

// ---------------- gates GEMM: one row x 128 cells per warp --------------------------
__device__ __forceinline__ void gemm_row(int j, int lane) {
    int D4, xoff;
    if (j < 256)      { D4 = 65; xoff = 0; }
    else if (j < 384) { D4 = 33; xoff = 0; }
    else              { D4 = 32; xoff = DMSG; }

    const float4* gp = (const float4*)(g_Gp + j * XR);
    const float4* xp = ((const float4*)(g_X + xoff * 128)) + lane;
    float4 a = {0, 0, 0, 0};
#pragma unroll 4
    for (int q = 0; q < D4; q++) {
        float4 w = __ldg(gp + q);
        float4 x0 = __ldg(xp + (4 * q + 0) * 32);
        float4 x1 = __ldg(xp + (4 * q + 1) * 32);
        float4 x2 = __ldg(xp + (4 * q + 2) * 32);
        float4 x3 = __ldg(xp + (4 * q + 3) * 32);
        a.x = fmaf(w.x, x0.x, a.x); a.y = fmaf(w.x, x0.y, a.y);
        a.z = fmaf(w.x, x0.z, a.z); a.w = fmaf(w.x, x0.w, a.w);
        a.x = fmaf(w.y, x1.x, a.x); a.y = fmaf(w.y, x1.y, a.y);
        a.z = fmaf(w.y, x1.z, a.z); a.w = fmaf(w.y, x1.w, a.w);
        a.x = fmaf(w.z, x2.x, a.x); a.y = fmaf(w.z, x2.y, a.y);
        a.z = fmaf(w.z, x2.z, a.z); a.w = fmaf(w.z, x2.w, a.w);
        a.x = fmaf(w.w, x3.x, a.x); a.y = fmaf(w.w, x3.y, a.y);
        a.z = fmaf(w.w, x3.z, a.z); a.w = fmaf(w.w, x3.w, a.w);
    }
    ((float4*)(g_gates + j * 128))[lane] = a;
}

// ---------------- scores: lane-parallel rows, Chebyshev polys ------------------------
__device__ __forceinline__ void scores_task(
        int b, int tile, int lane, int s,
        const float* __restrict__ x, const float* __restrict__ t,
        const int* __restrict__ mask, float cgL, float cv0) {
    int n0 = tile * TSZ;
    int n1 = (n0 + TSZ < NN) ? (n0 + TSZ) : NN;
    long base = ((long)(s * BSZ + b)) * NN;
    float cfL = g_cf[b * KCH + (lane & 15)];
    float qbk = g_qbk[b];
    float ck0 = g_ck[b * DH];

    float m = -1e30f, Z = 0.0f, V = 0.0f;
#pragma unroll 2
    for (int it = 0; it < TSZ / 32; it++) {
        int nn = n0 + it * 32 + lane;
        bool pred = nn < n1;
        int n = pred ? nn : (NN - 1);
        float tv = __ldg(t + base + n);
        int   mk = __ldg(mask + base + n);
        float xv = __ldg(x + base + n);
        float md = g_memdot[n];
        int   dm = g_dmap[n];
        float sd = (dm >= 0) ? g_sdot[b * ND2 + dm] : 0.0f;

        float u = 2.0f * tv - 1.0f;
        float u2 = u + u;
        float b1 = 0.f, b2 = 0.f, d1 = 0.f, d2 = 0.f;
#pragma unroll
        for (int j = KCH - 1; j >= 1; j--) {
            float cj = __shfl_sync(0xffffffffu, cfL, j);
            float gj = __shfl_sync(0xffffffffu, cgL, j);
            float nb = fmaf(u2, b1, cj) - b2; b2 = b1; b1 = nb;
            float nd = fmaf(u2, d1, gj) - d2; d2 = d1; d1 = nd;
        }
        float f = fmaf(u, b1, __shfl_sync(0xffffffffu, cfL, 0)) - b2;
        float g = fmaf(u, d1, __shfl_sync(0xffffffffu, cgL, 0)) - d2;

        float sc = qbk + fmaf(ck0, xv, f) + sd;
        sc = mk ? sc : -1e9f;
        sc = pred ? sc : -3.0e38f;
        float val = fmaf(cv0, xv, md) + g;

        float M = fmaxf(m, sc);
        float eo = __expf(m - M);
        float en = __expf(sc - M);
        Z = fmaf(Z, eo, en);
        V = fmaf(V, eo, en * val);
        m = M;
    }
    merge_mzv(m, Z, V);
    if (lane == 0) g_part[b * NTILE + tile] = make_float4(m, Z, V, 0.0f);
}

// ---------------- the persistent kernel ----------------------------------------------
__global__ void __launch_bounds__(NTHR) k_persist(
        const float* __restrict__ x, const float* __restrict__ t,
        const int* __restrict__ src, const int* __restrict__ tgt,
        const int* __restrict__ mask,
        const float* __restrict__ time_w, const float* __restrict__ time_b,
        const float* __restrict__ W_ih, const float* __restrict__ W_hh,
        const float* __restrict__ b_ih, const float* __restrict__ b_hh,
        const float* __restrict__ Wq, const float* __restrict__ bq,
        const float* __restrict__ Wk, const float* __restrict__ bk,
        const float* __restrict__ Wv, const float* __restrict__ bv,
        const float* __restrict__ W_out, const float* __restrict__ b_out,
        float* __restrict__ out) {
    __shared__ int   s_nodes[128];
    __shared__ float s_red[4];
    __shared__ float s_th[DH];
    __shared__ float s_qp4[4][LL];
    __shared__ float s_q[LL];
    __shared__ float s_ck[DH];
    __shared__ float s_fv[KCH];
    __shared__ int   s_win, s_didx;

    int tid = threadIdx.x;
    int lane = tid & 31, wid = tid >> 5;
    int gw = blockIdx.x * 16 + wid;
    int gtid = blockIdx.x * NTHR + tid;
    const int nthr = NBLK * NTHR;

    // ================= init =================
    for (int i = gtid; i < XR * 128; i += nthr) g_X[i] = 0.0f;
    for (int i = gtid; i < GR * XR; i += nthr) {
        int j = i / XR, d = i - j * XR;
        float v = 0.0f;
        if (j < 256) {
            if (d < DMSG) v = W_ih[j * DMSG + d];
            else if (d < 257) v = W_hh[j * LL + (d - DMSG)];
        } else if (j < 384) {
            if (d < DMSG) v = W_ih[j * DMSG + d];
        } else {
            if (d < LL) v = W_hh[(j - 128) * LL + d];
        }
        g_Gp[i] = v;
    }
    for (int i = gtid; i < GR; i += nthr) {
        float v;
        if (i < 256) v = b_ih[i] + b_hh[i];
        else if (i < 384) v = b_ih[i];
        else v = b_hh[i - 128];
        g_bias[i] = v;
    }
    for (int i = gtid; i < NN; i += nthr) { g_dmap[i] = -1; g_memdot[i] = 0.0f; }
    for (int d = gw; d < DH; d += NWARP) {
        float a = 0.0f;
        const float* wr = Wv + d * LL;
#pragma unroll
        for (int ch = 0; ch < 4; ch++)
            a = fmaf(__ldg(wr + ch * 32 + lane), __ldg(W_out + ch * 32 + lane), a);
#pragma unroll
        for (int o = 16; o; o >>= 1) a += __shfl_xor_sync(0xffffffffu, a, o);
        if (lane == 0) g_cv[d] = a;
    }
    if (gw == 300) {
        float a = 0.0f;
#pragma unroll
        for (int ch = 0; ch < 4; ch++)
            a = fmaf(__ldg(bv + ch * 32 + lane), __ldg(W_out + ch * 32 + lane), a);
#pragma unroll
        for (int o = 16; o; o >>= 1) a += __shfl_xor_sync(0xffffffffu, a, o);
        if (lane == 0) g_cvc = a + b_out[0];
    }
    for (int i = gtid; i < LL; i += nthr) g_enc0[i] = cosf(time_b[i]);
    for (int i = gtid; i < KCH * LL; i += nthr) {
        int k = i >> 7, l = i & 127;
        float tk = 0.5f + 0.5f * cosf(PI_F * (k + 0.5f) / KCH);
        g_cosk[i] = cosf(fmaf(tk, time_w[l], time_b[l]));
    }
    for (int i = gtid; i < KCH * KCH; i += nthr) {
        int j = i >> 4, k = i & 15;
        float w = (j == 0) ? (1.0f / KCH) : (2.0f / KCH);
        g_Tm[i] = w * cosf(j * PI_F * (k + 0.5f) / KCH);
    }
    if (gtid == 0) g_dcount = 0;
    gsync();

    // ===== init2: fit value poly g (step-invariant) + prep(step 0) =====
    if (gw == 0) {
        float gv = 0.0f;
        if (lane < KCH) {
            for (int l = 0; l < LL; l++)
                gv = fmaf(g_cv[1 + LL + l], g_cosk[lane * LL + l], gv);
        }
        if (lane < KCH) {
            float c = 0.0f;
#pragma unroll
            for (int k = 0; k < KCH; k++)
                c = fmaf(g_Tm[lane * KCH + k], __shfl_sync(0x0000ffffu, gv, k), c);
            g_cg[lane] = c;
        }
    }
    if (gw >= 8 && gw < 136) prep_warp(0, gw - 8, lane, x, t, src, tgt, time_w, time_b);
    gsync();

    float cgL = g_cg[lane & 15];
    float cv0 = g_cv[0];

    // ================= step loop =================
    for (int s = 0; s < S_LEN; s++) {
        // ---- P1: gates GEMM + combine(s-1) ----
        if (gw < 512) gemm_row(gw, lane);
        else if (gw < 576) { if (s > 0) combine_warp(out, s - 1, gw - 512, lane); }
        gsync();

        // ---- P2: scatter + qck/fit ----
        for (int bt = blockIdx.x; bt < 192; bt += NBLK) {
            __syncthreads();
            if (tid < 128)
                s_nodes[tid] = (tid < BSZ) ? src[s * BSZ + tid] : tgt[s * BSZ + (tid - BSZ)];
            __syncthreads();

            if (bt < 128) {
                int c = bt;
                int my = s_nodes[c];
                bool loser = (tid < 128) && (tid > c) && (s_nodes[tid] == my);
                bool skip = __syncthreads_or(loser);
                if (!skip) {
                    if (tid == 0) {
                        int di = g_dmap[my];
                        if (di < 0) { di = atomicAdd(&g_dcount, 1); g_dmap[my] = di; }
                        s_didx = di;
                    }
                    __syncthreads();
                    int di = s_didx;
                    if (tid < 128) {
                        float v = gru_cell(c, tid);
                        g_dmemT[tid * ND2 + di] = v;
                        float a = v * g_cv[1 + tid];
#pragma unroll
                        for (int o = 16; o; o >>= 1) a += __shfl_xor_sync(0xffffffffu, a, o);
                        if ((tid & 31) == 0) s_red[tid >> 5] = a;
                    }
                    __syncthreads();
                    if (tid == 0)
                        g_memdot[my] = s_red[0] + s_red[1] + s_red[2] + s_red[3];
                }
            } else {
                int b = bt - 128;
                int mynode = s_nodes[BSZ + b];
                if (tid == 0) s_win = BSZ + b;
                __syncthreads();
                if (tid < 128 && s_nodes[tid] == mynode) atomicMax(&s_win, tid);
                __syncthreads();
                int cwin = s_win;

                if (tid == 0) s_th[0] = x[((long)(s * BSZ + b)) * NN + mynode];
                if (tid < LL) {
                    s_th[1 + tid] = gru_cell(cwin, tid);
                    s_th[1 + LL + tid] = g_enc0[tid];
                }
                __syncthreads();
                {   // q: 4-way d-split across 512 threads
                    int l = tid & 127, p = tid >> 7;
                    int d0 = p * 64, d1 = (p == 3) ? DH : (d0 + 64);
                    float a0 = 0.f, a1 = 0.f, a2 = 0.f, a3 = 0.f;
                    int d = d0;
                    for (; d + 3 < d1; d += 4) {
                        a0 = fmaf(s_th[d],     __ldg(Wq + (d    ) * LL + l), a0);
                        a1 = fmaf(s_th[d + 1], __ldg(Wq + (d + 1) * LL + l), a1);
                        a2 = fmaf(s_th[d + 2], __ldg(Wq + (d + 2) * LL + l), a2);
                        a3 = fmaf(s_th[d + 3], __ldg(Wq + (d + 3) * LL + l), a3);
                    }
                    for (; d < d1; d++) a0 = fmaf(s_th[d], __ldg(Wq + d * LL + l), a0);
                    s_qp4[p][l] = (a0 + a1) + (a2 + a3);
                }
                __syncthreads();
                if (tid < LL)
                    s_q[tid] = (s_qp4[0][tid] + s_qp4[1][tid]) + (s_qp4[2][tid] + s_qp4[3][tid]) + bq[tid];
                __syncthreads();

                for (int d = wid; d < DH; d += 16) {
                    float a = 0.0f;
                    const float* wr = Wk + d * LL;
#pragma unroll
                    for (int ch = 0; ch < 4; ch++)
                        a = fmaf(__ldg(wr + ch * 32 + lane), s_q[ch * 32 + lane], a);
#pragma unroll
                    for (int o = 16; o; o >>= 1) a += __shfl_xor_sync(0xffffffffu, a, o);
                    if (lane == 0) {
                        float v = SCALE * a;
                        g_ck[b * DH + d] = v;
                        s_ck[d] = v;
                    }
                }
                __syncthreads();
                // fit f_b: warp k computes fv_k = ckd . cosk[k]
                if (wid < KCH) {
                    float a = 0.0f;
#pragma unroll
                    for (int ch = 0; ch < 4; ch++) {
                        int l = ch * 32 + lane;
                        a = fmaf(s_ck[1 + LL + l], g_cosk[wid * LL + l], a);
                    }
#pragma unroll
                    for (int o = 16; o; o >>= 1) a += __shfl_xor_sync(0xffffffffu, a, o);
                    if (lane == 0) s_fv[wid] = a;
                }
                __syncthreads();
                if (tid < KCH) {
                    float c = 0.0f;
#pragma unroll
                    for (int k = 0; k < KCH; k++) c = fmaf(g_Tm[tid * KCH + k], s_fv[k], c);
                    g_cf[b * KCH + tid] = c;
                }
                if (wid == 1) {   // qbk
                    float a = 0.0f;
#pragma unroll
                    for (int ch = 0; ch < 4; ch++)
                        a = fmaf(s_q[ch * 32 + lane], __ldg(bk + ch * 32 + lane), a);
#pragma unroll
                    for (int o = 16; o; o >>= 1) a += __shfl_xor_sync(0xffffffffu, a, o);
                    if (lane == 0) g_qbk[b] = SCALE * a;
                }
            }
        }
        gsync();

        // ---- P2.5: sdot GEMM over dirty nodes ----
        {
            int nd = g_dcount;
            int ng = (nd + 31) >> 5;
            for (int wt = gw; wt < ng * 64; wt += NWARP) {
                int b = wt & 63, gI = wt >> 6;
                int i = gI * 32 + lane;
                int ii = (i < nd) ? i : (nd - 1);
                float ck4[4];
#pragma unroll
                for (int j = 0; j < 4; j++) ck4[j] = g_ck[b * DH + 1 + j * 32 + lane];
                float acc = 0.0f;
#pragma unroll 4
                for (int l = 0; l < LL; l++) {
                    float v = g_dmemT[l * ND2 + ii];
                    float ckl = __shfl_sync(0xffffffffu, ck4[l >> 5], l & 31);
                    acc = fmaf(ckl, v, acc);
                }
                if (i < nd) g_sdot[b * ND2 + i] = acc;
            }
        }
        gsync();

        // ---- P3: scores + prep(s+1) ----
        if (gw < 2048) scores_task(gw >> 5, gw & 31, lane, s, x, t, mask, cgL, cv0);
        else if (gw < 2176) {
            if (s + 1 < S_LEN) prep_warp(s + 1, gw - 2048, lane, x, t, src, tgt, time_w, time_b);
        }
        gsync();
    }

    // final combine for step 15
    if (gw < 64) combine_warp(out, S_LEN - 1, gw, lane);
}

// ---------------- host ----------------------------------------------------------------
extern "C" void kernel_launch(void* const* d_in, const int* in_sizes, int n_in,
                              void* d_out, int out_size) {
    const float* x       = (const float*)d_in[0];
    const float* t       = (const float*)d_in[1];
    const int*   src     = (const int*)d_in[2];
    const int*   tgt     = (const int*)d_in[3];
    const int*   mask    = (const int*)d_in[4];
    const float* time_w  = (const float*)d_in[5];
    const float* time_b  = (const float*)d_in[6];
    const float* W_ih    = (const float*)d_in[7];
    const float* W_hh    = (const float*)d_in[8];
    const float* b_ih    = (const float*)d_in[9];
    const float* b_hh    = (const float*)d_in[10];
    const float* Wq      = (const float*)d_in[11];
    const float* bq      = (const float*)d_in[12];
    const float* Wk      = (const float*)d_in[13];
    const float* bk      = (const float*)d_in[14];
    const float* Wv      = (const float*)d_in[15];
    const float* bv      = (const float*)d_in[16];
    const float* W_out   = (const float*)d_in[17];
    const float* b_out   = (const float*)d_in[18];

    k_persist<<<NBLK, NTHR>>>(x, t, src, tgt, mask, time_w, time_b,
                              W_ih, W_hh, b_ih, b_hh, Wq, bq, Wk, bk,
                              Wv, bv, W_out, b_out, (float*)d_out);
}

// round 10
// speedup vs baseline: 4.7675x; 1.7123x over previous
#include <cuda_runtime.h>
#include <math.h>

#define S_LEN 16
#define BSZ   64
#define NN    10000
#define LL    128
#define DMSG  129
#define DH    257
#define SCALE 0.08838834764831844f
#define XR    260
#define GR    512
#define NBLK  296
#define NTHR  512
#define NWARP (NBLK * 16)      // 4736
#define ND2   2048
#define KCH   16
#define NTILE 64
#define TSZ   160
#define PI_F  3.14159265358979f

// ---------------- device state ----------------------------------------------------
__device__ float g_X[XR * 128];
__device__ float g_Gp[GR * XR];
__device__ float g_bias[GR];
__device__ float g_gates[GR * 128];
__device__ float g_ck[BSZ * DH];
__device__ float g_qbk[BSZ];
__device__ float g_memdot[NN];
__device__ int   g_dmap[NN];
__device__ int   g_dcount;
__device__ float g_dmemT[LL * ND2];
__device__ float g_sdot[BSZ * ND2];
__device__ float g_cosk[KCH * LL];
__device__ float g_Tm[KCH * KCH];
__device__ float g_cf[BSZ * KCH];
__device__ float g_cg[KCH];
__device__ float4 g_part[BSZ * NTILE];
__device__ float g_cv[DH];
__device__ float g_cvc;
__device__ float g_enc0[LL];
__device__ unsigned g_count;
__device__ volatile unsigned g_gen;

// ---------------- grid barrier -----------------------------------------------------
__device__ __forceinline__ void gsync() {
    __threadfence();
    __syncthreads();
    if (threadIdx.x == 0) {
        unsigned gen = g_gen;
        if (atomicAdd(&g_count, 1) == NBLK - 1) {
            g_count = 0;
            __threadfence();
            g_gen = gen + 1;
        } else {
            while (g_gen == gen) { }
            __threadfence();
        }
    }
    __syncthreads();
}

// ---------------- GRU epilogue ------------------------------------------------------
__device__ __forceinline__ float gru_cell(int c, int j) {
    float srz = g_gates[j * 128 + c];
    float szz = g_gates[(128 + j) * 128 + c];
    float gin = g_gates[(256 + j) * 128 + c];
    float ghn = g_gates[(384 + j) * 128 + c];
    float h   = g_X[(DMSG + j) * 128 + c];
    float r = 1.0f / (1.0f + __expf(-(srz + g_bias[j])));
    float z = 1.0f / (1.0f + __expf(-(szz + g_bias[128 + j])));
    float n = tanhf(fmaf(r, ghn + g_bias[384 + j], gin + g_bias[256 + j]));
    return fmaf(z, h - n, n);
}

// ---------------- prep: build X column for cell c of step sp (one warp) -------------
__device__ __forceinline__ void prep_warp(
        int sp, int c, int lane,
        const float* __restrict__ x, const float* __restrict__ t,
        const int* __restrict__ src, const int* __restrict__ tgt,
        const float* __restrict__ time_w, const float* __restrict__ time_b) {
    int b = c & 63, is_t = c >> 6;
    int node = (is_t ? tgt : src)[sp * BSZ + b];
    long base = ((long)(sp * BSZ + b)) * NN + node;
    float tv = __ldg(t + base);
    if (lane == 0) g_X[c] = __ldg(x + base);
    int dm = g_dmap[node];
#pragma unroll
    for (int j = 0; j < 4; j++) {
        int l = j * 32 + lane;
        g_X[(1 + l) * 128 + c] = cosf(fmaf(tv, __ldg(time_w + l), __ldg(time_b + l)));
        float h = (dm >= 0) ? g_dmemT[l * ND2 + dm] : 0.0f;
        g_X[(DMSG + l) * 128 + c] = h;
    }
}

// ---------------- lane-state softmax merge ------------------------------------------
__device__ __forceinline__ void merge_mzv(float& m, float& Z, float& V) {
#pragma unroll
    for (int o = 16; o; o >>= 1) {
        float om = __shfl_xor_sync(0xffffffffu, m, o);
        float oZ = __shfl_xor_sync(0xffffffffu, Z, o);
        float oV = __shfl_xor_sync(0xffffffffu, V, o);
        float M = fmaxf(m, om);
        float e1 = __expf(m - M), e2 = __expf(om - M);
        Z = fmaf(Z, e1, oZ * e2);
        V = fmaf(V, e1, oV * e2);
        m = M;
    }
}

// ---------------- combine: merge NTILE(=64) partials for batch b (one warp) ---------
__device__ __forceinline__ void combine_warp(float* __restrict__ out, int cs, int b, int lane) {
    float4 p0 = g_part[b * NTILE + lane];
    float4 p1 = g_part[b * NTILE + 32 + lane];
    float m = fmaxf(p0.x, p1.x);
    float e0 = __expf(p0.x - m), e1 = __expf(p1.x - m);
    float Z = fmaf(p0.y, e0, p1.y * e1);
    float V = fmaf(p0.z, e0, p1.z * e1);
    merge_mzv(m, Z, V);
    if (lane == 0) out[cs * BSZ + b] = V / Z + g_cvc;
}

// ---------------- gates GEMM: one row x 128 cells per warp --------------------------
__device__ __forceinline__ void gemm_row(int j, int lane) {
    int D4, xoff;
    if (j < 256)      { D4 = 65; xoff = 0; }
    else if (j < 384) { D4 = 33; xoff = 0; }
    else              { D4 = 32; xoff = DMSG; }

    const float4* gp = (const float4*)(g_Gp + j * XR);
    const float4* xp = ((const float4*)(g_X + xoff * 128)) + lane;
    float4 a = {0, 0, 0, 0};
#pragma unroll 4
    for (int q = 0; q < D4; q++) {
        float4 w = __ldg(gp + q);
        float4 x0 = __ldg(xp + (4 * q + 0) * 32);
        float4 x1 = __ldg(xp + (4 * q + 1) * 32);
        float4 x2 = __ldg(xp + (4 * q + 2) * 32);
        float4 x3 = __ldg(xp + (4 * q + 3) * 32);
        a.x = fmaf(w.x, x0.x, a.x); a.y = fmaf(w.x, x0.y, a.y);
        a.z = fmaf(w.x, x0.z, a.z); a.w = fmaf(w.x, x0.w, a.w);
        a.x = fmaf(w.y, x1.x, a.x); a.y = fmaf(w.y, x1.y, a.y);
        a.z = fmaf(w.y, x1.z, a.z); a.w = fmaf(w.y, x1.w, a.w);
        a.x = fmaf(w.z, x2.x, a.x); a.y = fmaf(w.z, x2.y, a.y);
        a.z = fmaf(w.z, x2.z, a.z); a.w = fmaf(w.z, x2.w, a.w);
        a.x = fmaf(w.w, x3.x, a.x); a.y = fmaf(w.w, x3.y, a.y);
        a.z = fmaf(w.w, x3.z, a.z); a.w = fmaf(w.w, x3.w, a.w);
    }
    ((float4*)(g_gates + j * 128))[lane] = a;
}

// ---------------- scores: lane-parallel rows, Chebyshev polys ------------------------
__device__ __forceinline__ void scores_task(
        int b, int tile, int lane, int s,
        const float* __restrict__ x, const float* __restrict__ t,
        const int* __restrict__ mask, float cgL, float cv0) {
    int n0 = tile * TSZ;
    long base = ((long)(s * BSZ + b)) * NN;
    float cfL = g_cf[b * KCH + (lane & 15)];
    float qbk = g_qbk[b];
    float ck0 = g_ck[b * DH];

    float m = -1e30f, Z = 0.0f, V = 0.0f;
#pragma unroll
    for (int it = 0; it < TSZ / 32; it++) {
        int nn = n0 + it * 32 + lane;
        bool pred = nn < NN;
        int n = pred ? nn : (NN - 1);
        float tv = __ldg(t + base + n);
        int   mk = __ldg(mask + base + n);
        float xv = __ldg(x + base + n);
        float md = g_memdot[n];
        int   dm = g_dmap[n];
        float sd = (dm >= 0) ? g_sdot[b * ND2 + dm] : 0.0f;

        float u = 2.0f * tv - 1.0f;
        float u2 = u + u;
        float b1 = 0.f, b2 = 0.f, d1 = 0.f, d2 = 0.f;
#pragma unroll
        for (int j = KCH - 1; j >= 1; j--) {
            float cj = __shfl_sync(0xffffffffu, cfL, j);
            float gj = __shfl_sync(0xffffffffu, cgL, j);
            float nb = fmaf(u2, b1, cj) - b2; b2 = b1; b1 = nb;
            float nd = fmaf(u2, d1, gj) - d2; d2 = d1; d1 = nd;
        }
        float f = fmaf(u, b1, __shfl_sync(0xffffffffu, cfL, 0)) - b2;
        float g = fmaf(u, d1, __shfl_sync(0xffffffffu, cgL, 0)) - d2;

        float sc = qbk + fmaf(ck0, xv, f) + sd;
        sc = mk ? sc : -1e9f;
        sc = pred ? sc : -3.0e38f;
        float val = fmaf(cv0, xv, md) + g;

        float M = fmaxf(m, sc);
        float eo = __expf(m - M);
        float en = __expf(sc - M);
        Z = fmaf(Z, eo, en);
        V = fmaf(V, eo, en * val);
        m = M;
    }
    merge_mzv(m, Z, V);
    if (lane == 0) g_part[b * NTILE + tile] = make_float4(m, Z, V, 0.0f);
}

// ---------------- the persistent kernel ----------------------------------------------
__global__ void __launch_bounds__(NTHR, 2) k_persist(
        const float* __restrict__ x, const float* __restrict__ t,
        const int* __restrict__ src, const int* __restrict__ tgt,
        const int* __restrict__ mask,
        const float* __restrict__ time_w, const float* __restrict__ time_b,
        const float* __restrict__ W_ih, const float* __restrict__ W_hh,
        const float* __restrict__ b_ih, const float* __restrict__ b_hh,
        const float* __restrict__ Wq, const float* __restrict__ bq,
        const float* __restrict__ Wk, const float* __restrict__ bk,
        const float* __restrict__ Wv, const float* __restrict__ bv,
        const float* __restrict__ W_out, const float* __restrict__ b_out,
        float* __restrict__ out) {
    __shared__ int   s_nodes[128];
    __shared__ float s_red[4];
    __shared__ float s_th[DH];
    __shared__ float s_qp4[4][LL];
    __shared__ float s_q[LL];
    __shared__ float s_ck[DH];
    __shared__ float s_fv[KCH];
    __shared__ int   s_win, s_didx;

    int tid = threadIdx.x;
    int lane = tid & 31, wid = tid >> 5;
    int gw = blockIdx.x * 16 + wid;
    int gtid = blockIdx.x * NTHR + tid;
    const int nthr = NBLK * NTHR;

    // ================= init =================
    for (int i = gtid; i < XR * 128; i += nthr) g_X[i] = 0.0f;
    for (int i = gtid; i < GR * XR; i += nthr) {
        int j = i / XR, d = i - j * XR;
        float v = 0.0f;
        if (j < 256) {
            if (d < DMSG) v = W_ih[j * DMSG + d];
            else if (d < 257) v = W_hh[j * LL + (d - DMSG)];
        } else if (j < 384) {
            if (d < DMSG) v = W_ih[j * DMSG + d];
        } else {
            if (d < LL) v = W_hh[(j - 128) * LL + d];
        }
        g_Gp[i] = v;
    }
    for (int i = gtid; i < GR; i += nthr) {
        float v;
        if (i < 256) v = b_ih[i] + b_hh[i];
        else if (i < 384) v = b_ih[i];
        else v = b_hh[i - 128];
        g_bias[i] = v;
    }
    for (int i = gtid; i < NN; i += nthr) { g_dmap[i] = -1; g_memdot[i] = 0.0f; }
    for (int d = gw; d < DH; d += NWARP) {
        float a = 0.0f;
        const float* wr = Wv + d * LL;
#pragma unroll
        for (int ch = 0; ch < 4; ch++)
            a = fmaf(__ldg(wr + ch * 32 + lane), __ldg(W_out + ch * 32 + lane), a);
#pragma unroll
        for (int o = 16; o; o >>= 1) a += __shfl_xor_sync(0xffffffffu, a, o);
        if (lane == 0) g_cv[d] = a;
    }
    if (gw == 300) {
        float a = 0.0f;
#pragma unroll
        for (int ch = 0; ch < 4; ch++)
            a = fmaf(__ldg(bv + ch * 32 + lane), __ldg(W_out + ch * 32 + lane), a);
#pragma unroll
        for (int o = 16; o; o >>= 1) a += __shfl_xor_sync(0xffffffffu, a, o);
        if (lane == 0) g_cvc = a + b_out[0];
    }
    for (int i = gtid; i < LL; i += nthr) g_enc0[i] = cosf(time_b[i]);
    for (int i = gtid; i < KCH * LL; i += nthr) {
        int k = i >> 7, l = i & 127;
        float tk = 0.5f + 0.5f * cosf(PI_F * (k + 0.5f) / KCH);
        g_cosk[i] = cosf(fmaf(tk, time_w[l], time_b[l]));
    }
    for (int i = gtid; i < KCH * KCH; i += nthr) {
        int j = i >> 4, k = i & 15;
        float w = (j == 0) ? (1.0f / KCH) : (2.0f / KCH);
        g_Tm[i] = w * cosf(j * PI_F * (k + 0.5f) / KCH);
    }
    if (gtid == 0) g_dcount = 0;
    gsync();

    // ===== init2: fit value poly g (step-invariant) + prep(step 0) =====
    if (gw == 0) {
        float gv = 0.0f;
        if (lane < KCH) {
            for (int l = 0; l < LL; l++)
                gv = fmaf(g_cv[1 + LL + l], g_cosk[lane * LL + l], gv);
        }
        if (lane < KCH) {
            float c = 0.0f;
#pragma unroll
            for (int k = 0; k < KCH; k++)
                c = fmaf(g_Tm[lane * KCH + k], __shfl_sync(0x0000ffffu, gv, k), c);
            g_cg[lane] = c;
        }
    }
    if (gw >= 8 && gw < 136) prep_warp(0, gw - 8, lane, x, t, src, tgt, time_w, time_b);
    gsync();

    float cgL = g_cg[lane & 15];
    float cv0 = g_cv[0];

    // ================= step loop =================
    for (int s = 0; s < S_LEN; s++) {
        // ---- P1: gates GEMM + combine(s-1) ----
        if (gw < 512) gemm_row(gw, lane);
        else if (gw < 576) { if (s > 0) combine_warp(out, s - 1, gw - 512, lane); }
        gsync();

        // ---- P2: qck (blocks 0-63) + scatter (blocks 64-191) ----
        if (blockIdx.x < 192) {
            if (tid < 128)
                s_nodes[tid] = (tid < BSZ) ? src[s * BSZ + tid] : tgt[s * BSZ + (tid - BSZ)];
            __syncthreads();

            if (blockIdx.x >= 64) {
                int c = blockIdx.x - 64;
                int my = s_nodes[c];
                bool loser = (tid < 128) && (tid > c) && (s_nodes[tid] == my);
                bool skip = __syncthreads_or(loser);
                if (!skip) {
                    if (tid == 0) {
                        int di = g_dmap[my];
                        if (di < 0) { di = atomicAdd(&g_dcount, 1); g_dmap[my] = di; }
                        s_didx = di;
                    }
                    __syncthreads();
                    int di = s_didx;
                    if (tid < 128) {
                        float v = gru_cell(c, tid);
                        g_dmemT[tid * ND2 + di] = v;
                        float a = v * g_cv[1 + tid];
#pragma unroll
                        for (int o = 16; o; o >>= 1) a += __shfl_xor_sync(0xffffffffu, a, o);
                        if ((tid & 31) == 0) s_red[tid >> 5] = a;
                    }
                    __syncthreads();
                    if (tid == 0)
                        g_memdot[my] = s_red[0] + s_red[1] + s_red[2] + s_red[3];
                }
            } else {
                int b = blockIdx.x;
                int mynode = s_nodes[BSZ + b];
                if (tid == 0) s_win = BSZ + b;
                __syncthreads();
                if (tid < 128 && s_nodes[tid] == mynode) atomicMax(&s_win, tid);
                __syncthreads();
                int cwin = s_win;

                if (tid == 0) s_th[0] = x[((long)(s * BSZ + b)) * NN + mynode];
                if (tid < LL) {
                    s_th[1 + tid] = gru_cell(cwin, tid);
                    s_th[1 + LL + tid] = g_enc0[tid];
                }
                __syncthreads();
                {   // q: 4-way d-split across 512 threads
                    int l = tid & 127, p = tid >> 7;
                    int d0 = p * 64, d1 = (p == 3) ? DH : (d0 + 64);
                    float a0 = 0.f, a1 = 0.f, a2 = 0.f, a3 = 0.f;
                    int d = d0;
                    for (; d + 3 < d1; d += 4) {
                        a0 = fmaf(s_th[d],     __ldg(Wq + (d    ) * LL + l), a0);
                        a1 = fmaf(s_th[d + 1], __ldg(Wq + (d + 1) * LL + l), a1);
                        a2 = fmaf(s_th[d + 2], __ldg(Wq + (d + 2) * LL + l), a2);
                        a3 = fmaf(s_th[d + 3], __ldg(Wq + (d + 3) * LL + l), a3);
                    }
                    for (; d < d1; d++) a0 = fmaf(s_th[d], __ldg(Wq + d * LL + l), a0);
                    s_qp4[p][l] = (a0 + a1) + (a2 + a3);
                }
                __syncthreads();
                if (tid < LL)
                    s_q[tid] = (s_qp4[0][tid] + s_qp4[1][tid]) + (s_qp4[2][tid] + s_qp4[3][tid]) + bq[tid];
                __syncthreads();

                for (int d = wid; d < DH; d += 16) {
                    float a = 0.0f;
                    const float* wr = Wk + d * LL;
#pragma unroll
                    for (int ch = 0; ch < 4; ch++)
                        a = fmaf(__ldg(wr + ch * 32 + lane), s_q[ch * 32 + lane], a);
#pragma unroll
                    for (int o = 16; o; o >>= 1) a += __shfl_xor_sync(0xffffffffu, a, o);
                    if (lane == 0) {
                        float v = SCALE * a;
                        g_ck[b * DH + d] = v;
                        s_ck[d] = v;
                    }
                }
                __syncthreads();
                if (wid < KCH) {
                    float a = 0.0f;
#pragma unroll
                    for (int ch = 0; ch < 4; ch++) {
                        int l = ch * 32 + lane;
                        a = fmaf(s_ck[1 + LL + l], g_cosk[wid * LL + l], a);
                    }
#pragma unroll
                    for (int o = 16; o; o >>= 1) a += __shfl_xor_sync(0xffffffffu, a, o);
                    if (lane == 0) s_fv[wid] = a;
                }
                __syncthreads();
                if (tid < KCH) {
                    float c = 0.0f;
#pragma unroll
                    for (int k = 0; k < KCH; k++) c = fmaf(g_Tm[tid * KCH + k], s_fv[k], c);
                    g_cf[b * KCH + tid] = c;
                }
                if (wid == 1) {
                    float a = 0.0f;
#pragma unroll
                    for (int ch = 0; ch < 4; ch++)
                        a = fmaf(s_q[ch * 32 + lane], __ldg(bk + ch * 32 + lane), a);
#pragma unroll
                    for (int o = 16; o; o >>= 1) a += __shfl_xor_sync(0xffffffffu, a, o);
                    if (lane == 0) g_qbk[b] = SCALE * a;
                }
            }
        }
        gsync();

        // ---- P2.5: sdot GEMM over dirty nodes, tiled 4 b per task ----
        {
            int nd = g_dcount;
            int ntask = ((nd + 31) >> 5) * 16;
            for (int wt = gw; wt < ntask; wt += NWARP) {
                int bg = wt & 15, gI = wt >> 4;
                int i = gI * 32 + lane;
                int ii = (i < nd) ? i : (nd - 1);
                float ckr[4][4];
#pragma unroll
                for (int bb = 0; bb < 4; bb++)
#pragma unroll
                    for (int j = 0; j < 4; j++)
                        ckr[bb][j] = g_ck[(bg * 4 + bb) * DH + 1 + j * 32 + lane];
                float acc[4] = {0.f, 0.f, 0.f, 0.f};
#pragma unroll
                for (int ch = 0; ch < 4; ch++) {
#pragma unroll 8
                    for (int lo = 0; lo < 32; lo++) {
                        float v = g_dmemT[(ch * 32 + lo) * ND2 + ii];
#pragma unroll
                        for (int bb = 0; bb < 4; bb++)
                            acc[bb] = fmaf(__shfl_sync(0xffffffffu, ckr[bb][ch], lo), v, acc[bb]);
                    }
                }
                if (i < nd) {
#pragma unroll
                    for (int bb = 0; bb < 4; bb++)
                        g_sdot[(bg * 4 + bb) * ND2 + i] = acc[bb];
                }
            }
        }
        gsync();

        // ---- P3: scores + prep(s+1) ----
        if (gw < 4096) scores_task(gw & 63, gw >> 6, lane, s, x, t, mask, cgL, cv0);
        else if (gw < 4224) {
            if (s + 1 < S_LEN) prep_warp(s + 1, gw - 4096, lane, x, t, src, tgt, time_w, time_b);
        }
        gsync();
    }

    // final combine for step 15
    if (gw < 64) combine_warp(out, S_LEN - 1, gw, lane);
}

// ---------------- host ----------------------------------------------------------------
extern "C" void kernel_launch(void* const* d_in, const int* in_sizes, int n_in,
                              void* d_out, int out_size) {
    const float* x       = (const float*)d_in[0];
    const float* t       = (const float*)d_in[1];
    const int*   src     = (const int*)d_in[2];
    const int*   tgt     = (const int*)d_in[3];
    const int*   mask    = (const int*)d_in[4];
    const float* time_w  = (const float*)d_in[5];
    const float* time_b  = (const float*)d_in[6];
    const float* W_ih    = (const float*)d_in[7];
    const float* W_hh    = (const float*)d_in[8];
    const float* b_ih    = (const float*)d_in[9];
    const float* b_hh    = (const float*)d_in[10];
    const float* Wq      = (const float*)d_in[11];
    const float* bq      = (const float*)d_in[12];
    const float* Wk      = (const float*)d_in[13];
    const float* bk      = (const float*)d_in[14];
    const float* Wv      = (const float*)d_in[15];
    const float* bv      = (const float*)d_in[16];
    const float* W_out   = (const float*)d_in[17];
    const float* b_out   = (const float*)d_in[18];

    k_persist<<<NBLK, NTHR>>>(x, t, src, tgt, mask, time_w, time_b,
                              W_ih, W_hh, b_ih, b_hh, Wq, bq, Wk, bk,
                              Wv, bv, W_out, b_out, (float*)d_out);
}

// round 11
// speedup vs baseline: 5.6085x; 1.1764x over previous
#include <cuda_runtime.h>
#include <math.h>

#define S_LEN 16
#define BSZ   64
#define NN    10000
#define LL    128
#define DMSG  129
#define DH    257
#define SCALE 0.08838834764831844f
#define XR    260
#define GR    512
#define NBLK  296
#define NTHR  512
#define NWARP (NBLK * 16)      // 4736
#define ND2   2048
#define KCH   16
#define NTILE 64
#define TSZ   160
#define PI_F  3.14159265358979f

// ---------------- device state ----------------------------------------------------
__device__ float g_X[XR * 128];
__device__ float g_Gp[GR * XR];
__device__ float g_bias[GR];
__device__ float g_gates[GR * 128];
__device__ float g_gatesB[GR * 128];
__device__ float g_ck[BSZ * DH];
__device__ float g_qbk[BSZ];
__device__ float g_memdot[NN];
__device__ int   g_dmap[NN];
__device__ int   g_dcount;
__device__ float g_dmemT[LL * ND2];
__device__ float g_sdot[BSZ * ND2];
__device__ float g_cosk[KCH * LL];
__device__ float g_Tm[KCH * KCH];
__device__ float g_cf[BSZ * KCH];
__device__ float g_cg[KCH];
__device__ float4 g_part[BSZ * NTILE];
__device__ float g_cv[DH];
__device__ float g_cvc;
__device__ float g_enc0[LL];
__device__ unsigned g_count;
__device__ volatile unsigned g_gen;

// ---------------- grid barrier -----------------------------------------------------
__device__ __forceinline__ void gsync() {
    __threadfence();
    __syncthreads();
    if (threadIdx.x == 0) {
        unsigned gen = g_gen;
        if (atomicAdd(&g_count, 1) == NBLK - 1) {
            g_count = 0;
            __threadfence();
            g_gen = gen + 1;
        } else {
            while (g_gen == gen) { }
            __threadfence();
        }
    }
    __syncthreads();
}

// ---------------- GRU epilogue (sums the two K-split partials) ----------------------
__device__ __forceinline__ float gru_cell(int c, int j) {
    float srz = g_gates[j * 128 + c]         + g_gatesB[j * 128 + c];
    float szz = g_gates[(128 + j) * 128 + c] + g_gatesB[(128 + j) * 128 + c];
    float gin = g_gates[(256 + j) * 128 + c] + g_gatesB[(256 + j) * 128 + c];
    float ghn = g_gates[(384 + j) * 128 + c] + g_gatesB[(384 + j) * 128 + c];
    float h   = g_X[(DMSG + j) * 128 + c];
    float r = 1.0f / (1.0f + __expf(-(srz + g_bias[j])));
    float z = 1.0f / (1.0f + __expf(-(szz + g_bias[128 + j])));
    float n = tanhf(fmaf(r, ghn + g_bias[384 + j], gin + g_bias[256 + j]));
    return fmaf(z, h - n, n);
}

// ---------------- prep: build X column for cell c of step sp (one warp) -------------
__device__ __forceinline__ void prep_warp(
        int sp, int c, int lane,
        const float* __restrict__ x, const float* __restrict__ t,
        const int* __restrict__ src, const int* __restrict__ tgt,
        const float* __restrict__ time_w, const float* __restrict__ time_b) {
    int b = c & 63, is_t = c >> 6;
    int node = (is_t ? tgt : src)[sp * BSZ + b];
    long base = ((long)(sp * BSZ + b)) * NN + node;
    float tv = __ldg(t + base);
    if (lane == 0) g_X[c] = __ldg(x + base);
    int dm = g_dmap[node];
#pragma unroll
    for (int j = 0; j < 4; j++) {
        int l = j * 32 + lane;
        g_X[(1 + l) * 128 + c] = cosf(fmaf(tv, __ldg(time_w + l), __ldg(time_b + l)));
        float h = (dm >= 0) ? g_dmemT[l * ND2 + dm] : 0.0f;
        g_X[(DMSG + l) * 128 + c] = h;
    }
}

// ---------------- lane-state softmax merge ------------------------------------------
__device__ __forceinline__ void merge_mzv(float& m, float& Z, float& V) {
#pragma unroll
    for (int o = 16; o; o >>= 1) {
        float om = __shfl_xor_sync(0xffffffffu, m, o);
        float oZ = __shfl_xor_sync(0xffffffffu, Z, o);
        float oV = __shfl_xor_sync(0xffffffffu, V, o);
        float M = fmaxf(m, om);
        float e1 = __expf(m - M), e2 = __expf(om - M);
        Z = fmaf(Z, e1, oZ * e2);
        V = fmaf(V, e1, oV * e2);
        m = M;
    }
}

// ---------------- combine: merge NTILE(=64) partials for batch b (one warp) ---------
__device__ __forceinline__ void combine_warp(float* __restrict__ out, int cs, int b, int lane) {
    float4 p0 = g_part[b * NTILE + lane];
    float4 p1 = g_part[b * NTILE + 32 + lane];
    float m = fmaxf(p0.x, p1.x);
    float e0 = __expf(p0.x - m), e1 = __expf(p1.x - m);
    float Z = fmaf(p0.y, e0, p1.y * e1);
    float V = fmaf(p0.z, e0, p1.z * e1);
    merge_mzv(m, Z, V);
    if (lane == 0) out[cs * BSZ + b] = V / Z + g_cvc;
}

// ---------------- gates GEMM: half a row (K-split) x 128 cells per warp -------------
__device__ __forceinline__ void gemm_row_half(int j, int half, int lane) {
    int D4, xoff;
    if (j < 256)      { D4 = 65; xoff = 0; }
    else if (j < 384) { D4 = 33; xoff = 0; }
    else              { D4 = 32; xoff = DMSG; }
    int h0 = (D4 + 1) >> 1;
    int q0 = half ? h0 : 0;
    int q1 = half ? D4 : h0;

    const float4* gp = (const float4*)(g_Gp + j * XR);
    const float4* xp = ((const float4*)(g_X + xoff * 128)) + lane;
    float4 a = {0, 0, 0, 0};
#pragma unroll 4
    for (int q = q0; q < q1; q++) {
        float4 w = __ldg(gp + q);
        float4 x0 = __ldg(xp + (4 * q + 0) * 32);
        float4 x1 = __ldg(xp + (4 * q + 1) * 32);
        float4 x2 = __ldg(xp + (4 * q + 2) * 32);
        float4 x3 = __ldg(xp + (4 * q + 3) * 32);
        a.x = fmaf(w.x, x0.x, a.x); a.y = fmaf(w.x, x0.y, a.y);
        a.z = fmaf(w.x, x0.z, a.z); a.w = fmaf(w.x, x0.w, a.w);
        a.x = fmaf(w.y, x1.x, a.x); a.y = fmaf(w.y, x1.y, a.y);
        a.z = fmaf(w.y, x1.z, a.z); a.w = fmaf(w.y, x1.w, a.w);
        a.x = fmaf(w.z, x2.x, a.x); a.y = fmaf(w.z, x2.y, a.y);
        a.z = fmaf(w.z, x2.z, a.z); a.w = fmaf(w.z, x2.w, a.w);
        a.x = fmaf(w.w, x3.x, a.x); a.y = fmaf(w.w, x3.y, a.y);
        a.z = fmaf(w.w, x3.z, a.z); a.w = fmaf(w.w, x3.w, a.w);
    }
    float* dst = half ? g_gatesB : g_gates;
    ((float4*)(dst + j * 128))[lane] = a;
}

// ---------------- scores: lane-parallel rows, Chebyshev polys ------------------------
__device__ __forceinline__ void scores_task(
        int b, int tile, int lane, int s,
        const float* __restrict__ x, const float* __restrict__ t,
        const int* __restrict__ mask, float cgL, float cv0) {
    int n0 = tile * TSZ;
    long base = ((long)(s * BSZ + b)) * NN;
    float cfL = g_cf[b * KCH + (lane & 15)];
    float qbk = g_qbk[b];
    float ck0 = g_ck[b * DH];

    float m = -1e30f, Z = 0.0f, V = 0.0f;
#pragma unroll
    for (int it = 0; it < TSZ / 32; it++) {
        int nn = n0 + it * 32 + lane;
        bool pred = nn < NN;
        int n = pred ? nn : (NN - 1);
        float tv = __ldg(t + base + n);
        int   mk = __ldg(mask + base + n);
        float xv = __ldg(x + base + n);
        float md = g_memdot[n];
        int   dm = g_dmap[n];
        float sd = (dm >= 0) ? g_sdot[b * ND2 + dm] : 0.0f;

        float u = 2.0f * tv - 1.0f;
        float u2 = u + u;
        float b1 = 0.f, b2 = 0.f, d1 = 0.f, d2 = 0.f;
#pragma unroll
        for (int j = KCH - 1; j >= 1; j--) {
            float cj = __shfl_sync(0xffffffffu, cfL, j);
            float gj = __shfl_sync(0xffffffffu, cgL, j);
            float nb = fmaf(u2, b1, cj) - b2; b2 = b1; b1 = nb;
            float nd = fmaf(u2, d1, gj) - d2; d2 = d1; d1 = nd;
        }
        float f = fmaf(u, b1, __shfl_sync(0xffffffffu, cfL, 0)) - b2;
        float g = fmaf(u, d1, __shfl_sync(0xffffffffu, cgL, 0)) - d2;

        float sc = qbk + fmaf(ck0, xv, f) + sd;
        sc = mk ? sc : -1e9f;
        sc = pred ? sc : -3.0e38f;
        float val = fmaf(cv0, xv, md) + g;

        float M = fmaxf(m, sc);
        float eo = __expf(m - M);
        float en = __expf(sc - M);
        Z = fmaf(Z, eo, en);
        V = fmaf(V, eo, en * val);
        m = M;
    }
    merge_mzv(m, Z, V);
    if (lane == 0) g_part[b * NTILE + tile] = make_float4(m, Z, V, 0.0f);
}

// ---------------- the persistent kernel ----------------------------------------------
__global__ void __launch_bounds__(NTHR, 2) k_persist(
        const float* __restrict__ x, const float* __restrict__ t,
        const int* __restrict__ src, const int* __restrict__ tgt,
        const int* __restrict__ mask,
        const float* __restrict__ time_w, const float* __restrict__ time_b,
        const float* __restrict__ W_ih, const float* __restrict__ W_hh,
        const float* __restrict__ b_ih, const float* __restrict__ b_hh,
        const float* __restrict__ Wq, const float* __restrict__ bq,
        const float* __restrict__ Wk, const float* __restrict__ bk,
        const float* __restrict__ Wv, const float* __restrict__ bv,
        const float* __restrict__ W_out, const float* __restrict__ b_out,
        float* __restrict__ out) {
    __shared__ int   s_nodes[128];
    __shared__ float s_red[4];
    __shared__ float s_th[DH];
    __shared__ float s_qp4[4][LL];
    __shared__ float s_q[LL];
    __shared__ float s_ck[DH];
    __shared__ float s_fv[KCH];
    __shared__ int   s_win, s_didx;

    int tid = threadIdx.x;
    int lane = tid & 31, wid = tid >> 5;
    int gw = blockIdx.x * 16 + wid;
    int gtid = blockIdx.x * NTHR + tid;
    const int nthr = NBLK * NTHR;
    // spread-mapped warp task id: consecutive tasks land on different blocks
    int sw = blockIdx.x + wid * NBLK;

    // ================= init =================
    for (int i = gtid; i < XR * 128; i += nthr) g_X[i] = 0.0f;
    for (int i = gtid; i < GR * XR; i += nthr) {
        int j = i / XR, d = i - j * XR;
        float v = 0.0f;
        if (j < 256) {
            if (d < DMSG) v = W_ih[j * DMSG + d];
            else if (d < 257) v = W_hh[j * LL + (d - DMSG)];
        } else if (j < 384) {
            if (d < DMSG) v = W_ih[j * DMSG + d];
        } else {
            if (d < LL) v = W_hh[(j - 128) * LL + d];
        }
        g_Gp[i] = v;
    }
    for (int i = gtid; i < GR; i += nthr) {
        float v;
        if (i < 256) v = b_ih[i] + b_hh[i];
        else if (i < 384) v = b_ih[i];
        else v = b_hh[i - 128];
        g_bias[i] = v;
    }
    for (int i = gtid; i < NN; i += nthr) { g_dmap[i] = -1; g_memdot[i] = 0.0f; }
    for (int d = gw; d < DH; d += NWARP) {
        float a = 0.0f;
        const float* wr = Wv + d * LL;
#pragma unroll
        for (int ch = 0; ch < 4; ch++)
            a = fmaf(__ldg(wr + ch * 32 + lane), __ldg(W_out + ch * 32 + lane), a);
#pragma unroll
        for (int o = 16; o; o >>= 1) a += __shfl_xor_sync(0xffffffffu, a, o);
        if (lane == 0) g_cv[d] = a;
    }
    if (gw == 300) {
        float a = 0.0f;
#pragma unroll
        for (int ch = 0; ch < 4; ch++)
            a = fmaf(__ldg(bv + ch * 32 + lane), __ldg(W_out + ch * 32 + lane), a);
#pragma unroll
        for (int o = 16; o; o >>= 1) a += __shfl_xor_sync(0xffffffffu, a, o);
        if (lane == 0) g_cvc = a + b_out[0];
    }
    for (int i = gtid; i < LL; i += nthr) g_enc0[i] = cosf(time_b[i]);
    for (int i = gtid; i < KCH * LL; i += nthr) {
        int k = i >> 7, l = i & 127;
        float tk = 0.5f + 0.5f * cosf(PI_F * (k + 0.5f) / KCH);
        g_cosk[i] = cosf(fmaf(tk, time_w[l], time_b[l]));
    }
    for (int i = gtid; i < KCH * KCH; i += nthr) {
        int j = i >> 4, k = i & 15;
        float w = (j == 0) ? (1.0f / KCH) : (2.0f / KCH);
        g_Tm[i] = w * cosf(j * PI_F * (k + 0.5f) / KCH);
    }
    if (gtid == 0) g_dcount = 0;
    gsync();

    // ===== init2: fit value poly g (step-invariant) + prep(step 0) =====
    if (gw == 0) {
        float gv = 0.0f;
        if (lane < KCH) {
            for (int l = 0; l < LL; l++)
                gv = fmaf(g_cv[1 + LL + l], g_cosk[lane * LL + l], gv);
        }
        if (lane < KCH) {
            float c = 0.0f;
#pragma unroll
            for (int k = 0; k < KCH; k++)
                c = fmaf(g_Tm[lane * KCH + k], __shfl_sync(0x0000ffffu, gv, k), c);
            g_cg[lane] = c;
        }
    }
    if (gw >= 8 && gw < 136) prep_warp(0, gw - 8, lane, x, t, src, tgt, time_w, time_b);
    gsync();

    float cgL = g_cg[lane & 15];
    float cv0 = g_cv[0];

    // ================= step loop =================
    for (int s = 0; s < S_LEN; s++) {
        // ---- P1: gates GEMM (1024 spread tasks) + combine(s-1) ----
        if (sw < 1024) gemm_row_half(sw >> 1, sw & 1, lane);
        else if (wid == 8 && blockIdx.x < 64) {
            if (s > 0) combine_warp(out, s - 1, blockIdx.x, lane);
        }
        gsync();

        // ---- P2: qck (blocks 0-63) + scatter (blocks 64-191) ----
        if (blockIdx.x < 192) {
            if (tid < 128)
                s_nodes[tid] = (tid < BSZ) ? src[s * BSZ + tid] : tgt[s * BSZ + (tid - BSZ)];
            __syncthreads();

            if (blockIdx.x >= 64) {
                int c = blockIdx.x - 64;
                int my = s_nodes[c];
                bool loser = (tid < 128) && (tid > c) && (s_nodes[tid] == my);
                bool skip = __syncthreads_or(loser);
                if (!skip) {
                    if (tid == 0) {
                        int di = g_dmap[my];
                        if (di < 0) { di = atomicAdd(&g_dcount, 1); g_dmap[my] = di; }
                        s_didx = di;
                    }
                    __syncthreads();
                    int di = s_didx;
                    if (tid < 128) {
                        float v = gru_cell(c, tid);
                        g_dmemT[tid * ND2 + di] = v;
                        float a = v * g_cv[1 + tid];
#pragma unroll
                        for (int o = 16; o; o >>= 1) a += __shfl_xor_sync(0xffffffffu, a, o);
                        if ((tid & 31) == 0) s_red[tid >> 5] = a;
                    }
                    __syncthreads();
                    if (tid == 0)
                        g_memdot[my] = s_red[0] + s_red[1] + s_red[2] + s_red[3];
                }
            } else {
                int b = blockIdx.x;
                int mynode = s_nodes[BSZ + b];
                if (tid == 0) s_win = BSZ + b;
                __syncthreads();
                if (tid < 128 && s_nodes[tid] == mynode) atomicMax(&s_win, tid);
                __syncthreads();
                int cwin = s_win;

                if (tid == 0) s_th[0] = x[((long)(s * BSZ + b)) * NN + mynode];
                if (tid < LL) {
                    s_th[1 + tid] = gru_cell(cwin, tid);
                    s_th[1 + LL + tid] = g_enc0[tid];
                }
                __syncthreads();
                {   // q: 4-way d-split across 512 threads
                    int l = tid & 127, p = tid >> 7;
                    int d0 = p * 64, d1 = (p == 3) ? DH : (d0 + 64);
                    float a0 = 0.f, a1 = 0.f, a2 = 0.f, a3 = 0.f;
                    int d = d0;
                    for (; d + 3 < d1; d += 4) {
                        a0 = fmaf(s_th[d],     __ldg(Wq + (d    ) * LL + l), a0);
                        a1 = fmaf(s_th[d + 1], __ldg(Wq + (d + 1) * LL + l), a1);
                        a2 = fmaf(s_th[d + 2], __ldg(Wq + (d + 2) * LL + l), a2);
                        a3 = fmaf(s_th[d + 3], __ldg(Wq + (d + 3) * LL + l), a3);
                    }
                    for (; d < d1; d++) a0 = fmaf(s_th[d], __ldg(Wq + d * LL + l), a0);
                    s_qp4[p][l] = (a0 + a1) + (a2 + a3);
                }
                __syncthreads();
                if (tid < LL)
                    s_q[tid] = (s_qp4[0][tid] + s_qp4[1][tid]) + (s_qp4[2][tid] + s_qp4[3][tid]) + bq[tid];
                __syncthreads();

                for (int d = wid; d < DH; d += 16) {
                    float a = 0.0f;
                    const float* wr = Wk + d * LL;
#pragma unroll
                    for (int ch = 0; ch < 4; ch++)
                        a = fmaf(__ldg(wr + ch * 32 + lane), s_q[ch * 32 + lane], a);
#pragma unroll
                    for (int o = 16; o; o >>= 1) a += __shfl_xor_sync(0xffffffffu, a, o);
                    if (lane == 0) {
                        float v = SCALE * a;
                        g_ck[b * DH + d] = v;
                        s_ck[d] = v;
                    }
                }
                __syncthreads();
                if (wid < KCH) {
                    float a = 0.0f;
#pragma unroll
                    for (int ch = 0; ch < 4; ch++) {
                        int l = ch * 32 + lane;
                        a = fmaf(s_ck[1 + LL + l], g_cosk[wid * LL + l], a);
                    }
#pragma unroll
                    for (int o = 16; o; o >>= 1) a += __shfl_xor_sync(0xffffffffu, a, o);
                    if (lane == 0) s_fv[wid] = a;
                }
                __syncthreads();
                if (tid < KCH) {
                    float c = 0.0f;
#pragma unroll
                    for (int k = 0; k < KCH; k++) c = fmaf(g_Tm[tid * KCH + k], s_fv[k], c);
                    g_cf[b * KCH + tid] = c;
                }
                if (wid == 1) {
                    float a = 0.0f;
#pragma unroll
                    for (int ch = 0; ch < 4; ch++)
                        a = fmaf(s_q[ch * 32 + lane], __ldg(bk + ch * 32 + lane), a);
#pragma unroll
                    for (int o = 16; o; o >>= 1) a += __shfl_xor_sync(0xffffffffu, a, o);
                    if (lane == 0) g_qbk[b] = SCALE * a;
                }
            }
        }
        gsync();

        // ---- P2.5: sdot GEMM over dirty nodes (spread tasks, 4 b per task) ----
        {
            int nd = g_dcount;
            int ntask = ((nd + 31) >> 5) * 16;
            for (int wt = sw; wt < ntask; wt += NWARP) {
                int bg = wt & 15, gI = wt >> 4;
                int i = gI * 32 + lane;
                int ii = (i < nd) ? i : (nd - 1);
                float ckr[4][4];
#pragma unroll
                for (int bb = 0; bb < 4; bb++)
#pragma unroll
                    for (int j = 0; j < 4; j++)
                        ckr[bb][j] = g_ck[(bg * 4 + bb) * DH + 1 + j * 32 + lane];
                float acc[4] = {0.f, 0.f, 0.f, 0.f};
#pragma unroll
                for (int ch = 0; ch < 4; ch++) {
#pragma unroll 8
                    for (int lo = 0; lo < 32; lo++) {
                        float v = g_dmemT[(ch * 32 + lo) * ND2 + ii];
#pragma unroll
                        for (int bb = 0; bb < 4; bb++)
                            acc[bb] = fmaf(__shfl_sync(0xffffffffu, ckr[bb][ch], lo), v, acc[bb]);
                    }
                }
                if (i < nd) {
#pragma unroll
                    for (int bb = 0; bb < 4; bb++)
                        g_sdot[(bg * 4 + bb) * ND2 + i] = acc[bb];
                }
            }
        }
        gsync();

        // ---- P3: scores + prep(s+1), spread tasks ----
        if (sw < 4096) scores_task(sw & 63, sw >> 6, lane, s, x, t, mask, cgL, cv0);
        else if (sw < 4224) {
            if (s + 1 < S_LEN) prep_warp(s + 1, sw - 4096, lane, x, t, src, tgt, time_w, time_b);
        }
        gsync();
    }

    // final combine for step 15
    if (gw < 64) combine_warp(out, S_LEN - 1, gw, lane);
}

// ---------------- host ----------------------------------------------------------------
extern "C" void kernel_launch(void* const* d_in, const int* in_sizes, int n_in,
                              void* d_out, int out_size) {
    const float* x       = (const float*)d_in[0];
    const float* t       = (const float*)d_in[1];
    const int*   src     = (const int*)d_in[2];
    const int*   tgt     = (const int*)d_in[3];
    const int*   mask    = (const int*)d_in[4];
    const float* time_w  = (const float*)d_in[5];
    const float* time_b  = (const float*)d_in[6];
    const float* W_ih    = (const float*)d_in[7];
    const float* W_hh    = (const float*)d_in[8];
    const float* b_ih    = (const float*)d_in[9];
    const float* b_hh    = (const float*)d_in[10];
    const float* Wq      = (const float*)d_in[11];
    const float* bq      = (const float*)d_in[12];
    const float* Wk      = (const float*)d_in[13];
    const float* bk      = (const float*)d_in[14];
    const float* Wv      = (const float*)d_in[15];
    const float* bv      = (const float*)d_in[16];
    const float* W_out   = (const float*)d_in[17];
    const float* b_out   = (const float*)d_in[18];

    k_persist<<<NBLK, NTHR>>>(x, t, src, tgt, mask, time_w, time_b,
                              W_ih, W_hh, b_ih, b_hh, Wq, bq, Wk, bk,
                              Wv, bv, W_out, b_out, (float*)d_out);
}

// round 12
// speedup vs baseline: 6.4130x; 1.1434x over previous
#include <cuda_runtime.h>
#include <math.h>

#define S_LEN 16
#define BSZ   64
#define NN    10000
#define LL    128
#define DMSG  129
#define DH    257
#define SCALE 0.08838834764831844f
#define XR    260
#define GR    512
#define NBLK  296
#define NTHR  512
#define NWARP (NBLK * 16)      // 4736
#define ND2   2048
#define KCH   16
#define NTILE 53
#define TSZ   192
#define NROW  146              // ck0(1) + ckm(128) + cf(16) + qbk(1)
#define PI_F  3.14159265358979f

// ---------------- device state ----------------------------------------------------
__device__ float g_X[XR * 128];
__device__ float g_Gp[GR * XR];
__device__ float g_bias[GR];
__device__ float g_gates[GR * 128];
__device__ float g_gatesB[GR * 128];
__device__ float g_ck0[BSZ];
__device__ float g_ckm[BSZ * LL];
__device__ float g_cf[BSZ * KCH];
__device__ float g_qbk[BSZ];
__device__ float g_memdot[NN];
__device__ int   g_dmap[NN];
__device__ int   g_dcount;
__device__ float g_dmemT[LL * ND2];
__device__ float g_sdot[BSZ * ND2];
__device__ float g_cosk[KCH * LL];
__device__ float g_Tm[KCH * KCH];
__device__ float g_R[KCH * LL];        // Tm @ cosk
__device__ float g_vENC[LL];           // Wq[129:].T @ enc0
__device__ float g_U[NROW * LL];       // folded "Wk-side" vectors
__device__ float g_Mq[NROW * LL];      // mem-part coefs
__device__ float g_Mqx[NROW];          // x coefs
__device__ float g_Mqc[NROW];          // consts
__device__ float g_cg[KCH];
__device__ float4 g_part[2][BSZ * NTILE];
__device__ float g_cv[DH];
__device__ float g_cvc;
__device__ float g_enc0[LL];
__device__ unsigned g_count;
__device__ volatile unsigned g_gen;

// ---------------- grid barrier -----------------------------------------------------
__device__ __forceinline__ void gsync() {
    __threadfence();
    __syncthreads();
    if (threadIdx.x == 0) {
        unsigned gen = g_gen;
        if (atomicAdd(&g_count, 1) == NBLK - 1) {
            g_count = 0;
            __threadfence();
            g_gen = gen + 1;
        } else {
            while (g_gen == gen) { }
            __threadfence();
        }
    }
    __syncthreads();
}

// ---------------- GRU epilogue (sums K-split partials) ------------------------------
__device__ __forceinline__ float gru_cell(int c, int j) {
    float srz = g_gates[j * 128 + c]         + g_gatesB[j * 128 + c];
    float szz = g_gates[(128 + j) * 128 + c] + g_gatesB[(128 + j) * 128 + c];
    float gin = g_gates[(256 + j) * 128 + c] + g_gatesB[(256 + j) * 128 + c];
    float ghn = g_gates[(384 + j) * 128 + c] + g_gatesB[(384 + j) * 128 + c];
    float h   = g_X[(DMSG + j) * 128 + c];
    float r = 1.0f / (1.0f + __expf(-(srz + g_bias[j])));
    float z = 1.0f / (1.0f + __expf(-(szz + g_bias[128 + j])));
    float n = tanhf(fmaf(r, ghn + g_bias[384 + j], gin + g_bias[256 + j]));
    return fmaf(z, h - n, n);
}

// ---------------- prep: build X column for cell c of step sp ------------------------
__device__ __forceinline__ void prep_warp(
        int sp, int c, int lane,
        const float* __restrict__ x, const float* __restrict__ t,
        const int* __restrict__ src, const int* __restrict__ tgt,
        const float* __restrict__ time_w, const float* __restrict__ time_b) {
    int b = c & 63, is_t = c >> 6;
    int node = (is_t ? tgt : src)[sp * BSZ + b];
    long base = ((long)(sp * BSZ + b)) * NN + node;
    float tv = __ldg(t + base);
    if (lane == 0) g_X[c] = __ldg(x + base);
    int dm = g_dmap[node];
#pragma unroll
    for (int j = 0; j < 4; j++) {
        int l = j * 32 + lane;
        g_X[(1 + l) * 128 + c] = cosf(fmaf(tv, __ldg(time_w + l), __ldg(time_b + l)));
        float h = (dm >= 0) ? g_dmemT[l * ND2 + dm] : 0.0f;
        g_X[(DMSG + l) * 128 + c] = h;
    }
}

// ---------------- lane-state softmax merge ------------------------------------------
__device__ __forceinline__ void merge_mzv(float& m, float& Z, float& V) {
#pragma unroll
    for (int o = 16; o; o >>= 1) {
        float om = __shfl_xor_sync(0xffffffffu, m, o);
        float oZ = __shfl_xor_sync(0xffffffffu, Z, o);
        float oV = __shfl_xor_sync(0xffffffffu, V, o);
        float M = fmaxf(m, om);
        float e1 = __expf(m - M), e2 = __expf(om - M);
        Z = fmaf(Z, e1, oZ * e2);
        V = fmaf(V, e1, oV * e2);
        m = M;
    }
}

// ---------------- combine: merge NTILE(=53) partials for batch b --------------------
__device__ __forceinline__ void combine_warp(float* __restrict__ out, int cs, int b,
                                             int lane, int pb) {
    float4 p0 = g_part[pb][b * NTILE + lane];
    float4 p1 = (lane + 32 < NTILE) ? g_part[pb][b * NTILE + 32 + lane]
                                    : make_float4(-1e30f, 0.0f, 0.0f, 0.0f);
    float m = fmaxf(p0.x, p1.x);
    float e0 = __expf(p0.x - m), e1 = __expf(p1.x - m);
    float Z = fmaf(p0.y, e0, p1.y * e1);
    float V = fmaf(p0.z, e0, p1.z * e1);
    merge_mzv(m, Z, V);
    if (lane == 0) out[cs * BSZ + b] = V / Z + g_cvc;
}

// ---------------- gates GEMM: half a row (K-split) x 128 cells per warp -------------
__device__ __forceinline__ void gemm_row_half(int j, int half, int lane) {
    int D4, xoff;
    if (j < 256)      { D4 = 65; xoff = 0; }
    else if (j < 384) { D4 = 33; xoff = 0; }
    else              { D4 = 32; xoff = DMSG; }
    int h0 = (D4 + 1) >> 1;
    int q0 = half ? h0 : 0;
    int q1 = half ? D4 : h0;

    const float4* gp = (const float4*)(g_Gp + j * XR);
    const float4* xp = ((const float4*)(g_X + xoff * 128)) + lane;
    float4 a = {0, 0, 0, 0};
#pragma unroll 4
    for (int q = q0; q < q1; q++) {
        float4 w = __ldg(gp + q);
        float4 x0 = __ldg(xp + (4 * q + 0) * 32);
        float4 x1 = __ldg(xp + (4 * q + 1) * 32);
        float4 x2 = __ldg(xp + (4 * q + 2) * 32);
        float4 x3 = __ldg(xp + (4 * q + 3) * 32);
        a.x = fmaf(w.x, x0.x, a.x); a.y = fmaf(w.x, x0.y, a.y);
        a.z = fmaf(w.x, x0.z, a.z); a.w = fmaf(w.x, x0.w, a.w);
        a.x = fmaf(w.y, x1.x, a.x); a.y = fmaf(w.y, x1.y, a.y);
        a.z = fmaf(w.y, x1.z, a.z); a.w = fmaf(w.y, x1.w, a.w);
        a.x = fmaf(w.z, x2.x, a.x); a.y = fmaf(w.z, x2.y, a.y);
        a.z = fmaf(w.z, x2.z, a.z); a.w = fmaf(w.z, x2.w, a.w);
        a.x = fmaf(w.w, x3.x, a.x); a.y = fmaf(w.w, x3.y, a.y);
        a.z = fmaf(w.w, x3.z, a.z); a.w = fmaf(w.w, x3.w, a.w);
    }
    float* dst = half ? g_gatesB : g_gates;
    ((float4*)(dst + j * 128))[lane] = a;
}

// ---------------- scores: lane-parallel rows, Chebyshev polys ------------------------
__device__ __forceinline__ void scores_task(
        int b, int tile, int lane, int s, int pb,
        const float* __restrict__ x, const float* __restrict__ t,
        const int* __restrict__ mask, float cgL, float cv0) {
    int n0 = tile * TSZ;
    long base = ((long)(s * BSZ + b)) * NN;
    float cfL = g_cf[b * KCH + (lane & 15)];
    float qbk = g_qbk[b];
    float ck0 = g_ck0[b];

    float m = -1e30f, Z = 0.0f, V = 0.0f;
#pragma unroll
    for (int it = 0; it < TSZ / 32; it++) {
        int nn = n0 + it * 32 + lane;
        bool pred = nn < NN;
        int n = pred ? nn : (NN - 1);
        float tv = __ldg(t + base + n);
        int   mk = __ldg(mask + base + n);
        float xv = __ldg(x + base + n);
        float md = g_memdot[n];
        int   dm = g_dmap[n];
        float sd = (dm >= 0) ? g_sdot[b * ND2 + dm] : 0.0f;

        float u = 2.0f * tv - 1.0f;
        float u2 = u + u;
        float b1 = 0.f, b2 = 0.f, d1 = 0.f, d2 = 0.f;
#pragma unroll
        for (int j = KCH - 1; j >= 1; j--) {
            float cj = __shfl_sync(0xffffffffu, cfL, j);
            float gj = __shfl_sync(0xffffffffu, cgL, j);
            float nb = fmaf(u2, b1, cj) - b2; b2 = b1; b1 = nb;
            float nd = fmaf(u2, d1, gj) - d2; d2 = d1; d1 = nd;
        }
        float f = fmaf(u, b1, __shfl_sync(0xffffffffu, cfL, 0)) - b2;
        float g = fmaf(u, d1, __shfl_sync(0xffffffffu, cgL, 0)) - d2;

        float sc = qbk + fmaf(ck0, xv, f) + sd;
        sc = mk ? sc : -1e9f;
        sc = pred ? sc : -3.0e38f;
        float val = fmaf(cv0, xv, md) + g;

        float M = fmaxf(m, sc);
        float eo = __expf(m - M);
        float en = __expf(sc - M);
        Z = fmaf(Z, eo, en);
        V = fmaf(V, eo, en * val);
        m = M;
    }
    merge_mzv(m, Z, V);
    if (lane == 0) g_part[pb][b * NTILE + tile] = make_float4(m, Z, V, 0.0f);
}

// ---------------- the persistent kernel ----------------------------------------------
__global__ void __launch_bounds__(NTHR, 2) k_persist(
        const float* __restrict__ x, const float* __restrict__ t,
        const int* __restrict__ src, const int* __restrict__ tgt,
        const int* __restrict__ mask,
        const float* __restrict__ time_w, const float* __restrict__ time_b,
        const float* __restrict__ W_ih, const float* __restrict__ W_hh,
        const float* __restrict__ b_ih, const float* __restrict__ b_hh,
        const float* __restrict__ Wq, const float* __restrict__ bq,
        const float* __restrict__ Wk, const float* __restrict__ bk,
        const float* __restrict__ Wv, const float* __restrict__ bv,
        const float* __restrict__ W_out, const float* __restrict__ b_out,
        float* __restrict__ out) {
    __shared__ int   s_nodes[128];
    __shared__ float s_red[4];
    __shared__ float s_h[LL];
    __shared__ float s_xt;
    __shared__ int   s_win, s_didx;

    int tid = threadIdx.x;
    int lane = tid & 31, wid = tid >> 5;
    int gw = blockIdx.x * 16 + wid;
    int gtid = blockIdx.x * NTHR + tid;
    const int nthr = NBLK * NTHR;
    int sw = blockIdx.x + wid * NBLK;   // spread-mapped warp task id

    // ================= stage 1 =================
    for (int i = gtid; i < XR * 128; i += nthr) g_X[i] = 0.0f;
    for (int i = gtid; i < GR * XR; i += nthr) {
        int j = i / XR, d = i - j * XR;
        float v = 0.0f;
        if (j < 256) {
            if (d < DMSG) v = W_ih[j * DMSG + d];
            else if (d < 257) v = W_hh[j * LL + (d - DMSG)];
        } else if (j < 384) {
            if (d < DMSG) v = W_ih[j * DMSG + d];
        } else {
            if (d < LL) v = W_hh[(j - 128) * LL + d];
        }
        g_Gp[i] = v;
    }
    for (int i = gtid; i < GR; i += nthr) {
        float v;
        if (i < 256) v = b_ih[i] + b_hh[i];
        else if (i < 384) v = b_ih[i];
        else v = b_hh[i - 128];
        g_bias[i] = v;
    }
    for (int i = gtid; i < NN; i += nthr) { g_dmap[i] = -1; g_memdot[i] = 0.0f; }
    for (int d = gw; d < DH; d += NWARP) {
        float a = 0.0f;
        const float* wr = Wv + d * LL;
#pragma unroll
        for (int ch = 0; ch < 4; ch++)
            a = fmaf(__ldg(wr + ch * 32 + lane), __ldg(W_out + ch * 32 + lane), a);
#pragma unroll
        for (int o = 16; o; o >>= 1) a += __shfl_xor_sync(0xffffffffu, a, o);
        if (lane == 0) g_cv[d] = a;
    }
    if (gw == 300) {
        float a = 0.0f;
#pragma unroll
        for (int ch = 0; ch < 4; ch++)
            a = fmaf(__ldg(bv + ch * 32 + lane), __ldg(W_out + ch * 32 + lane), a);
#pragma unroll
        for (int o = 16; o; o >>= 1) a += __shfl_xor_sync(0xffffffffu, a, o);
        if (lane == 0) g_cvc = a + b_out[0];
    }
    for (int i = gtid; i < LL; i += nthr) g_enc0[i] = cosf(time_b[i]);
    for (int i = gtid; i < KCH * LL; i += nthr) {
        int k = i >> 7, l = i & 127;
        float tk = 0.5f + 0.5f * cosf(PI_F * (k + 0.5f) / KCH);
        g_cosk[i] = cosf(fmaf(tk, time_w[l], time_b[l]));
    }
    for (int i = gtid; i < KCH * KCH; i += nthr) {
        int j = i >> 4, k = i & 15;
        float w = (j == 0) ? (1.0f / KCH) : (2.0f / KCH);
        g_Tm[i] = w * cosf(j * PI_F * (k + 0.5f) / KCH);
    }
    if (gtid == 0) g_dcount = 0;
    gsync();

    // ================= stage 2: R, vENC, cg fit, prep(0) =================
    if (gtid < KCH * LL) {
        int k = gtid >> 7, l = gtid & 127;
        float a = 0.0f;
#pragma unroll
        for (int kk = 0; kk < KCH; kk++)
            a = fmaf(g_Tm[k * KCH + kk], g_cosk[kk * LL + l], a);
        g_R[gtid] = a;
    } else if (gtid < KCH * LL + LL) {
        int l = gtid - KCH * LL;
        float a = 0.0f;
#pragma unroll 8
        for (int j = 0; j < LL; j++)
            a = fmaf(__ldg(Wq + (DMSG + j) * LL + l), g_enc0[j], a);
        g_vENC[l] = a;
    }
    if (gw == 296) {   // cg fit (value poly, step-invariant)
        float gv = 0.0f;
        if (lane < KCH)
            for (int l = 0; l < LL; l++)
                gv = fmaf(g_cv[1 + LL + l], g_cosk[lane * LL + l], gv);
        if (lane < KCH) {
            float c = 0.0f;
#pragma unroll
            for (int k = 0; k < KCH; k++)
                c = fmaf(g_Tm[lane * KCH + k], __shfl_sync(0x0000ffffu, gv, k), c);
            g_cg[lane] = c;
        }
    }
    if (gw >= 8 && gw < 136) prep_warp(0, gw - 8, lane, x, t, src, tgt, time_w, time_b);
    gsync();

    // ================= stage 3: U table =================
    for (int i = gtid; i < 129 * LL; i += nthr) {          // U rows 0..128 <- Wk
        int r = i >> 7, l = i & 127;
        g_U[i] = Wk[r * LL + l];
    }
    for (int i = gtid; i < LL; i += nthr) g_U[145 * LL + i] = bk[i];
    {
        int base3 = 0;
        for (int i = gtid; i < KCH * LL; i += nthr) {      // S rows (129..144)
            int k = i >> 7, l = i & 127;
            float a = 0.0f;
#pragma unroll 8
            for (int lp = 0; lp < LL; lp++)
                a = fmaf(g_R[k * LL + lp], __ldg(Wk + (DMSG + lp) * LL + l), a);
            g_U[(129 + k) * LL + l] = a;
        }
        (void)base3;
    }
    gsync();

    // ================= stage 4: Mq pack + gemm(0) =================
    if (sw < 1024) gemm_row_half(sw >> 1, sw & 1, lane);
    for (int mtask = sw; mtask < NROW * 130; mtask += NWARP) {
        int r = mtask / 130, c = mtask - r * 130;
        float a = 0.0f;
        if (c < 128) {
            const float* v = Wq + (1 + c) * LL;
#pragma unroll
            for (int ch = 0; ch < 4; ch++)
                a = fmaf(g_U[r * LL + ch * 32 + lane], __ldg(v + ch * 32 + lane), a);
        } else if (c == 128) {
#pragma unroll
            for (int ch = 0; ch < 4; ch++)
                a = fmaf(g_U[r * LL + ch * 32 + lane], __ldg(Wq + ch * 32 + lane), a);
        } else {
#pragma unroll
            for (int ch = 0; ch < 4; ch++) {
                int l = ch * 32 + lane;
                a = fmaf(g_U[r * LL + l], g_vENC[l] + __ldg(bq + l), a);
            }
        }
#pragma unroll
        for (int o = 16; o; o >>= 1) a += __shfl_xor_sync(0xffffffffu, a, o);
        if (lane == 0) {
            a *= SCALE;
            if (c < 128) g_Mq[r * LL + c] = a;
            else if (c == 128) g_Mqx[r] = a;
            else g_Mqc[r] = a;
        }
    }
    gsync();

    float cgL = g_cg[lane & 15];
    float cv0 = g_cv[0];

    // ================= step loop: 3 phases =================
    for (int s = 0; s < S_LEN; s++) {
        // ---- A: qck (blocks 0..63) + scatter (blocks 64..191) ----
        if (blockIdx.x < 192) {
            if (tid < 128)
                s_nodes[tid] = (tid < BSZ) ? src[s * BSZ + tid] : tgt[s * BSZ + (tid - BSZ)];
            __syncthreads();

            if (blockIdx.x >= 64) {
                int c = blockIdx.x - 64;
                int my = s_nodes[c];
                bool loser = (tid < 128) && (tid > c) && (s_nodes[tid] == my);
                bool skip = __syncthreads_or(loser);
                if (!skip) {
                    if (tid == 0) {
                        int di = g_dmap[my];
                        if (di < 0) { di = atomicAdd(&g_dcount, 1); g_dmap[my] = di; }
                        s_didx = di;
                    }
                    __syncthreads();
                    int di = s_didx;
                    if (tid < 128) {
                        float v = gru_cell(c, tid);
                        g_dmemT[tid * ND2 + di] = v;
                        float a = v * g_cv[1 + tid];
#pragma unroll
                        for (int o = 16; o; o >>= 1) a += __shfl_xor_sync(0xffffffffu, a, o);
                        if ((tid & 31) == 0) s_red[tid >> 5] = a;
                    }
                    __syncthreads();
                    if (tid == 0)
                        g_memdot[my] = s_red[0] + s_red[1] + s_red[2] + s_red[3];
                }
            } else {
                int b = blockIdx.x;
                int mynode = s_nodes[BSZ + b];
                if (tid == 0) s_win = BSZ + b;
                __syncthreads();
                if (tid < 128 && s_nodes[tid] == mynode) atomicMax(&s_win, tid);
                __syncthreads();
                int cwin = s_win;
                if (tid < 128) s_h[tid] = gru_cell(cwin, tid);
                if (tid == 128) s_xt = x[((long)(s * BSZ + b)) * NN + mynode];
                __syncthreads();
                float xt = s_xt;
                for (int r = wid; r < NROW; r += 16) {
                    float a = 0.0f;
#pragma unroll
                    for (int ch = 0; ch < 4; ch++) {
                        int l = ch * 32 + lane;
                        a = fmaf(__ldg(g_Mq + r * LL + l), s_h[l], a);
                    }
#pragma unroll
                    for (int o = 16; o; o >>= 1) a += __shfl_xor_sync(0xffffffffu, a, o);
                    if (lane == 0) {
                        float val = fmaf(g_Mqx[r], xt, a) + g_Mqc[r];
                        if (r == 0) g_ck0[b] = val;
                        else if (r < 129) g_ckm[b * LL + r - 1] = val;
                        else if (r < 145) g_cf[b * KCH + r - 129] = val;
                        else g_qbk[b] = val;
                    }
                }
            }
        }
        gsync();

        // ---- B: sdot GEMM + prep(s+1) ----
        {
            int nd = g_dcount;
            int nsd = ((nd + 31) >> 5) * 16;
            for (int wt = sw; wt < nsd + 128; wt += NWARP) {
                if (wt < nsd) {
                    int bg = wt & 15, gI = wt >> 4;
                    int i = gI * 32 + lane;
                    int ii = (i < nd) ? i : (nd - 1);
                    float ckr[4][4];
#pragma unroll
                    for (int bb = 0; bb < 4; bb++)
#pragma unroll
                        for (int j = 0; j < 4; j++)
                            ckr[bb][j] = g_ckm[(bg * 4 + bb) * LL + j * 32 + lane];
                    float acc[4] = {0.f, 0.f, 0.f, 0.f};
#pragma unroll
                    for (int ch = 0; ch < 4; ch++) {
#pragma unroll 8
                        for (int lo = 0; lo < 32; lo++) {
                            float v = g_dmemT[(ch * 32 + lo) * ND2 + ii];
#pragma unroll
                            for (int bb = 0; bb < 4; bb++)
                                acc[bb] = fmaf(__shfl_sync(0xffffffffu, ckr[bb][ch], lo), v, acc[bb]);
                        }
                    }
                    if (i < nd) {
#pragma unroll
                        for (int bb = 0; bb < 4; bb++)
                            g_sdot[(bg * 4 + bb) * ND2 + i] = acc[bb];
                    }
                } else if (s + 1 < S_LEN) {
                    prep_warp(s + 1, wt - nsd, lane, x, t, src, tgt, time_w, time_b);
                }
            }
        }
        gsync();

        // ---- C: gemm(s+1) + scores(s) + combine(s-1) ----
        if (sw < 1024) {
            if (s + 1 < S_LEN) gemm_row_half(sw >> 1, sw & 1, lane);
        } else if (sw < 1024 + 64 * NTILE) {
            int st = sw - 1024;
            scores_task(st & 63, st >> 6, lane, s, s & 1, x, t, mask, cgL, cv0);
        } else if (sw < 1024 + 64 * NTILE + 64) {
            if (s > 0) combine_warp(out, s - 1, sw - (1024 + 64 * NTILE), lane, (s - 1) & 1);
        }
        gsync();
    }

    // final combine for step 15
    if (gw < 64) combine_warp(out, S_LEN - 1, gw, lane, (S_LEN - 1) & 1);
}

// ---------------- host ----------------------------------------------------------------
extern "C" void kernel_launch(void* const* d_in, const int* in_sizes, int n_in,
                              void* d_out, int out_size) {
    const float* x       = (const float*)d_in[0];
    const float* t       = (const float*)d_in[1];
    const int*   src     = (const int*)d_in[2];
    const int*   tgt     = (const int*)d_in[3];
    const int*   mask    = (const int*)d_in[4];
    const float* time_w  = (const float*)d_in[5];
    const float* time_b  = (const float*)d_in[6];
    const float* W_ih    = (const float*)d_in[7];
    const float* W_hh    = (const float*)d_in[8];
    const float* b_ih    = (const float*)d_in[9];
    const float* b_hh    = (const float*)d_in[10];
    const float* Wq      = (const float*)d_in[11];
    const float* bq      = (const float*)d_in[12];
    const float* Wk      = (const float*)d_in[13];
    const float* bk      = (const float*)d_in[14];
    const float* Wv      = (const float*)d_in[15];
    const float* bv      = (const float*)d_in[16];
    const float* W_out   = (const float*)d_in[17];
    const float* b_out   = (const float*)d_in[18];

    k_persist<<<NBLK, NTHR>>>(x, t, src, tgt, mask, time_w, time_b,
                              W_ih, W_hh, b_ih, b_hh, Wq, bq, Wk, bk,
                              Wv, bv, W_out, b_out, (float*)d_out);
}

// round 13
// speedup vs baseline: 6.9035x; 1.0765x over previous
#include <cuda_runtime.h>
#include <math.h>

#define S_LEN 16
#define BSZ   64
#define NN    10000
#define LL    128
#define DMSG  129
#define DH    257
#define SCALE 0.08838834764831844f
#define XR    260
#define GR    512
#define NBLK  296
#define NTHR  512
#define NWARP (NBLK * 16)      // 4736
#define ND2   2048
#define KCH   16
#define NTILE 53
#define TSZ   192
#define NROW  146
#define PI_F  3.14159265358979f

// ---------------- device state ----------------------------------------------------
__device__ float g_X[XR * 128];
__device__ float g_Gp[GR * XR];
__device__ float g_bias[GR];
__device__ float g_gates[GR * 128];
__device__ float g_gatesB[GR * 128];
__device__ float g_ck0S[S_LEN * BSZ];
__device__ float g_ckmS[S_LEN * BSZ * LL];
__device__ float g_cfS[S_LEN * BSZ * KCH];
__device__ float g_qbkS[S_LEN * BSZ];
__device__ int   g_dmap[NN];
__device__ int   g_dmapS[S_LEN * NN];
__device__ int   g_cntS[S_LEN];
__device__ int   g_dcount;
__device__ float g_dmemT[LL * ND2];
__device__ float g_memdotC[ND2];
__device__ float g_sdotS[S_LEN * BSZ * ND2];   // 8MB
__device__ float g_cosk[KCH * LL];
__device__ float g_Tm[KCH * KCH];
__device__ float g_R[KCH * LL];
__device__ float g_vENC[LL];
__device__ float g_U[NROW * LL];
__device__ float g_Mq[NROW * LL];
__device__ float g_Mqx[NROW];
__device__ float g_Mqc[NROW];
__device__ float g_cg[KCH];
__device__ float4 g_partS[S_LEN * BSZ * NTILE];
__device__ float g_cv[DH];
__device__ float g_cvc;
__device__ float g_enc0[LL];
__device__ unsigned g_count;
__device__ volatile unsigned g_gen;

// ---------------- grid barrier -----------------------------------------------------
__device__ __forceinline__ void gsync() {
    __threadfence();
    __syncthreads();
    if (threadIdx.x == 0) {
        unsigned gen = g_gen;
        if (atomicAdd(&g_count, 1) == NBLK - 1) {
            g_count = 0;
            __threadfence();
            g_gen = gen + 1;
        } else {
            while (g_gen == gen) { }
            __threadfence();
        }
    }
    __syncthreads();
}

// ---------------- GRU epilogue (sums K-split partials) ------------------------------
__device__ __forceinline__ float gru_cell(int c, int j) {
    float srz = g_gates[j * 128 + c]         + g_gatesB[j * 128 + c];
    float szz = g_gates[(128 + j) * 128 + c] + g_gatesB[(128 + j) * 128 + c];
    float gin = g_gates[(256 + j) * 128 + c] + g_gatesB[(256 + j) * 128 + c];
    float ghn = g_gates[(384 + j) * 128 + c] + g_gatesB[(384 + j) * 128 + c];
    float h   = g_X[(DMSG + j) * 128 + c];
    float r = 1.0f / (1.0f + __expf(-(srz + g_bias[j])));
    float z = 1.0f / (1.0f + __expf(-(szz + g_bias[128 + j])));
    float n = tanhf(fmaf(r, ghn + g_bias[384 + j], gin + g_bias[256 + j]));
    return fmaf(z, h - n, n);
}

// ---------------- prep: build X column for cell c of step sp ------------------------
__device__ __forceinline__ void prep_warp(
        int sp, int c, int lane,
        const float* __restrict__ x, const float* __restrict__ t,
        const int* __restrict__ src, const int* __restrict__ tgt,
        const float* __restrict__ time_w, const float* __restrict__ time_b) {
    int b = c & 63, is_t = c >> 6;
    int node = (is_t ? tgt : src)[sp * BSZ + b];
    long base = ((long)(sp * BSZ + b)) * NN + node;
    float tv = __ldg(t + base);
    if (lane == 0) g_X[c] = __ldg(x + base);
    int dm = g_dmap[node];
#pragma unroll
    for (int j = 0; j < 4; j++) {
        int l = j * 32 + lane;
        g_X[(1 + l) * 128 + c] = cosf(fmaf(tv, __ldg(time_w + l), __ldg(time_b + l)));
        float h = (dm >= 0) ? g_dmemT[l * ND2 + dm] : 0.0f;
        g_X[(DMSG + l) * 128 + c] = h;
    }
}

// ---------------- lane-state softmax merge ------------------------------------------
__device__ __forceinline__ void merge_mzv(float& m, float& Z, float& V) {
#pragma unroll
    for (int o = 16; o; o >>= 1) {
        float om = __shfl_xor_sync(0xffffffffu, m, o);
        float oZ = __shfl_xor_sync(0xffffffffu, Z, o);
        float oV = __shfl_xor_sync(0xffffffffu, V, o);
        float M = fmaxf(m, om);
        float e1 = __expf(m - M), e2 = __expf(om - M);
        Z = fmaf(Z, e1, oZ * e2);
        V = fmaf(V, e1, oV * e2);
        m = M;
    }
}

// ---------------- combine NTILE(=53) partials for (cs, b) ---------------------------
__device__ __forceinline__ void combine_warp(float* __restrict__ out, int cs, int b, int lane) {
    const float4* pp = g_partS + (cs * BSZ + b) * NTILE;
    float4 p0 = pp[lane];
    float4 p1 = (lane + 32 < NTILE) ? pp[32 + lane]
                                    : make_float4(-1e30f, 0.0f, 0.0f, 0.0f);
    float m = fmaxf(p0.x, p1.x);
    float e0 = __expf(p0.x - m), e1 = __expf(p1.x - m);
    float Z = fmaf(p0.y, e0, p1.y * e1);
    float V = fmaf(p0.z, e0, p1.z * e1);
    merge_mzv(m, Z, V);
    if (lane == 0) out[cs * BSZ + b] = V / Z + g_cvc;
}

// ---------------- gates GEMM: half a row (K-split) x 128 cells per warp -------------
__device__ __forceinline__ void gemm_row_half(int j, int half, int lane) {
    int D4, xoff;
    if (j < 256)      { D4 = 65; xoff = 0; }
    else if (j < 384) { D4 = 33; xoff = 0; }
    else              { D4 = 32; xoff = DMSG; }
    int h0 = (D4 + 1) >> 1;
    int q0 = half ? h0 : 0;
    int q1 = half ? D4 : h0;

    const float4* gp = (const float4*)(g_Gp + j * XR);
    const float4* xp = ((const float4*)(g_X + xoff * 128)) + lane;
    float4 a = {0, 0, 0, 0};
#pragma unroll 4
    for (int q = q0; q < q1; q++) {
        float4 w = __ldg(gp + q);
        float4 x0 = __ldg(xp + (4 * q + 0) * 32);
        float4 x1 = __ldg(xp + (4 * q + 1) * 32);
        float4 x2 = __ldg(xp + (4 * q + 2) * 32);
        float4 x3 = __ldg(xp + (4 * q + 3) * 32);
        a.x = fmaf(w.x, x0.x, a.x); a.y = fmaf(w.x, x0.y, a.y);
        a.z = fmaf(w.x, x0.z, a.z); a.w = fmaf(w.x, x0.w, a.w);
        a.x = fmaf(w.y, x1.x, a.x); a.y = fmaf(w.y, x1.y, a.y);
        a.z = fmaf(w.y, x1.z, a.z); a.w = fmaf(w.y, x1.w, a.w);
        a.x = fmaf(w.z, x2.x, a.x); a.y = fmaf(w.z, x2.y, a.y);
        a.z = fmaf(w.z, x2.z, a.z); a.w = fmaf(w.z, x2.w, a.w);
        a.x = fmaf(w.w, x3.x, a.x); a.y = fmaf(w.w, x3.y, a.y);
        a.z = fmaf(w.w, x3.z, a.z); a.w = fmaf(w.w, x3.w, a.w);
    }
    float* dst = half ? g_gatesB : g_gates;
    ((float4*)(dst + j * 128))[lane] = a;
}

// ---------------- scores: lane-parallel rows, Chebyshev polys ------------------------
__device__ __forceinline__ void scores_task(
        int s, int b, int tile, int lane,
        const float* __restrict__ x, const float* __restrict__ t,
        const int* __restrict__ mask, float cgL, float cv0) {
    int n0 = tile * TSZ;
    int sb = s * BSZ + b;
    long base = ((long)sb) * NN;
    float cfL = g_cfS[sb * KCH + (lane & 15)];
    float qbk = g_qbkS[sb];
    float ck0 = g_ck0S[sb];
    const int* dmapS = g_dmapS + s * NN;
    const float* sdot = g_sdotS + (long)sb * ND2;

    float m = -1e30f, Z = 0.0f, V = 0.0f;
#pragma unroll
    for (int it = 0; it < TSZ / 32; it++) {
        int nn = n0 + it * 32 + lane;
        bool pred = nn < NN;
        int n = pred ? nn : (NN - 1);
        float tv = __ldg(t + base + n);
        int   mk = __ldg(mask + base + n);
        float xv = __ldg(x + base + n);
        int   dm = __ldg(dmapS + n);
        float sd = (dm >= 0) ? __ldg(sdot + dm) : 0.0f;
        float md = (dm >= 0) ? g_memdotC[dm] : 0.0f;

        float u = 2.0f * tv - 1.0f;
        float u2 = u + u;
        float b1 = 0.f, b2 = 0.f, d1 = 0.f, d2 = 0.f;
#pragma unroll
        for (int j = KCH - 1; j >= 1; j--) {
            float cj = __shfl_sync(0xffffffffu, cfL, j);
            float gj = __shfl_sync(0xffffffffu, cgL, j);
            float nb = fmaf(u2, b1, cj) - b2; b2 = b1; b1 = nb;
            float nd = fmaf(u2, d1, gj) - d2; d2 = d1; d1 = nd;
        }
        float f = fmaf(u, b1, __shfl_sync(0xffffffffu, cfL, 0)) - b2;
        float g = fmaf(u, d1, __shfl_sync(0xffffffffu, cgL, 0)) - d2;

        float sc = qbk + fmaf(ck0, xv, f) + sd;
        sc = mk ? sc : -1e9f;
        sc = pred ? sc : -3.0e38f;
        float val = fmaf(cv0, xv, md) + g;

        float M = fmaxf(m, sc);
        float eo = __expf(m - M);
        float en = __expf(sc - M);
        Z = fmaf(Z, eo, en);
        V = fmaf(V, eo, en * val);
        m = M;
    }
    merge_mzv(m, Z, V);
    if (lane == 0) g_partS[sb * NTILE + tile] = make_float4(m, Z, V, 0.0f);
}

// ---------------- the persistent kernel ----------------------------------------------
__global__ void __launch_bounds__(NTHR, 2) k_persist(
        const float* __restrict__ x, const float* __restrict__ t,
        const int* __restrict__ src, const int* __restrict__ tgt,
        const int* __restrict__ mask,
        const float* __restrict__ time_w, const float* __restrict__ time_b,
        const float* __restrict__ W_ih, const float* __restrict__ W_hh,
        const float* __restrict__ b_ih, const float* __restrict__ b_hh,
        const float* __restrict__ Wq, const float* __restrict__ bq,
        const float* __restrict__ Wk, const float* __restrict__ bk,
        const float* __restrict__ Wv, const float* __restrict__ bv,
        const float* __restrict__ W_out, const float* __restrict__ b_out,
        float* __restrict__ out) {
    __shared__ int   s_nodes[128];
    __shared__ float s_red[4];
    __shared__ float s_h[LL];
    __shared__ float s_xt;
    __shared__ int   s_win, s_didx;

    int tid = threadIdx.x;
    int lane = tid & 31, wid = tid >> 5;
    int gw = blockIdx.x * 16 + wid;
    int gtid = blockIdx.x * NTHR + tid;
    const int nthr = NBLK * NTHR;
    int sw = blockIdx.x + wid * NBLK;   // spread-mapped warp task id

    // ================= stage 1 =================
    for (int i = gtid; i < XR * 128; i += nthr) g_X[i] = 0.0f;
    for (int i = gtid; i < GR * XR; i += nthr) {
        int j = i / XR, d = i - j * XR;
        float v = 0.0f;
        if (j < 256) {
            if (d < DMSG) v = W_ih[j * DMSG + d];
            else if (d < 257) v = W_hh[j * LL + (d - DMSG)];
        } else if (j < 384) {
            if (d < DMSG) v = W_ih[j * DMSG + d];
        } else {
            if (d < LL) v = W_hh[(j - 128) * LL + d];
        }
        g_Gp[i] = v;
    }
    for (int i = gtid; i < GR; i += nthr) {
        float v;
        if (i < 256) v = b_ih[i] + b_hh[i];
        else if (i < 384) v = b_ih[i];
        else v = b_hh[i - 128];
        g_bias[i] = v;
    }
    for (int i = gtid; i < NN; i += nthr) g_dmap[i] = -1;
    for (int d = gw; d < DH; d += NWARP) {
        float a = 0.0f;
        const float* wr = Wv + d * LL;
#pragma unroll
        for (int ch = 0; ch < 4; ch++)
            a = fmaf(__ldg(wr + ch * 32 + lane), __ldg(W_out + ch * 32 + lane), a);
#pragma unroll
        for (int o = 16; o; o >>= 1) a += __shfl_xor_sync(0xffffffffu, a, o);
        if (lane == 0) g_cv[d] = a;
    }
    if (gw == 300) {
        float a = 0.0f;
#pragma unroll
        for (int ch = 0; ch < 4; ch++)
            a = fmaf(__ldg(bv + ch * 32 + lane), __ldg(W_out + ch * 32 + lane), a);
#pragma unroll
        for (int o = 16; o; o >>= 1) a += __shfl_xor_sync(0xffffffffu, a, o);
        if (lane == 0) g_cvc = a + b_out[0];
    }
    for (int i = gtid; i < LL; i += nthr) g_enc0[i] = cosf(time_b[i]);
    for (int i = gtid; i < KCH * LL; i += nthr) {
        int k = i >> 7, l = i & 127;
        float tk = 0.5f + 0.5f * cosf(PI_F * (k + 0.5f) / KCH);
        g_cosk[i] = cosf(fmaf(tk, time_w[l], time_b[l]));
    }
    for (int i = gtid; i < KCH * KCH; i += nthr) {
        int j = i >> 4, k = i & 15;
        float w = (j == 0) ? (1.0f / KCH) : (2.0f / KCH);
        g_Tm[i] = w * cosf(j * PI_F * (k + 0.5f) / KCH);
    }
    if (gtid == 0) g_dcount = 0;
    gsync();

    // ================= stage 2: R, vENC, cg fit, prep(0) =================
    if (gtid < KCH * LL) {
        int k = gtid >> 7, l = gtid & 127;
        float a = 0.0f;
#pragma unroll
        for (int kk = 0; kk < KCH; kk++)
            a = fmaf(g_Tm[k * KCH + kk], g_cosk[kk * LL + l], a);
        g_R[gtid] = a;
    } else if (gtid < KCH * LL + LL) {
        int l = gtid - KCH * LL;
        float a = 0.0f;
#pragma unroll 8
        for (int j = 0; j < LL; j++)
            a = fmaf(__ldg(Wq + (DMSG + j) * LL + l), g_enc0[j], a);
        g_vENC[l] = a;
    }
    if (gw == 296) {
        float gv = 0.0f;
        if (lane < KCH)
            for (int l = 0; l < LL; l++)
                gv = fmaf(g_cv[1 + LL + l], g_cosk[lane * LL + l], gv);
        if (lane < KCH) {
            float c = 0.0f;
#pragma unroll
            for (int k = 0; k < KCH; k++)
                c = fmaf(g_Tm[lane * KCH + k], __shfl_sync(0x0000ffffu, gv, k), c);
            g_cg[lane] = c;
        }
    }
    if (gw >= 8 && gw < 136) prep_warp(0, gw - 8, lane, x, t, src, tgt, time_w, time_b);
    gsync();

    // ================= stage 3: U table =================
    for (int i = gtid; i < 129 * LL; i += nthr) {
        int r = i >> 7, l = i & 127;
        g_U[i] = Wk[r * LL + l];
    }
    for (int i = gtid; i < LL; i += nthr) g_U[145 * LL + i] = bk[i];
    for (int i = gtid; i < KCH * LL; i += nthr) {
        int k = i >> 7, l = i & 127;
        float a = 0.0f;
#pragma unroll 8
        for (int lp = 0; lp < LL; lp++)
            a = fmaf(g_R[k * LL + lp], __ldg(Wk + (DMSG + lp) * LL + l), a);
        g_U[(129 + k) * LL + l] = a;
    }
    gsync();

    // ================= stage 4: Mq pack + gemm(0) =================
    if (sw < 1024) gemm_row_half(sw >> 1, sw & 1, lane);
    for (int mtask = sw; mtask < NROW * 130; mtask += NWARP) {
        int r = mtask / 130, c = mtask - r * 130;
        float a = 0.0f;
        if (c < 128) {
            const float* v = Wq + (1 + c) * LL;
#pragma unroll
            for (int ch = 0; ch < 4; ch++)
                a = fmaf(g_U[r * LL + ch * 32 + lane], __ldg(v + ch * 32 + lane), a);
        } else if (c == 128) {
#pragma unroll
            for (int ch = 0; ch < 4; ch++)
                a = fmaf(g_U[r * LL + ch * 32 + lane], __ldg(Wq + ch * 32 + lane), a);
        } else {
#pragma unroll
            for (int ch = 0; ch < 4; ch++) {
                int l = ch * 32 + lane;
                a = fmaf(g_U[r * LL + l], g_vENC[l] + __ldg(bq + l), a);
            }
        }
#pragma unroll
        for (int o = 16; o; o >>= 1) a += __shfl_xor_sync(0xffffffffu, a, o);
        if (lane == 0) {
            a *= SCALE;
            if (c < 128) g_Mq[r * LL + c] = a;
            else if (c == 128) g_Mqx[r] = a;
            else g_Mqc[r] = a;
        }
    }
    gsync();

    float cgL = g_cg[lane & 15];
    float cv0 = g_cv[0];

    // ================= serial step loop (light) =================
    for (int s = 0; s < S_LEN; s++) {
        // ---- A: qck (blocks 0..63) + scatter (blocks 64..191) ----
        if (blockIdx.x < 192) {
            if (tid < 128)
                s_nodes[tid] = (tid < BSZ) ? src[s * BSZ + tid] : tgt[s * BSZ + (tid - BSZ)];
            __syncthreads();

            if (blockIdx.x >= 64) {
                int c = blockIdx.x - 64;
                int my = s_nodes[c];
                bool loser = (tid < 128) && (tid > c) && (s_nodes[tid] == my);
                bool skip = __syncthreads_or(loser);
                if (!skip) {
                    if (tid == 0) {
                        int di = atomicAdd(&g_dcount, 1);   // fresh column per write
                        g_dmap[my] = di;
                        s_didx = di;
                    }
                    __syncthreads();
                    int di = s_didx;
                    if (tid < 128) {
                        float v = gru_cell(c, tid);
                        g_dmemT[tid * ND2 + di] = v;
                        float a = v * g_cv[1 + tid];
#pragma unroll
                        for (int o = 16; o; o >>= 1) a += __shfl_xor_sync(0xffffffffu, a, o);
                        if ((tid & 31) == 0) s_red[tid >> 5] = a;
                    }
                    __syncthreads();
                    if (tid == 0)
                        g_memdotC[di] = s_red[0] + s_red[1] + s_red[2] + s_red[3];
                }
            } else {
                int b = blockIdx.x;
                int mynode = s_nodes[BSZ + b];
                if (tid == 0) s_win = BSZ + b;
                __syncthreads();
                if (tid < 128 && s_nodes[tid] == mynode) atomicMax(&s_win, tid);
                __syncthreads();
                int cwin = s_win;
                if (tid < 128) s_h[tid] = gru_cell(cwin, tid);
                if (tid == 128) s_xt = x[((long)(s * BSZ + b)) * NN + mynode];
                __syncthreads();
                float xt = s_xt;
                int sb = s * BSZ + b;
                for (int r = wid; r < NROW; r += 16) {
                    float a = 0.0f;
#pragma unroll
                    for (int ch = 0; ch < 4; ch++) {
                        int l = ch * 32 + lane;
                        a = fmaf(__ldg(g_Mq + r * LL + l), s_h[l], a);
                    }
#pragma unroll
                    for (int o = 16; o; o >>= 1) a += __shfl_xor_sync(0xffffffffu, a, o);
                    if (lane == 0) {
                        float val = fmaf(g_Mqx[r], xt, a) + g_Mqc[r];
                        if (r == 0) g_ck0S[sb] = val;
                        else if (r < 129) g_ckmS[sb * LL + r - 1] = val;
                        else if (r < 145) g_cfS[sb * KCH + r - 129] = val;
                        else g_qbkS[sb] = val;
                    }
                }
            }
        }
        gsync();

        // ---- B: prep(s+1) + snapshot dmapS[s] + record cnt ----
        {
            if (sw < 128) {
                if (s + 1 < S_LEN)
                    prep_warp(s + 1, sw, lane, x, t, src, tgt, time_w, time_b);
            } else if (sw < 128 + 313) {
                int i0 = (sw - 128) * 32 + lane;
                if (i0 < NN) g_dmapS[s * NN + i0] = g_dmap[i0];
            } else if (sw == 512 && lane == 0) {
                g_cntS[s] = g_dcount;
            }
        }
        gsync();

        // ---- C: gemm(s+1) ----
        if (s + 1 < S_LEN) {
            if (sw < 1024) gemm_row_half(sw >> 1, sw & 1, lane);
            gsync();
        }
    }
    gsync();

    // ================= mega-sdot: 16 GEMMs 64 x cnt[s] x 128 =================
    for (int wt = sw; wt < S_LEN * 1024; wt += NWARP) {
        int s = wt >> 10;
        int rem = wt & 1023;
        int bg = rem & 15, gI = rem >> 4;       // gI: 0..63 col groups
        int cnt = g_cntS[s];
        if (gI * 32 >= cnt) continue;
        int i = gI * 32 + lane;
        int ii = (i < cnt) ? i : (cnt - 1);
        float ckr[4][4];
#pragma unroll
        for (int bb = 0; bb < 4; bb++)
#pragma unroll
            for (int j = 0; j < 4; j++)
                ckr[bb][j] = g_ckmS[(s * BSZ + bg * 4 + bb) * LL + j * 32 + lane];
        float acc[4] = {0.f, 0.f, 0.f, 0.f};
#pragma unroll
        for (int ch = 0; ch < 4; ch++) {
#pragma unroll 8
            for (int lo = 0; lo < 32; lo++) {
                float v = g_dmemT[(ch * 32 + lo) * ND2 + ii];
#pragma unroll
                for (int bb = 0; bb < 4; bb++)
                    acc[bb] = fmaf(__shfl_sync(0xffffffffu, ckr[bb][ch], lo), v, acc[bb]);
            }
        }
        if (i < cnt) {
#pragma unroll
            for (int bb = 0; bb < 4; bb++)
                g_sdotS[(long)(s * BSZ + bg * 4 + bb) * ND2 + i] = acc[bb];
        }
    }
    gsync();

    // ================= mega-scores: all (s, b, tile) =================
    for (int wt = sw; wt < S_LEN * BSZ * NTILE; wt += NWARP) {
        int s = wt / (BSZ * NTILE);
        int rem = wt - s * (BSZ * NTILE);
        scores_task(s, rem & 63, rem >> 6, lane, x, t, mask, cgL, cv0);
    }
    gsync();

    // ================= combine: all (s, b) =================
    if (sw < S_LEN * BSZ) combine_warp(out, sw >> 6, sw & 63, lane);
}

// ---------------- host ----------------------------------------------------------------
extern "C" void kernel_launch(void* const* d_in, const int* in_sizes, int n_in,
                              void* d_out, int out_size) {
    const float* x       = (const float*)d_in[0];
    const float* t       = (const float*)d_in[1];
    const int*   src     = (const int*)d_in[2];
    const int*   tgt     = (const int*)d_in[3];
    const int*   mask    = (const int*)d_in[4];
    const float* time_w  = (const float*)d_in[5];
    const float* time_b  = (const float*)d_in[6];
    const float* W_ih    = (const float*)d_in[7];
    const float* W_hh    = (const float*)d_in[8];
    const float* b_ih    = (const float*)d_in[9];
    const float* b_hh    = (const float*)d_in[10];
    const float* Wq      = (const float*)d_in[11];
    const float* bq      = (const float*)d_in[12];
    const float* Wk      = (const float*)d_in[13];
    const float* bk      = (const float*)d_in[14];
    const float* Wv      = (const float*)d_in[15];
    const float* bv      = (const float*)d_in[16];
    const float* W_out   = (const float*)d_in[17];
    const float* b_out   = (const float*)d_in[18];

    k_persist<<<NBLK, NTHR>>>(x, t, src, tgt, mask, time_w, time_b,
                              W_ih, W_hh, b_ih, b_hh, Wq, bq, Wk, bk,
                              Wv, bv, W_out, b_out, (float*)d_out);
}

// round 14
// speedup vs baseline: 7.5669x; 1.0961x over previous
#include <cuda_runtime.h>
#include <math.h>

#define S_LEN 16
#define BSZ   64
#define NN    10000
#define LL    128
#define DMSG  129
#define DH    257
#define SCALE 0.08838834764831844f
#define XR    260
#define GR    512
#define NBLK  296
#define NTHR  512
#define NWARP (NBLK * 16)      // 4736
#define ND2   2048
#define KCH   16
#define NTILE 53
#define TSZ   192
#define NROW  146
#define PI_F  3.14159265358979f

// ---------------- f32x2 packed helpers ----------------------------------------------
__device__ __forceinline__ unsigned long long pk2(float lo, float hi) {
    unsigned long long r;
    asm("mov.b64 %0, {%1,%2};" : "=l"(r) : "f"(lo), "f"(hi));
    return r;
}
__device__ __forceinline__ void upk2(unsigned long long v, float& lo, float& hi) {
    asm("mov.b64 {%0,%1}, %2;" : "=f"(lo), "=f"(hi) : "l"(v));
}
#define FMA2(d, a, b, c) asm("fma.rn.f32x2 %0,%1,%2,%3;" : "=l"(d) : "l"(a), "l"(b), "l"(c))
#define ADD2(d, a, b)    asm("add.rn.f32x2 %0,%1,%2;"    : "=l"(d) : "l"(a), "l"(b))

// ---------------- device state ----------------------------------------------------
__device__ float g_XS[S_LEN * XR * 128];        // per-step X (pads stay 0)
__device__ float g_Gp[GR * XR];
__device__ float g_bias[GR];
__device__ float g_gatesA[S_LEN * GR * 128];
__device__ float g_gatesBf[S_LEN * GR * 128];
__device__ float g_ck0S[S_LEN * BSZ];
__device__ float g_ckmS[S_LEN * BSZ * LL];
__device__ float2 g_cfgS[S_LEN * BSZ * KCH];    // (.x=cf, .y=cg)
__device__ float g_qbkS[S_LEN * BSZ];
__device__ int   g_dmap[NN];
__device__ int   g_dmapS[S_LEN * NN];
__device__ int   g_cntS[S_LEN];
__device__ int   g_dcount;
__device__ float g_dmemT[LL * ND2];
__device__ float g_memdotC[ND2];
__device__ float g_sdotS[S_LEN * BSZ * ND2];
__device__ float g_cosk[KCH * LL];
__device__ float g_Tm[KCH * KCH];
__device__ float g_R[KCH * LL];
__device__ float g_vENC[LL];
__device__ float g_U[NROW * LL];
__device__ float g_Mq[NROW * LL];
__device__ float g_Mqx[NROW];
__device__ float g_Mqc[NROW];
__device__ float g_cg[KCH];
__device__ float4 g_partS[S_LEN * BSZ * NTILE];
__device__ float g_cv[DH];
__device__ float g_cvc;
__device__ float g_enc0[LL];
__device__ unsigned g_count;
__device__ volatile unsigned g_gen;

// ---------------- grid barrier -----------------------------------------------------
__device__ __forceinline__ void gsync() {
    __threadfence();
    __syncthreads();
    if (threadIdx.x == 0) {
        unsigned gen = g_gen;
        if (atomicAdd(&g_count, 1) == NBLK - 1) {
            g_count = 0;
            __threadfence();
            g_gen = gen + 1;
        } else {
            while (g_gen == gen) { }
            __threadfence();
        }
    }
    __syncthreads();
}

// ---------------- GRU epilogue (per-step buffers) ------------------------------------
__device__ __forceinline__ float gru_cellS(int s, int c, int j) {
    const float* gA = g_gatesA  + (size_t)s * GR * 128;
    const float* gB = g_gatesBf + (size_t)s * GR * 128;
    const float* Xs = g_XS + (size_t)s * XR * 128;
    float srz = gA[j * 128 + c]         + gB[j * 128 + c];
    float szz = gA[(128 + j) * 128 + c] + gB[(128 + j) * 128 + c];
    float gin = gA[(256 + j) * 128 + c] + gB[(256 + j) * 128 + c];
    float ghn = gA[(384 + j) * 128 + c] + gB[(384 + j) * 128 + c];
    float h   = Xs[(DMSG + j) * 128 + c];
    float r = 1.0f / (1.0f + __expf(-(srz + g_bias[j])));
    float z = 1.0f / (1.0f + __expf(-(szz + g_bias[128 + j])));
    float n = tanhf(fmaf(r, ghn + g_bias[384 + j], gin + g_bias[256 + j]));
    return fmaf(z, h - n, n);
}

// ---------------- prep for step 0 (memory all zero) ----------------------------------
__device__ __forceinline__ void prep0(
        int c, int lane,
        const float* __restrict__ x, const float* __restrict__ t,
        const int* __restrict__ src, const int* __restrict__ tgt,
        const float* __restrict__ time_w, const float* __restrict__ time_b) {
    int b = c & 63, is_t = c >> 6;
    int node = (is_t ? tgt : src)[b];
    size_t base = (size_t)b * NN + node;
    float tv = __ldg(t + base);
    float* Xn = g_XS;
    if (lane == 0) Xn[c] = __ldg(x + base);
#pragma unroll
    for (int j = 0; j < 4; j++) {
        int l = j * 32 + lane;
        Xn[(1 + l) * 128 + c] = cosf(fmaf(tv, __ldg(time_w + l), __ldg(time_b + l)));
        Xn[(DMSG + l) * 128 + c] = 0.0f;
    }
}

// ---------------- prep for step sp = s+1 (winner recompute; runs beside scatter) -----
__device__ __forceinline__ void prep_next(
        int sp, int c, int lane, int sPrev, const int* sh_nodes,
        const float* __restrict__ x, const float* __restrict__ t,
        const int* __restrict__ src, const int* __restrict__ tgt,
        const float* __restrict__ time_w, const float* __restrict__ time_b) {
    int b = c & 63, is_t = c >> 6;
    int node = (is_t ? tgt : src)[sp * BSZ + b];
    size_t base = (size_t)(sp * BSZ + b) * NN + node;
    float tv = __ldg(t + base);
    int win = -1;
#pragma unroll
    for (int k = 0; k < 4; k++) {
        int cc = k * 32 + lane;
        if (sh_nodes[cc] == node) win = cc;    // ascending k -> max per lane
    }
#pragma unroll
    for (int o = 16; o; o >>= 1) win = max(win, __shfl_xor_sync(0xffffffffu, win, o));
    int dm = -1;
    if (win < 0) dm = g_dmap[node];            // untouched this phase (node not updated)
    float* Xn = g_XS + (size_t)sp * XR * 128;
    if (lane == 0) Xn[c] = __ldg(x + base);
#pragma unroll
    for (int j = 0; j < 4; j++) {
        int l = j * 32 + lane;
        Xn[(1 + l) * 128 + c] = cosf(fmaf(tv, __ldg(time_w + l), __ldg(time_b + l)));
        float h;
        if (win >= 0) h = gru_cellS(sPrev, win, l);
        else h = (dm >= 0) ? g_dmemT[l * ND2 + dm] : 0.0f;
        Xn[(DMSG + l) * 128 + c] = h;
    }
}

// ---------------- lane-state softmax merge ------------------------------------------
__device__ __forceinline__ void merge_mzv(float& m, float& Z, float& V) {
#pragma unroll
    for (int o = 16; o; o >>= 1) {
        float om = __shfl_xor_sync(0xffffffffu, m, o);
        float oZ = __shfl_xor_sync(0xffffffffu, Z, o);
        float oV = __shfl_xor_sync(0xffffffffu, V, o);
        float M = fmaxf(m, om);
        float e1 = __expf(m - M), e2 = __expf(om - M);
        Z = fmaf(Z, e1, oZ * e2);
        V = fmaf(V, e1, oV * e2);
        m = M;
    }
}

// ---------------- combine NTILE partials for (cs, b) ---------------------------------
__device__ __forceinline__ void combine_warp(float* __restrict__ out, int cs, int b, int lane) {
    const float4* pp = g_partS + (cs * BSZ + b) * NTILE;
    float4 p0 = pp[lane];
    float4 p1 = (lane + 32 < NTILE) ? pp[32 + lane]
                                    : make_float4(-1e30f, 0.0f, 0.0f, 0.0f);
    float m = fmaxf(p0.x, p1.x);
    float e0 = __expf(p0.x - m), e1 = __expf(p1.x - m);
    float Z = fmaf(p0.y, e0, p1.y * e1);
    float V = fmaf(p0.z, e0, p1.z * e1);
    merge_mzv(m, Z, V);
    if (lane == 0) out[cs * BSZ + b] = V / Z + g_cvc;
}

// ---------------- gates GEMM: half a row (K-split) into step buffers -----------------
__device__ __forceinline__ void gemm_row_half(int sp, int j, int half, int lane) {
    int D4, xoff;
    if (j < 256)      { D4 = 65; xoff = 0; }
    else if (j < 384) { D4 = 33; xoff = 0; }
    else              { D4 = 32; xoff = DMSG; }
    int h0 = (D4 + 1) >> 1;
    int q0 = half ? h0 : 0;
    int q1 = half ? D4 : h0;

    const float* Xs = g_XS + (size_t)sp * XR * 128;
    const float4* gp = (const float4*)(g_Gp + j * XR);
    const float4* xp = ((const float4*)(Xs + xoff * 128)) + lane;
    float4 a = {0, 0, 0, 0};
#pragma unroll 4
    for (int q = q0; q < q1; q++) {
        float4 w = __ldg(gp + q);
        float4 x0 = __ldg(xp + (4 * q + 0) * 32);
        float4 x1 = __ldg(xp + (4 * q + 1) * 32);
        float4 x2 = __ldg(xp + (4 * q + 2) * 32);
        float4 x3 = __ldg(xp + (4 * q + 3) * 32);
        a.x = fmaf(w.x, x0.x, a.x); a.y = fmaf(w.x, x0.y, a.y);
        a.z = fmaf(w.x, x0.z, a.z); a.w = fmaf(w.x, x0.w, a.w);
        a.x = fmaf(w.y, x1.x, a.x); a.y = fmaf(w.y, x1.y, a.y);
        a.z = fmaf(w.y, x1.z, a.z); a.w = fmaf(w.y, x1.w, a.w);
        a.x = fmaf(w.z, x2.x, a.x); a.y = fmaf(w.z, x2.y, a.y);
        a.z = fmaf(w.z, x2.z, a.z); a.w = fmaf(w.z, x2.w, a.w);
        a.x = fmaf(w.w, x3.x, a.x); a.y = fmaf(w.w, x3.y, a.y);
        a.z = fmaf(w.w, x3.z, a.z); a.w = fmaf(w.w, x3.w, a.w);
    }
    float* dst = (half ? g_gatesBf : g_gatesA) + (size_t)sp * GR * 128;
    ((float4*)(dst + j * 128))[lane] = a;
}

// ---------------- mega-qck: one warp per (s, b) ---------------------------------------
__device__ __forceinline__ void qck_task(
        int s, int b, int lane,
        const float* __restrict__ x,
        const int* __restrict__ src, const int* __restrict__ tgt) {
    int nd = tgt[s * BSZ + b];
    int win = -1;
#pragma unroll
    for (int k = 0; k < 4; k++) {
        int cc = k * 32 + lane;
        int nn2 = (cc < 64) ? src[s * BSZ + cc] : tgt[s * BSZ + cc - 64];
        if (nn2 == nd) win = cc;
    }
#pragma unroll
    for (int o = 16; o; o >>= 1) win = max(win, __shfl_xor_sync(0xffffffffu, win, o));
    float h[4];
#pragma unroll
    for (int k = 0; k < 4; k++) h[k] = gru_cellS(s, win, k * 32 + lane);
    float xt = __ldg(x + (size_t)(s * BSZ + b) * NN + nd);
    int sb = s * BSZ + b;
    for (int r = 0; r < NROW; r++) {
        float a = 0.0f;
#pragma unroll
        for (int k = 0; k < 4; k++)
            a = fmaf(__ldg(g_Mq + r * LL + k * 32 + lane), h[k], a);
#pragma unroll
        for (int o = 16; o; o >>= 1) a += __shfl_xor_sync(0xffffffffu, a, o);
        if (lane == 0) {
            float val = fmaf(g_Mqx[r], xt, a) + g_Mqc[r];
            if (r == 0) g_ck0S[sb] = val;
            else if (r < 129) g_ckmS[sb * LL + r - 1] = val;
            else if (r < 145) g_cfgS[sb * KCH + r - 129].x = val;
            else g_qbkS[sb] = val;
        }
    }
}

// ---------------- scores: f32x2 packed Clenshaw ---------------------------------------
__device__ __forceinline__ void scores_task(
        int s, int b, int tile, int lane,
        const float* __restrict__ x, const float* __restrict__ t,
        const int* __restrict__ mask, float cv0) {
    int n0 = tile * TSZ;
    int sb = s * BSZ + b;
    size_t base = (size_t)sb * NN;
    const unsigned long long* cfg = (const unsigned long long*)(g_cfgS + sb * KCH);
    float qbk = g_qbkS[sb];
    float ck0 = g_ck0S[sb];
    const int* dmapS = g_dmapS + s * NN;
    const float* sdot = g_sdotS + (size_t)sb * ND2;
    const unsigned long long NEG2 = 0x8000000080000000ULL;

    float m = -1e30f, Z = 0.0f, V = 0.0f;
#pragma unroll
    for (int it = 0; it < TSZ / 32; it++) {
        int nn = n0 + it * 32 + lane;
        bool pred = nn < NN;
        int n = pred ? nn : (NN - 1);
        float tv = __ldg(t + base + n);
        int   mk = __ldg(mask + base + n);
        float xv = __ldg(x + base + n);
        int   dm = __ldg(dmapS + n);
        float sd = (dm >= 0) ? __ldg(sdot + dm) : 0.0f;
        float md = (dm >= 0) ? g_memdotC[dm] : 0.0f;

        float u = 2.0f * tv - 1.0f;
        unsigned long long u2p = pk2(u + u, u + u);
        unsigned long long b1 = 0ULL, mb2 = 0ULL;
#pragma unroll
        for (int j = KCH - 1; j >= 1; j--) {
            unsigned long long cj = __ldg(cfg + j);
            unsigned long long tmp, nb;
            FMA2(tmp, u2p, b1, cj);
            ADD2(nb, tmp, mb2);
            mb2 = b1 ^ NEG2;
            b1 = nb;
        }
        unsigned long long up = pk2(u, u);
        unsigned long long fin;
        FMA2(fin, up, b1, mb2);
        unsigned long long c0 = __ldg(cfg);
        ADD2(fin, fin, c0);
        float f, g;
        upk2(fin, f, g);

        float sc = qbk + fmaf(ck0, xv, f) + sd;
        sc = mk ? sc : -1e9f;
        sc = pred ? sc : -3.0e38f;
        float val = fmaf(cv0, xv, md) + g;

        float M = fmaxf(m, sc);
        float eo = __expf(m - M);
        float en = __expf(sc - M);
        Z = fmaf(Z, eo, en);
        V = fmaf(V, eo, en * val);
        m = M;
    }
    merge_mzv(m, Z, V);
    if (lane == 0) g_partS[sb * NTILE + tile] = make_float4(m, Z, V, 0.0f);
}

// ---------------- the persistent kernel ----------------------------------------------
__global__ void __launch_bounds__(NTHR, 2) k_persist(
        const float* __restrict__ x, const float* __restrict__ t,
        const int* __restrict__ src, const int* __restrict__ tgt,
        const int* __restrict__ mask,
        const float* __restrict__ time_w, const float* __restrict__ time_b,
        const float* __restrict__ W_ih, const float* __restrict__ W_hh,
        const float* __restrict__ b_ih, const float* __restrict__ b_hh,
        const float* __restrict__ Wq, const float* __restrict__ bq,
        const float* __restrict__ Wk, const float* __restrict__ bk,
        const float* __restrict__ Wv, const float* __restrict__ bv,
        const float* __restrict__ W_out, const float* __restrict__ b_out,
        float* __restrict__ out) {
    __shared__ int   s_nodes[128];
    __shared__ float s_red[4];
    __shared__ int   s_didx;

    int tid = threadIdx.x;
    int lane = tid & 31, wid = tid >> 5;
    int gw = blockIdx.x * 16 + wid;
    int gtid = blockIdx.x * NTHR + tid;
    const int nthr = NBLK * NTHR;
    int sw = blockIdx.x + wid * NBLK;

    // ================= S1 =================
    for (int i = gtid; i < GR * XR; i += nthr) {
        int j = i / XR, d = i - j * XR;
        float v = 0.0f;
        if (j < 256) {
            if (d < DMSG) v = W_ih[j * DMSG + d];
            else if (d < 257) v = W_hh[j * LL + (d - DMSG)];
        } else if (j < 384) {
            if (d < DMSG) v = W_ih[j * DMSG + d];
        } else {
            if (d < LL) v = W_hh[(j - 128) * LL + d];
        }
        g_Gp[i] = v;
    }
    for (int i = gtid; i < GR; i += nthr) {
        float v;
        if (i < 256) v = b_ih[i] + b_hh[i];
        else if (i < 384) v = b_ih[i];
        else v = b_hh[i - 128];
        g_bias[i] = v;
    }
    for (int i = gtid; i < NN; i += nthr) g_dmap[i] = -1;
    for (int d = gw; d < DH; d += NWARP) {
        float a = 0.0f;
        const float* wr = Wv + d * LL;
#pragma unroll
        for (int ch = 0; ch < 4; ch++)
            a = fmaf(__ldg(wr + ch * 32 + lane), __ldg(W_out + ch * 32 + lane), a);
#pragma unroll
        for (int o = 16; o; o >>= 1) a += __shfl_xor_sync(0xffffffffu, a, o);
        if (lane == 0) g_cv[d] = a;
    }
    if (gw == 300) {
        float a = 0.0f;
#pragma unroll
        for (int ch = 0; ch < 4; ch++)
            a = fmaf(__ldg(bv + ch * 32 + lane), __ldg(W_out + ch * 32 + lane), a);
#pragma unroll
        for (int o = 16; o; o >>= 1) a += __shfl_xor_sync(0xffffffffu, a, o);
        if (lane == 0) g_cvc = a + b_out[0];
    }
    for (int i = gtid; i < LL; i += nthr) g_enc0[i] = cosf(time_b[i]);
    for (int i = gtid; i < KCH * LL; i += nthr) {
        int k = i >> 7, l = i & 127;
        float tk = 0.5f + 0.5f * cosf(PI_F * (k + 0.5f) / KCH);
        g_cosk[i] = cosf(fmaf(tk, time_w[l], time_b[l]));
    }
    for (int i = gtid; i < KCH * KCH; i += nthr) {
        int j = i >> 4, k = i & 15;
        float w = (j == 0) ? (1.0f / KCH) : (2.0f / KCH);
        g_Tm[i] = w * cosf(j * PI_F * (k + 0.5f) / KCH);
    }
    if (gtid == 0) g_dcount = 0;
    gsync();

    // ================= S2: R, vENC, cg =================
    if (gtid < KCH * LL) {
        int k = gtid >> 7, l = gtid & 127;
        float a = 0.0f;
#pragma unroll
        for (int kk = 0; kk < KCH; kk++)
            a = fmaf(g_Tm[k * KCH + kk], g_cosk[kk * LL + l], a);
        g_R[gtid] = a;
    } else if (gtid < KCH * LL + LL) {
        int l = gtid - KCH * LL;
        float a = 0.0f;
#pragma unroll 8
        for (int j = 0; j < LL; j++)
            a = fmaf(__ldg(Wq + (DMSG + j) * LL + l), g_enc0[j], a);
        g_vENC[l] = a;
    }
    if (gw == 296) {
        float gv = 0.0f;
        if (lane < KCH)
            for (int l = 0; l < LL; l++)
                gv = fmaf(g_cv[1 + LL + l], g_cosk[lane * LL + l], gv);
        if (lane < KCH) {
            float c = 0.0f;
#pragma unroll
            for (int k = 0; k < KCH; k++)
                c = fmaf(g_Tm[lane * KCH + k], __shfl_sync(0x0000ffffu, gv, k), c);
            g_cg[lane] = c;
        }
    }
    gsync();

    // ================= S3: U table + cfg .y prefill + prep(0) =================
    for (int i = gtid; i < 129 * LL; i += nthr) {
        int r = i >> 7, l = i & 127;
        g_U[i] = Wk[r * LL + l];
    }
    for (int i = gtid; i < LL; i += nthr) g_U[145 * LL + i] = bk[i];
    for (int i = gtid; i < KCH * LL; i += nthr) {
        int k = i >> 7, l = i & 127;
        float a = 0.0f;
#pragma unroll 8
        for (int lp = 0; lp < LL; lp++)
            a = fmaf(g_R[k * LL + lp], __ldg(Wk + (DMSG + lp) * LL + l), a);
        g_U[(129 + k) * LL + l] = a;
    }
    for (int i = gtid; i < S_LEN * BSZ * KCH; i += nthr)
        g_cfgS[i].y = g_cg[i & 15];
    if (gw >= 400 && gw < 528) prep0(gw - 400, lane, x, t, src, tgt, time_w, time_b);
    gsync();

    // ================= S4: Mq pack + gemm(0) =================
    if (sw < 1024) gemm_row_half(0, sw >> 1, sw & 1, lane);
    for (int mtask = sw; mtask < NROW * 130; mtask += NWARP) {
        int r = mtask / 130, c = mtask - r * 130;
        float a = 0.0f;
        if (c < 128) {
            const float* v = Wq + (1 + c) * LL;
#pragma unroll
            for (int ch = 0; ch < 4; ch++)
                a = fmaf(g_U[r * LL + ch * 32 + lane], __ldg(v + ch * 32 + lane), a);
        } else if (c == 128) {
#pragma unroll
            for (int ch = 0; ch < 4; ch++)
                a = fmaf(g_U[r * LL + ch * 32 + lane], __ldg(Wq + ch * 32 + lane), a);
        } else {
#pragma unroll
            for (int ch = 0; ch < 4; ch++) {
                int l = ch * 32 + lane;
                a = fmaf(g_U[r * LL + l], g_vENC[l] + __ldg(bq + l), a);
            }
        }
#pragma unroll
        for (int o = 16; o; o >>= 1) a += __shfl_xor_sync(0xffffffffu, a, o);
        if (lane == 0) {
            a *= SCALE;
            if (c < 128) g_Mq[r * LL + c] = a;
            else if (c == 128) g_Mqx[r] = a;
            else g_Mqc[r] = a;
        }
    }
    gsync();

    float cv0 = g_cv[0];

    // ================= serial loop: 2 phases/step =================
    for (int s = 0; s < S_LEN; s++) {
        // ---- A: scatter(s) [blocks 64..191] + prep(s+1) [blocks 0..63] ----
        if (blockIdx.x < 192) {
            if (tid < 128)
                s_nodes[tid] = (tid < BSZ) ? src[s * BSZ + tid] : tgt[s * BSZ + (tid - BSZ)];
            __syncthreads();

            if (blockIdx.x >= 64) {
                int c = blockIdx.x - 64;
                int my = s_nodes[c];
                bool loser = (tid < 128) && (tid > c) && (s_nodes[tid] == my);
                bool skip = __syncthreads_or(loser);
                if (!skip) {
                    if (tid == 0) {
                        int di = atomicAdd(&g_dcount, 1);
                        g_dmap[my] = di;
                        s_didx = di;
                    }
                    __syncthreads();
                    int di = s_didx;
                    if (tid < 128) {
                        float v = gru_cellS(s, c, tid);
                        g_dmemT[tid * ND2 + di] = v;
                        float a = v * g_cv[1 + tid];
#pragma unroll
                        for (int o = 16; o; o >>= 1) a += __shfl_xor_sync(0xffffffffu, a, o);
                        if ((tid & 31) == 0) s_red[tid >> 5] = a;
                    }
                    __syncthreads();
                    if (tid == 0)
                        g_memdotC[di] = s_red[0] + s_red[1] + s_red[2] + s_red[3];
                }
            } else if (wid < 2 && s + 1 < S_LEN) {
                int c2 = blockIdx.x * 2 + wid;
                prep_next(s + 1, c2, lane, s, s_nodes, x, t, src, tgt, time_w, time_b);
            }
        }
        gsync();

        // ---- B: gemm(s+1) + snapshot(s) + cnt(s) ----
        if (sw < 1024) {
            if (s + 1 < S_LEN) gemm_row_half(s + 1, sw >> 1, sw & 1, lane);
        } else if (sw < 1024 + 313) {
            int i0 = (sw - 1024) * 32 + lane;
            if (i0 < NN) g_dmapS[s * NN + i0] = g_dmap[i0];
        } else if (sw == 1400 && lane == 0) {
            g_cntS[s] = g_dcount;
        }
        gsync();
    }

    // ================= mega-qck =================
    if (sw < S_LEN * BSZ) qck_task(sw >> 6, sw & 63, lane, x, src, tgt);
    gsync();

    // ================= mega-sdot =================
    for (int wt = sw; wt < S_LEN * 1024; wt += NWARP) {
        int s = wt >> 10;
        int rem = wt & 1023;
        int bg = rem & 15, gI = rem >> 4;
        int cnt = g_cntS[s];
        if (gI * 32 >= cnt) continue;
        int i = gI * 32 + lane;
        int ii = (i < cnt) ? i : (cnt - 1);
        float ckr[4][4];
#pragma unroll
        for (int bb = 0; bb < 4; bb++)
#pragma unroll
            for (int j = 0; j < 4; j++)
                ckr[bb][j] = g_ckmS[(s * BSZ + bg * 4 + bb) * LL + j * 32 + lane];
        float acc[4] = {0.f, 0.f, 0.f, 0.f};
#pragma unroll
        for (int ch = 0; ch < 4; ch++) {
#pragma unroll 8
            for (int lo = 0; lo < 32; lo++) {
                float v = g_dmemT[(ch * 32 + lo) * ND2 + ii];
#pragma unroll
                for (int bb = 0; bb < 4; bb++)
                    acc[bb] = fmaf(__shfl_sync(0xffffffffu, ckr[bb][ch], lo), v, acc[bb]);
            }
        }
        if (i < cnt) {
#pragma unroll
            for (int bb = 0; bb < 4; bb++)
                g_sdotS[(size_t)(s * BSZ + bg * 4 + bb) * ND2 + i] = acc[bb];
        }
    }
    gsync();

    // ================= mega-scores =================
    for (int wt = sw; wt < S_LEN * BSZ * NTILE; wt += NWARP) {
        int s = wt / (BSZ * NTILE);
        int rem = wt - s * (BSZ * NTILE);
        scores_task(s, rem & 63, rem >> 6, lane, x, t, mask, cv0);
    }
    gsync();

    // ================= combine =================
    if (sw < S_LEN * BSZ) combine_warp(out, sw >> 6, sw & 63, lane);
}

// ---------------- host ----------------------------------------------------------------
extern "C" void kernel_launch(void* const* d_in, const int* in_sizes, int n_in,
                              void* d_out, int out_size) {
    const float* x       = (const float*)d_in[0];
    const float* t       = (const float*)d_in[1];
    const int*   src     = (const int*)d_in[2];
    const int*   tgt     = (const int*)d_in[3];
    const int*   mask    = (const int*)d_in[4];
    const float* time_w  = (const float*)d_in[5];
    const float* time_b  = (const float*)d_in[6];
    const float* W_ih    = (const float*)d_in[7];
    const float* W_hh    = (const float*)d_in[8];
    const float* b_ih    = (const float*)d_in[9];
    const float* b_hh    = (const float*)d_in[10];
    const float* Wq      = (const float*)d_in[11];
    const float* bq      = (const float*)d_in[12];
    const float* Wk      = (const float*)d_in[13];
    const float* bk      = (const float*)d_in[14];
    const float* Wv      = (const float*)d_in[15];
    const float* bv      = (const float*)d_in[16];
    const float* W_out   = (const float*)d_in[17];
    const float* b_out   = (const float*)d_in[18];

    k_persist<<<NBLK, NTHR>>>(x, t, src, tgt, mask, time_w, time_b,
                              W_ih, W_hh, b_ih, b_hh, Wq, bq, Wk, bk,
                              Wv, bv, W_out, b_out, (float*)d_out);
}

// round 15
// speedup vs baseline: 9.9690x; 1.3175x over previous
#include <cuda_runtime.h>
#include <math.h>

#define S_LEN 16
#define BSZ   64
#define NN    10000
#define LL    128
#define DMSG  129
#define DH    257
#define SCALE 0.08838834764831844f
#define NBLK  296
#define NTHR  512
#define NWARP (NBLK * 16)      // 4736
#define ND2   2048
#define KCH   12
#define NTILE 53
#define TSZ   192
#define NROW  142              // ck0(1) + ckm(128) + cf(12) + qbk(1)
#define PI_F  3.14159265358979f

// ---------------- f32x2 packed helpers ----------------------------------------------
__device__ __forceinline__ unsigned long long pk2(float lo, float hi) {
    unsigned long long r;
    asm("mov.b64 %0, {%1,%2};" : "=l"(r) : "f"(lo), "f"(hi));
    return r;
}
__device__ __forceinline__ void upk2(unsigned long long v, float& lo, float& hi) {
    asm("mov.b64 {%0,%1}, %2;" : "=f"(lo), "=f"(hi) : "l"(v));
}
#define FMA2(d, a, b, c) asm("fma.rn.f32x2 %0,%1,%2,%3;" : "=l"(d) : "l"(a), "l"(b), "l"(c))
#define ADD2(d, a, b)    asm("add.rn.f32x2 %0,%1,%2;"    : "=l"(d) : "l"(a), "l"(b))

// ---------------- device state ----------------------------------------------------
__device__ float g_Xc[S_LEN * 132 * 128];       // per-step msg (x, cos); pads zero
__device__ float g_GpIH[384 * 132];             // W_ih rows padded to 132
__device__ float g_gIH[S_LEN * 384 * 128];      // IH gemm out (b_ih folded)
__device__ float g_WhhT[128 * 384];             // W_hh transposed
__device__ float g_ck0S[S_LEN * BSZ];
__device__ float g_ckmS[S_LEN * BSZ * LL];
__device__ float2 g_cfgS[S_LEN * BSZ * KCH];    // (.x=cf, .y=cg)
__device__ float g_qbkS[S_LEN * BSZ];
__device__ int   g_dmap[NN];                    // rolling
__device__ int   g_dmapP[(S_LEN + 1) * NN];     // snapshots; row 0 = all -1
__device__ int   g_cntS[S_LEN];
__device__ int   g_dcount;
__device__ float g_dmemT[LL * ND2];
__device__ float g_memdotC[ND2];
__device__ float g_sdotS[S_LEN * BSZ * ND2];
__device__ float g_cosk[KCH * LL];
__device__ float g_Tm[KCH * KCH];
__device__ float g_R[KCH * LL];
__device__ float g_vENC[LL];
__device__ float g_U[NROW * LL];
__device__ float g_Mq[NROW * LL];
__device__ float g_Mqx[NROW];
__device__ float g_Mqc[NROW];
__device__ float g_cg[KCH];
__device__ float4 g_partS[S_LEN * BSZ * NTILE];
__device__ float g_cv[DH];
__device__ float g_cvc;
__device__ float g_enc0[LL];
__device__ unsigned g_count;
__device__ volatile unsigned g_gen;

// ---------------- grid barrier -----------------------------------------------------
__device__ __forceinline__ void gsync() {
    __threadfence();
    __syncthreads();
    if (threadIdx.x == 0) {
        unsigned gen = g_gen;
        if (atomicAdd(&g_count, 1) == NBLK - 1) {
            g_count = 0;
            __threadfence();
            g_gen = gen + 1;
        } else {
            while (g_gen == gen) { }
            __threadfence();
        }
    }
    __syncthreads();
}

// ---------------- prep-cos: msg column for cell c of step sp (one warp) -------------
__device__ __forceinline__ void prep_cos(
        int sp, int c, int lane,
        const float* __restrict__ x, const float* __restrict__ t,
        const int* __restrict__ src, const int* __restrict__ tgt,
        const float* __restrict__ time_w, const float* __restrict__ time_b) {
    int b = c & 63, is_t = c >> 6;
    int node = (is_t ? tgt : src)[sp * BSZ + b];
    size_t base = (size_t)(sp * BSZ + b) * NN + node;
    float tv = __ldg(t + base);
    float* Xn = g_Xc + (size_t)sp * 132 * 128;
    if (lane == 0) Xn[c] = __ldg(x + base);
#pragma unroll
    for (int j = 0; j < 4; j++) {
        int l = j * 32 + lane;
        Xn[(1 + l) * 128 + c] = cosf(fmaf(tv, __ldg(time_w + l), __ldg(time_b + l)));
    }
}

// ---------------- lane-state softmax merge ------------------------------------------
__device__ __forceinline__ void merge_mzv(float& m, float& Z, float& V) {
#pragma unroll
    for (int o = 16; o; o >>= 1) {
        float om = __shfl_xor_sync(0xffffffffu, m, o);
        float oZ = __shfl_xor_sync(0xffffffffu, Z, o);
        float oV = __shfl_xor_sync(0xffffffffu, V, o);
        float M = fmaxf(m, om);
        float e1 = __expf(m - M), e2 = __expf(om - M);
        Z = fmaf(Z, e1, oZ * e2);
        V = fmaf(V, e1, oV * e2);
        m = M;
    }
}

// ---------------- combine NTILE partials for (cs, b) ---------------------------------
__device__ __forceinline__ void combine_warp(float* __restrict__ out, int cs, int b, int lane) {
    const float4* pp = g_partS + (cs * BSZ + b) * NTILE;
    float4 p0 = pp[lane];
    float4 p1 = (lane + 32 < NTILE) ? pp[32 + lane]
                                    : make_float4(-1e30f, 0.0f, 0.0f, 0.0f);
    float m = fmaxf(p0.x, p1.x);
    float e0 = __expf(p0.x - m), e1 = __expf(p1.x - m);
    float Z = fmaf(p0.y, e0, p1.y * e1);
    float V = fmaf(p0.z, e0, p1.z * e1);
    merge_mzv(m, Z, V);
    if (lane == 0) out[cs * BSZ + b] = V / Z + g_cvc;
}

// ---------------- IH GEMM: 2 rows x 128 cells per warp -------------------------------
__device__ __forceinline__ void gemmIH2(int sp, int j0, int lane,
                                        const float* __restrict__ b_ih) {
    const float4* gp0 = (const float4*)(g_GpIH + (j0 + 0) * 132);
    const float4* gp1 = (const float4*)(g_GpIH + (j0 + 1) * 132);
    const float4* xp  = ((const float4*)(g_Xc + (size_t)sp * 132 * 128)) + lane;
    float4 a0 = {0, 0, 0, 0}, a1 = {0, 0, 0, 0};
#pragma unroll 3
    for (int q = 0; q < 33; q++) {
        float4 w0 = __ldg(gp0 + q);
        float4 w1 = __ldg(gp1 + q);
        float4 x0 = __ldg(xp + (4 * q + 0) * 32);
        float4 x1 = __ldg(xp + (4 * q + 1) * 32);
        float4 x2 = __ldg(xp + (4 * q + 2) * 32);
        float4 x3 = __ldg(xp + (4 * q + 3) * 32);
#define F4(acc, ws) \
        acc.x = fmaf(ws.x, x0.x, acc.x); acc.y = fmaf(ws.x, x0.y, acc.y); \
        acc.z = fmaf(ws.x, x0.z, acc.z); acc.w = fmaf(ws.x, x0.w, acc.w); \
        acc.x = fmaf(ws.y, x1.x, acc.x); acc.y = fmaf(ws.y, x1.y, acc.y); \
        acc.z = fmaf(ws.y, x1.z, acc.z); acc.w = fmaf(ws.y, x1.w, acc.w); \
        acc.x = fmaf(ws.z, x2.x, acc.x); acc.y = fmaf(ws.z, x2.y, acc.y); \
        acc.z = fmaf(ws.z, x2.z, acc.z); acc.w = fmaf(ws.z, x2.w, acc.w); \
        acc.x = fmaf(ws.w, x3.x, acc.x); acc.y = fmaf(ws.w, x3.y, acc.y); \
        acc.z = fmaf(ws.w, x3.z, acc.z); acc.w = fmaf(ws.w, x3.w, acc.w);
        F4(a0, w0) F4(a1, w1)
#undef F4
    }
    float bi0 = __ldg(b_ih + j0), bi1 = __ldg(b_ih + j0 + 1);
    a0.x += bi0; a0.y += bi0; a0.z += bi0; a0.w += bi0;
    a1.x += bi1; a1.y += bi1; a1.z += bi1; a1.w += bi1;
    float* dst = g_gIH + ((size_t)sp * 384) * 128;
    ((float4*)(dst + (j0 + 0) * 128))[lane] = a0;
    ((float4*)(dst + (j0 + 1) * 128))[lane] = a1;
}

// ---------------- mega-qck: one warp per (s, b); h read from dmemT -------------------
__device__ __forceinline__ void qck_task(
        int s, int b, int lane,
        const float* __restrict__ x, const int* __restrict__ tgt) {
    int node = tgt[s * BSZ + b];
    int di = g_dmapP[(s + 1) * NN + node];     // tgt always updated at step s
    float h[4];
#pragma unroll
    for (int k = 0; k < 4; k++)
        h[k] = __ldg(g_dmemT + (size_t)(k * 32 + lane) * ND2 + di);
    float xt = __ldg(x + (size_t)(s * BSZ + b) * NN + node);
    int sb = s * BSZ + b;
    for (int r = 0; r < NROW; r++) {
        float a = 0.0f;
#pragma unroll
        for (int k = 0; k < 4; k++)
            a = fmaf(__ldg(g_Mq + r * LL + k * 32 + lane), h[k], a);
#pragma unroll
        for (int o = 16; o; o >>= 1) a += __shfl_xor_sync(0xffffffffu, a, o);
        if (lane == 0) {
            float val = fmaf(g_Mqx[r], xt, a) + g_Mqc[r];
            if (r == 0) g_ck0S[sb] = val;
            else if (r < 129) g_ckmS[sb * LL + r - 1] = val;
            else if (r < 141) g_cfgS[sb * KCH + r - 129].x = val;
            else g_qbkS[sb] = val;
        }
    }
}

// ---------------- scores: f32x2 packed Clenshaw (KCH=12) -----------------------------
__device__ __forceinline__ void scores_task(
        int s, int b, int tile, int lane,
        const float* __restrict__ x, const float* __restrict__ t,
        const int* __restrict__ mask, float cv0) {
    int n0 = tile * TSZ;
    int sb = s * BSZ + b;
    size_t base = (size_t)sb * NN;
    const unsigned long long* cfg = (const unsigned long long*)(g_cfgS + sb * KCH);
    float qbk = g_qbkS[sb];
    float ck0 = g_ck0S[sb];
    const int* dmapS = g_dmapP + (s + 1) * NN;
    const float* sdot = g_sdotS + (size_t)sb * ND2;
    const unsigned long long NEG2 = 0x8000000080000000ULL;

    float m = -1e30f, Z = 0.0f, V = 0.0f;
#pragma unroll
    for (int it = 0; it < TSZ / 32; it++) {
        int nn = n0 + it * 32 + lane;
        bool pred = nn < NN;
        int n = pred ? nn : (NN - 1);
        float tv = __ldg(t + base + n);
        int   mk = __ldg(mask + base + n);
        float xv = __ldg(x + base + n);
        int   dm = __ldg(dmapS + n);
        float sd = (dm >= 0) ? __ldg(sdot + dm) : 0.0f;
        float md = (dm >= 0) ? g_memdotC[dm] : 0.0f;

        float u = 2.0f * tv - 1.0f;
        unsigned long long u2p = pk2(u + u, u + u);
        unsigned long long b1 = 0ULL, mb2 = 0ULL;
#pragma unroll
        for (int j = KCH - 1; j >= 1; j--) {
            unsigned long long cj = __ldg(cfg + j);
            unsigned long long tmp, nb;
            FMA2(tmp, u2p, b1, cj);
            ADD2(nb, tmp, mb2);
            mb2 = b1 ^ NEG2;
            b1 = nb;
        }
        unsigned long long up = pk2(u, u);
        unsigned long long fin;
        FMA2(fin, up, b1, mb2);
        unsigned long long c0 = __ldg(cfg);
        ADD2(fin, fin, c0);
        float f, g;
        upk2(fin, f, g);

        float sc = qbk + fmaf(ck0, xv, f) + sd;
        sc = mk ? sc : -1e9f;
        sc = pred ? sc : -3.0e38f;
        float val = fmaf(cv0, xv, md) + g;

        float M = fmaxf(m, sc);
        float eo = __expf(m - M);
        float en = __expf(sc - M);
        Z = fmaf(Z, eo, en);
        V = fmaf(V, eo, en * val);
        m = M;
    }
    merge_mzv(m, Z, V);
    if (lane == 0) g_partS[sb * NTILE + tile] = make_float4(m, Z, V, 0.0f);
}

// ---------------- the persistent kernel ----------------------------------------------
__global__ void __launch_bounds__(NTHR, 2) k_persist(
        const float* __restrict__ x, const float* __restrict__ t,
        const int* __restrict__ src, const int* __restrict__ tgt,
        const int* __restrict__ mask,
        const float* __restrict__ time_w, const float* __restrict__ time_b,
        const float* __restrict__ W_ih, const float* __restrict__ W_hh,
        const float* __restrict__ b_ih, const float* __restrict__ b_hh,
        const float* __restrict__ Wq, const float* __restrict__ bq,
        const float* __restrict__ Wk, const float* __restrict__ bk,
        const float* __restrict__ Wv, const float* __restrict__ bv,
        const float* __restrict__ W_out, const float* __restrict__ b_out,
        float* __restrict__ out) {
    __shared__ int   s_nodes[128];
    __shared__ float s_h[128];
    __shared__ float s_hh[384];
    __shared__ float s_red[4];
    __shared__ int   s_didx;

    int tid = threadIdx.x;
    int lane = tid & 31, wid = tid >> 5;
    int gw = blockIdx.x * 16 + wid;
    int gtid = blockIdx.x * NTHR + tid;
    const int nthr = NBLK * NTHR;
    int sw = blockIdx.x + wid * NBLK;

    // ================= S1 =================
    for (int i = gtid; i < S_LEN * 132 * 128; i += nthr) g_Xc[i] = 0.0f;
    for (int i = gtid; i < 384 * 132; i += nthr) {
        int j = i / 132, d = i - j * 132;
        g_GpIH[i] = (d < DMSG) ? W_ih[j * DMSG + d] : 0.0f;
    }
    for (int i = gtid; i < 384 * 128; i += nthr) {
        int r = i >> 7, l = i & 127;
        g_WhhT[l * 384 + r] = W_hh[i];
    }
    for (int i = gtid; i < NN; i += nthr) { g_dmap[i] = -1; g_dmapP[i] = -1; }
    for (int d = gw; d < DH; d += NWARP) {
        float a = 0.0f;
        const float* wr = Wv + d * LL;
#pragma unroll
        for (int ch = 0; ch < 4; ch++)
            a = fmaf(__ldg(wr + ch * 32 + lane), __ldg(W_out + ch * 32 + lane), a);
#pragma unroll
        for (int o = 16; o; o >>= 1) a += __shfl_xor_sync(0xffffffffu, a, o);
        if (lane == 0) g_cv[d] = a;
    }
    if (gw == 300) {
        float a = 0.0f;
#pragma unroll
        for (int ch = 0; ch < 4; ch++)
            a = fmaf(__ldg(bv + ch * 32 + lane), __ldg(W_out + ch * 32 + lane), a);
#pragma unroll
        for (int o = 16; o; o >>= 1) a += __shfl_xor_sync(0xffffffffu, a, o);
        if (lane == 0) g_cvc = a + b_out[0];
    }
    for (int i = gtid; i < LL; i += nthr) g_enc0[i] = cosf(time_b[i]);
    for (int i = gtid; i < KCH * LL; i += nthr) {
        int k = i >> 7, l = i & 127;
        float tk = 0.5f + 0.5f * cosf(PI_F * (k + 0.5f) / KCH);
        g_cosk[i] = cosf(fmaf(tk, time_w[l], time_b[l]));
    }
    for (int i = gtid; i < KCH * KCH; i += nthr) {
        int j = i / KCH, k = i - j * KCH;
        float w = (j == 0) ? (1.0f / KCH) : (2.0f / KCH);
        g_Tm[i] = w * cosf(j * PI_F * (k + 0.5f) / KCH);
    }
    if (gtid == 0) g_dcount = 0;
    gsync();

    // ================= S2: R, vENC, cg fit, prep-cos (all steps) =================
    if (gtid < KCH * LL) {
        int k = gtid >> 7, l = gtid & 127;
        float a = 0.0f;
#pragma unroll
        for (int kk = 0; kk < KCH; kk++)
            a = fmaf(g_Tm[k * KCH + kk], g_cosk[kk * LL + l], a);
        g_R[gtid] = a;
    } else if (gtid < KCH * LL + LL) {
        int l = gtid - KCH * LL;
        float a = 0.0f;
#pragma unroll 8
        for (int j = 0; j < LL; j++)
            a = fmaf(__ldg(Wq + (DMSG + j) * LL + l), g_enc0[j], a);
        g_vENC[l] = a;
    }
    if (gw == 296) {
        float gv = 0.0f;
        if (lane < KCH)
            for (int l = 0; l < LL; l++)
                gv = fmaf(g_cv[1 + LL + l], g_cosk[lane * LL + l], gv);
        float c = 0.0f;
#pragma unroll
        for (int k = 0; k < KCH; k++) {
            float gk = __shfl_sync(0xffffffffu, gv, k);
            if (lane < KCH) c = fmaf(g_Tm[lane * KCH + k], gk, c);
        }
        if (lane < KCH) g_cg[lane] = c;
    }
    {   // prep-cos for ALL steps: 2048 warp tasks
        int pt = sw - 512;
        if (pt >= 0 && pt < S_LEN * 128)
            prep_cos(pt >> 7, pt & 127, lane, x, t, src, tgt, time_w, time_b);
    }
    gsync();

    // ================= S3: U table + cfg.y prefill + mega-IH GEMM =================
    for (int i = gtid; i < 129 * LL; i += nthr) {
        int r = i >> 7, l = i & 127;
        g_U[i] = Wk[r * LL + l];
    }
    for (int i = gtid; i < LL; i += nthr) g_U[141 * LL + i] = bk[i];
    for (int i = gtid; i < KCH * LL; i += nthr) {
        int k = i >> 7, l = i & 127;
        float a = 0.0f;
#pragma unroll 8
        for (int lp = 0; lp < LL; lp++)
            a = fmaf(g_R[k * LL + lp], __ldg(Wk + (DMSG + lp) * LL + l), a);
        g_U[(129 + k) * LL + l] = a;
    }
    for (int i = gtid; i < S_LEN * BSZ * KCH; i += nthr)
        g_cfgS[i].y = g_cg[i - (i / KCH) * KCH];
    if (sw < S_LEN * 192) gemmIH2(sw / 192, (sw % 192) * 2, lane, b_ih);
    gsync();

    // ================= S4: Mq pack =================
    for (int mtask = sw; mtask < NROW * 130; mtask += NWARP) {
        int r = mtask / 130, c = mtask - r * 130;
        float a = 0.0f;
        if (c < 128) {
            const float* v = Wq + (1 + c) * LL;
#pragma unroll
            for (int ch = 0; ch < 4; ch++)
                a = fmaf(g_U[r * LL + ch * 32 + lane], __ldg(v + ch * 32 + lane), a);
        } else if (c == 128) {
#pragma unroll
            for (int ch = 0; ch < 4; ch++)
                a = fmaf(g_U[r * LL + ch * 32 + lane], __ldg(Wq + ch * 32 + lane), a);
        } else {
#pragma unroll
            for (int ch = 0; ch < 4; ch++) {
                int l = ch * 32 + lane;
                a = fmaf(g_U[r * LL + l], g_vENC[l] + __ldg(bq + l), a);
            }
        }
#pragma unroll
        for (int o = 16; o; o >>= 1) a += __shfl_xor_sync(0xffffffffu, a, o);
        if (lane == 0) {
            a *= SCALE;
            if (c < 128) g_Mq[r * LL + c] = a;
            else if (c == 128) g_Mqx[r] = a;
            else g_Mqc[r] = a;
        }
    }
    gsync();

    float cv0 = g_cv[0];

    // ================= serial loop: 2 tiny phases/step =================
    for (int s = 0; s < S_LEN; s++) {
        // ---- A: scatter-with-fused-hh (blocks 0..127) ----
        if (blockIdx.x < 128) {
            if (tid < 128)
                s_nodes[tid] = (tid < BSZ) ? src[s * BSZ + tid] : tgt[s * BSZ + (tid - BSZ)];
            __syncthreads();
            int c = blockIdx.x;
            int my = s_nodes[c];
            bool loser = (tid < 128) && (tid > c) && (s_nodes[tid] == my);
            bool skip = __syncthreads_or(loser);
            if (!skip) {
                int dmp = g_dmapP[s * NN + my];   // pre-step memory column (stable)
                if (tid == 0) {
                    int di = atomicAdd(&g_dcount, 1);
                    g_dmap[my] = di;
                    s_didx = di;
                }
                if (tid < 128)
                    s_h[tid] = (dmp >= 0) ? g_dmemT[(size_t)tid * ND2 + dmp] : 0.0f;
                __syncthreads();
                float hhv = 0.0f;
                if (tid < 384 && dmp >= 0) {
                    const float* wt = g_WhhT + tid;
                    float a0 = 0.f, a1 = 0.f, a2 = 0.f, a3 = 0.f;
#pragma unroll 8
                    for (int l = 0; l < 128; l += 4) {
                        a0 = fmaf(__ldg(wt + (l + 0) * 384), s_h[l + 0], a0);
                        a1 = fmaf(__ldg(wt + (l + 1) * 384), s_h[l + 1], a1);
                        a2 = fmaf(__ldg(wt + (l + 2) * 384), s_h[l + 2], a2);
                        a3 = fmaf(__ldg(wt + (l + 3) * 384), s_h[l + 3], a3);
                    }
                    hhv = (a0 + a1) + (a2 + a3);
                }
                if (tid < 384) s_hh[tid] = hhv;
                __syncthreads();
                int di = s_didx;
                if (tid < 128) {
                    const float* gIH = g_gIH + (size_t)s * 384 * 128;
                    int j = tid;
                    float IH0 = gIH[j * 128 + c];
                    float IH1 = gIH[(128 + j) * 128 + c];
                    float IH2 = gIH[(256 + j) * 128 + c];
                    float r = 1.0f / (1.0f + __expf(-(IH0 + s_hh[j] + __ldg(b_hh + j))));
                    float z = 1.0f / (1.0f + __expf(-(IH1 + s_hh[128 + j] + __ldg(b_hh + 128 + j))));
                    float n = tanhf(fmaf(r, s_hh[256 + j] + __ldg(b_hh + 256 + j), IH2));
                    float v = fmaf(z, s_h[j] - n, n);
                    g_dmemT[(size_t)j * ND2 + di] = v;
                    float a = v * g_cv[1 + j];
#pragma unroll
                    for (int o = 16; o; o >>= 1) a += __shfl_xor_sync(0xffffffffu, a, o);
                    if ((j & 31) == 0) s_red[j >> 5] = a;
                }
                __syncthreads();
                if (tid == 0)
                    g_memdotC[di] = s_red[0] + s_red[1] + s_red[2] + s_red[3];
            }
        }
        gsync();

        // ---- B: snapshot dmapP[s+1] + cnt ----
        if (sw < 313) {
            int i0 = sw * 32 + lane;
            if (i0 < NN) g_dmapP[(s + 1) * NN + i0] = g_dmap[i0];
        } else if (sw == 400 && lane == 0) {
            g_cntS[s] = g_dcount;
        }
        gsync();
    }

    // ================= mega-qck =================
    if (sw < S_LEN * BSZ) qck_task(sw >> 6, sw & 63, lane, x, tgt);
    gsync();

    // ================= mega-sdot =================
    for (int wt = sw; wt < S_LEN * 1024; wt += NWARP) {
        int s = wt >> 10;
        int rem = wt & 1023;
        int bg = rem & 15, gI = rem >> 4;
        int cnt = g_cntS[s];
        if (gI * 32 >= cnt) continue;
        int i = gI * 32 + lane;
        int ii = (i < cnt) ? i : (cnt - 1);
        float ckr[4][4];
#pragma unroll
        for (int bb = 0; bb < 4; bb++)
#pragma unroll
            for (int j = 0; j < 4; j++)
                ckr[bb][j] = g_ckmS[(s * BSZ + bg * 4 + bb) * LL + j * 32 + lane];
        float acc[4] = {0.f, 0.f, 0.f, 0.f};
#pragma unroll
        for (int ch = 0; ch < 4; ch++) {
#pragma unroll 8
            for (int lo = 0; lo < 32; lo++) {
                float v = g_dmemT[(size_t)(ch * 32 + lo) * ND2 + ii];
#pragma unroll
                for (int bb = 0; bb < 4; bb++)
                    acc[bb] = fmaf(__shfl_sync(0xffffffffu, ckr[bb][ch], lo), v, acc[bb]);
            }
        }
        if (i < cnt) {
#pragma unroll
            for (int bb = 0; bb < 4; bb++)
                g_sdotS[(size_t)(s * BSZ + bg * 4 + bb) * ND2 + i] = acc[bb];
        }
    }
    gsync();

    // ================= mega-scores =================
    for (int wt = sw; wt < S_LEN * BSZ * NTILE; wt += NWARP) {
        int s = wt / (BSZ * NTILE);
        int rem = wt - s * (BSZ * NTILE);
        scores_task(s, rem & 63, rem >> 6, lane, x, t, mask, cv0);
    }
    gsync();

    // ================= combine =================
    if (sw < S_LEN * BSZ) combine_warp(out, sw >> 6, sw & 63, lane);
}

// ---------------- host ----------------------------------------------------------------
extern "C" void kernel_launch(void* const* d_in, const int* in_sizes, int n_in,
                              void* d_out, int out_size) {
    const float* x       = (const float*)d_in[0];
    const float* t       = (const float*)d_in[1];
    const int*   src     = (const int*)d_in[2];
    const int*   tgt     = (const int*)d_in[3];
    const int*   mask    = (const int*)d_in[4];
    const float* time_w  = (const float*)d_in[5];
    const float* time_b  = (const float*)d_in[6];
    const float* W_ih    = (const float*)d_in[7];
    const float* W_hh    = (const float*)d_in[8];
    const float* b_ih    = (const float*)d_in[9];
    const float* b_hh    = (const float*)d_in[10];
    const float* Wq      = (const float*)d_in[11];
    const float* bq      = (const float*)d_in[12];
    const float* Wk      = (const float*)d_in[13];
    const float* bk      = (const float*)d_in[14];
    const float* Wv      = (const float*)d_in[15];
    const float* bv      = (const float*)d_in[16];
    const float* W_out   = (const float*)d_in[17];
    const float* b_out   = (const float*)d_in[18];

    k_persist<<<NBLK, NTHR>>>(x, t, src, tgt, mask, time_w, time_b,
                              W_ih, W_hh, b_ih, b_hh, Wq, bq, Wk, bk,
                              Wv, bv, W_out, b_out, (float*)d_out);
}

// round 16
// speedup vs baseline: 13.2076x; 1.3249x over previous
#include <cuda_runtime.h>
#include <math.h>

#define S_LEN 16
#define BSZ   64
#define NN    10000
#define LL    128
#define DMSG  129
#define DH    257
#define SCALE 0.08838834764831844f
#define NBLK  296
#define NTHR  512
#define NWARP (NBLK * 16)      // 4736
#define ND2   2048             // = S_LEN * 128, static column per (s,c)
#define KCH   12
#define NTILE 53
#define TSZ   192
#define NROW  142              // ck0(1) + ckm(128) + cf(12) + qbk(1)
#define PI_F  3.14159265358979f

// ---------------- f32x2 packed helpers ----------------------------------------------
__device__ __forceinline__ unsigned long long pk2(float lo, float hi) {
    unsigned long long r;
    asm("mov.b64 %0, {%1,%2};" : "=l"(r) : "f"(lo), "f"(hi));
    return r;
}
__device__ __forceinline__ void upk2(unsigned long long v, float& lo, float& hi) {
    asm("mov.b64 {%0,%1}, %2;" : "=f"(lo), "=f"(hi) : "l"(v));
}
#define FMA2(d, a, b, c) asm("fma.rn.f32x2 %0,%1,%2,%3;" : "=l"(d) : "l"(a), "l"(b), "l"(c))
#define ADD2(d, a, b)    asm("add.rn.f32x2 %0,%1,%2;"    : "=l"(d) : "l"(a), "l"(b))

// ---------------- device state ----------------------------------------------------
__device__ float g_Xc[S_LEN * 132 * 128];       // per-step msg (x, cos); pads zero
__device__ float g_GpIH[384 * 132];             // W_ih rows padded to 132
__device__ float g_gIH[S_LEN * 384 * 128];      // IH gemm out (b_ih folded)
__device__ float g_ck0S[S_LEN * BSZ];
__device__ float g_ckmS[S_LEN * BSZ * LL];
__device__ float2 g_cfgS[S_LEN * BSZ * KCH];    // (.x=cf, .y=cg)
__device__ float g_qbkS[S_LEN * BSZ];
__device__ int   g_dmapP[(S_LEN + 1) * NN];     // row r: latest column < r*128, else -1
__device__ int   g_flag[ND2];                   // column ready flags
__device__ float g_dmemT[LL * ND2];
__device__ float g_memdotC[ND2];
__device__ float g_sdotS[S_LEN * BSZ * ND2];
__device__ float g_cosk[KCH * LL];
__device__ float g_Tm[KCH * KCH];
__device__ float g_R[KCH * LL];
__device__ float g_vENC[LL];
__device__ float g_U[NROW * LL];
__device__ float g_Mq[NROW * LL];
__device__ float g_Mqx[NROW];
__device__ float g_Mqc[NROW];
__device__ float g_cg[KCH];
__device__ float4 g_partS[S_LEN * BSZ * NTILE];
__device__ float g_cv[DH];
__device__ float g_cvc;
__device__ float g_enc0[LL];
__device__ unsigned g_count;
__device__ volatile unsigned g_gen;

// ---------------- grid barrier -----------------------------------------------------
__device__ __forceinline__ void gsync() {
    __threadfence();
    __syncthreads();
    if (threadIdx.x == 0) {
        unsigned gen = g_gen;
        if (atomicAdd(&g_count, 1) == NBLK - 1) {
            g_count = 0;
            __threadfence();
            g_gen = gen + 1;
        } else {
            while (g_gen == gen) { }
            __threadfence();
        }
    }
    __syncthreads();
}

// ---------------- prep-cos: msg column for cell c of step sp (one warp) -------------
__device__ __forceinline__ void prep_cos(
        int sp, int c, int lane,
        const float* __restrict__ x, const float* __restrict__ t,
        const int* __restrict__ src, const int* __restrict__ tgt,
        const float* __restrict__ time_w, const float* __restrict__ time_b) {
    int b = c & 63, is_t = c >> 6;
    int node = (is_t ? tgt : src)[sp * BSZ + b];
    size_t base = (size_t)(sp * BSZ + b) * NN + node;
    float tv = __ldg(t + base);
    float* Xn = g_Xc + (size_t)sp * 132 * 128;
    if (lane == 0) Xn[c] = __ldg(x + base);
#pragma unroll
    for (int j = 0; j < 4; j++) {
        int l = j * 32 + lane;
        Xn[(1 + l) * 128 + c] = cosf(fmaf(tv, __ldg(time_w + l), __ldg(time_b + l)));
    }
}

// ---------------- lane-state softmax merge ------------------------------------------
__device__ __forceinline__ void merge_mzv(float& m, float& Z, float& V) {
#pragma unroll
    for (int o = 16; o; o >>= 1) {
        float om = __shfl_xor_sync(0xffffffffu, m, o);
        float oZ = __shfl_xor_sync(0xffffffffu, Z, o);
        float oV = __shfl_xor_sync(0xffffffffu, V, o);
        float M = fmaxf(m, om);
        float e1 = __expf(m - M), e2 = __expf(om - M);
        Z = fmaf(Z, e1, oZ * e2);
        V = fmaf(V, e1, oV * e2);
        m = M;
    }
}

// ---------------- combine NTILE partials for (cs, b) ---------------------------------
__device__ __forceinline__ void combine_warp(float* __restrict__ out, int cs, int b, int lane) {
    const float4* pp = g_partS + (cs * BSZ + b) * NTILE;
    float4 p0 = pp[lane];
    float4 p1 = (lane + 32 < NTILE) ? pp[32 + lane]
                                    : make_float4(-1e30f, 0.0f, 0.0f, 0.0f);
    float m = fmaxf(p0.x, p1.x);
    float e0 = __expf(p0.x - m), e1 = __expf(p1.x - m);
    float Z = fmaf(p0.y, e0, p1.y * e1);
    float V = fmaf(p0.z, e0, p1.z * e1);
    merge_mzv(m, Z, V);
    if (lane == 0) out[cs * BSZ + b] = V / Z + g_cvc;
}

// ---------------- IH GEMM: 2 rows x 128 cells per warp -------------------------------
__device__ __forceinline__ void gemmIH2(int sp, int j0, int lane,
                                        const float* __restrict__ b_ih) {
    const float4* gp0 = (const float4*)(g_GpIH + (j0 + 0) * 132);
    const float4* gp1 = (const float4*)(g_GpIH + (j0 + 1) * 132);
    const float4* xp  = ((const float4*)(g_Xc + (size_t)sp * 132 * 128)) + lane;
    float4 a0 = {0, 0, 0, 0}, a1 = {0, 0, 0, 0};
#pragma unroll 3
    for (int q = 0; q < 33; q++) {
        float4 w0 = __ldg(gp0 + q);
        float4 w1 = __ldg(gp1 + q);
        float4 x0 = __ldg(xp + (4 * q + 0) * 32);
        float4 x1 = __ldg(xp + (4 * q + 1) * 32);
        float4 x2 = __ldg(xp + (4 * q + 2) * 32);
        float4 x3 = __ldg(xp + (4 * q + 3) * 32);
#define F4(acc, ws) \
        acc.x = fmaf(ws.x, x0.x, acc.x); acc.y = fmaf(ws.x, x0.y, acc.y); \
        acc.z = fmaf(ws.x, x0.z, acc.z); acc.w = fmaf(ws.x, x0.w, acc.w); \
        acc.x = fmaf(ws.y, x1.x, acc.x); acc.y = fmaf(ws.y, x1.y, acc.y); \
        acc.z = fmaf(ws.y, x1.z, acc.z); acc.w = fmaf(ws.y, x1.w, acc.w); \
        acc.x = fmaf(ws.z, x2.x, acc.x); acc.y = fmaf(ws.z, x2.y, acc.y); \
        acc.z = fmaf(ws.z, x2.z, acc.z); acc.w = fmaf(ws.z, x2.w, acc.w); \
        acc.x = fmaf(ws.w, x3.x, acc.x); acc.y = fmaf(ws.w, x3.y, acc.y); \
        acc.z = fmaf(ws.w, x3.z, acc.z); acc.w = fmaf(ws.w, x3.w, acc.w);
        F4(a0, w0) F4(a1, w1)
#undef F4
    }
    float bi0 = __ldg(b_ih + j0), bi1 = __ldg(b_ih + j0 + 1);
    a0.x += bi0; a0.y += bi0; a0.z += bi0; a0.w += bi0;
    a1.x += bi1; a1.y += bi1; a1.z += bi1; a1.w += bi1;
    float* dst = g_gIH + ((size_t)sp * 384) * 128;
    ((float4*)(dst + (j0 + 0) * 128))[lane] = a0;
    ((float4*)(dst + (j0 + 1) * 128))[lane] = a1;
}

// ---------------- mega-qck: one warp per (s, b) ---------------------------------------
__device__ __forceinline__ void qck_task(
        int s, int b, int lane,
        const float* __restrict__ x, const int* __restrict__ tgt) {
    int node = tgt[s * BSZ + b];
    int di = g_dmapP[(s + 1) * NN + node];     // tgt always updated at step s
    float h[4];
#pragma unroll
    for (int k = 0; k < 4; k++)
        h[k] = __ldg(g_dmemT + (size_t)(k * 32 + lane) * ND2 + di);
    float xt = __ldg(x + (size_t)(s * BSZ + b) * NN + node);
    int sb = s * BSZ + b;
    for (int r = 0; r < NROW; r++) {
        float a = 0.0f;
#pragma unroll
        for (int k = 0; k < 4; k++)
            a = fmaf(__ldg(g_Mq + r * LL + k * 32 + lane), h[k], a);
#pragma unroll
        for (int o = 16; o; o >>= 1) a += __shfl_xor_sync(0xffffffffu, a, o);
        if (lane == 0) {
            float val = fmaf(g_Mqx[r], xt, a) + g_Mqc[r];
            if (r == 0) g_ck0S[sb] = val;
            else if (r < 129) g_ckmS[sb * LL + r - 1] = val;
            else if (r < 141) g_cfgS[sb * KCH + r - 129].x = val;
            else g_qbkS[sb] = val;
        }
    }
}

// ---------------- scores: f32x2 packed Clenshaw (KCH=12) -----------------------------
__device__ __forceinline__ void scores_task(
        int s, int b, int tile, int lane,
        const float* __restrict__ x, const float* __restrict__ t,
        const int* __restrict__ mask, float cv0) {
    int n0 = tile * TSZ;
    int sb = s * BSZ + b;
    size_t base = (size_t)sb * NN;
    const unsigned long long* cfg = (const unsigned long long*)(g_cfgS + sb * KCH);
    float qbk = g_qbkS[sb];
    float ck0 = g_ck0S[sb];
    const int* dmapS = g_dmapP + (s + 1) * NN;
    const float* sdot = g_sdotS + (size_t)sb * ND2;
    const unsigned long long NEG2 = 0x8000000080000000ULL;

    float m = -1e30f, Z = 0.0f, V = 0.0f;
#pragma unroll
    for (int it = 0; it < TSZ / 32; it++) {
        int nn = n0 + it * 32 + lane;
        bool pred = nn < NN;
        int n = pred ? nn : (NN - 1);
        float tv = __ldg(t + base + n);
        int   mk = __ldg(mask + base + n);
        float xv = __ldg(x + base + n);
        int   dm = __ldg(dmapS + n);
        float sd = (dm >= 0) ? __ldg(sdot + dm) : 0.0f;
        float md = (dm >= 0) ? g_memdotC[dm] : 0.0f;

        float u = 2.0f * tv - 1.0f;
        unsigned long long u2p = pk2(u + u, u + u);
        unsigned long long b1 = 0ULL, mb2 = 0ULL;
#pragma unroll
        for (int j = KCH - 1; j >= 1; j--) {
            unsigned long long cj = __ldg(cfg + j);
            unsigned long long tmp, nb;
            FMA2(tmp, u2p, b1, cj);
            ADD2(nb, tmp, mb2);
            mb2 = b1 ^ NEG2;
            b1 = nb;
        }
        unsigned long long up = pk2(u, u);
        unsigned long long fin;
        FMA2(fin, up, b1, mb2);
        unsigned long long c0 = __ldg(cfg);
        ADD2(fin, fin, c0);
        float f, g;
        upk2(fin, f, g);

        float sc = qbk + fmaf(ck0, xv, f) + sd;
        sc = mk ? sc : -1e9f;
        sc = pred ? sc : -3.0e38f;
        float val = fmaf(cv0, xv, md) + g;

        float M = fmaxf(m, sc);
        float eo = __expf(m - M);
        float en = __expf(sc - M);
        Z = fmaf(Z, eo, en);
        V = fmaf(V, eo, en * val);
        m = M;
    }
    merge_mzv(m, Z, V);
    if (lane == 0) g_partS[sb * NTILE + tile] = make_float4(m, Z, V, 0.0f);
}

// ---------------- the persistent kernel ----------------------------------------------
__global__ void __launch_bounds__(NTHR, 2) k_persist(
        const float* __restrict__ x, const float* __restrict__ t,
        const int* __restrict__ src, const int* __restrict__ tgt,
        const int* __restrict__ mask,
        const float* __restrict__ time_w, const float* __restrict__ time_b,
        const float* __restrict__ W_ih, const float* __restrict__ W_hh,
        const float* __restrict__ b_ih, const float* __restrict__ b_hh,
        const float* __restrict__ Wq, const float* __restrict__ bq,
        const float* __restrict__ Wk, const float* __restrict__ bk,
        const float* __restrict__ Wv, const float* __restrict__ bv,
        const float* __restrict__ W_out, const float* __restrict__ b_out,
        float* __restrict__ out) {
    __shared__ float s_hbuf[16 * 128];   // per-warp h staging (8KB)

    int tid = threadIdx.x;
    int lane = tid & 31, wid = tid >> 5;
    int gw = blockIdx.x * 16 + wid;
    int gtid = blockIdx.x * NTHR + tid;
    const int nthr = NBLK * NTHR;
    int sw = blockIdx.x + wid * NBLK;

    // ================= S1 =================
    for (int i = gtid; i < S_LEN * 132 * 128; i += nthr) g_Xc[i] = 0.0f;
    for (int i = gtid; i < 384 * 132; i += nthr) {
        int j = i / 132, d = i - j * 132;
        g_GpIH[i] = (d < DMSG) ? W_ih[j * DMSG + d] : 0.0f;
    }
    for (int i = gtid; i < (S_LEN + 1) * NN; i += nthr) g_dmapP[i] = -1;
    for (int i = gtid; i < ND2; i += nthr) g_flag[i] = 0;
    for (int d = gw; d < DH; d += NWARP) {
        float a = 0.0f;
        const float* wr = Wv + d * LL;
#pragma unroll
        for (int ch = 0; ch < 4; ch++)
            a = fmaf(__ldg(wr + ch * 32 + lane), __ldg(W_out + ch * 32 + lane), a);
#pragma unroll
        for (int o = 16; o; o >>= 1) a += __shfl_xor_sync(0xffffffffu, a, o);
        if (lane == 0) g_cv[d] = a;
    }
    if (gw == 300) {
        float a = 0.0f;
#pragma unroll
        for (int ch = 0; ch < 4; ch++)
            a = fmaf(__ldg(bv + ch * 32 + lane), __ldg(W_out + ch * 32 + lane), a);
#pragma unroll
        for (int o = 16; o; o >>= 1) a += __shfl_xor_sync(0xffffffffu, a, o);
        if (lane == 0) g_cvc = a + b_out[0];
    }
    for (int i = gtid; i < LL; i += nthr) g_enc0[i] = cosf(time_b[i]);
    for (int i = gtid; i < KCH * LL; i += nthr) {
        int k = i >> 7, l = i & 127;
        float tk = 0.5f + 0.5f * cosf(PI_F * (k + 0.5f) / KCH);
        g_cosk[i] = cosf(fmaf(tk, time_w[l], time_b[l]));
    }
    for (int i = gtid; i < KCH * KCH; i += nthr) {
        int j = i / KCH, k = i - j * KCH;
        float w = (j == 0) ? (1.0f / KCH) : (2.0f / KCH);
        g_Tm[i] = w * cosf(j * PI_F * (k + 0.5f) / KCH);
    }
    gsync();

    // ================= S2: R, vENC, cg fit, prep-cos (all steps) =================
    if (gtid < KCH * LL) {
        int k = gtid >> 7, l = gtid & 127;
        float a = 0.0f;
#pragma unroll
        for (int kk = 0; kk < KCH; kk++)
            a = fmaf(g_Tm[k * KCH + kk], g_cosk[kk * LL + l], a);
        g_R[gtid] = a;
    } else if (gtid < KCH * LL + LL) {
        int l = gtid - KCH * LL;
        float a = 0.0f;
#pragma unroll 8
        for (int j = 0; j < LL; j++)
            a = fmaf(__ldg(Wq + (DMSG + j) * LL + l), g_enc0[j], a);
        g_vENC[l] = a;
    }
    if (gw == 296) {
        float gv = 0.0f;
        if (lane < KCH)
            for (int l = 0; l < LL; l++)
                gv = fmaf(g_cv[1 + LL + l], g_cosk[lane * LL + l], gv);
        float c = 0.0f;
#pragma unroll
        for (int k = 0; k < KCH; k++) {
            float gk = __shfl_sync(0xffffffffu, gv, k);
            if (lane < KCH) c = fmaf(g_Tm[lane * KCH + k], gk, c);
        }
        if (lane < KCH) g_cg[lane] = c;
    }
    {   // prep-cos for ALL steps
        int pt = sw - 512;
        if (pt >= 0 && pt < S_LEN * 128)
            prep_cos(pt >> 7, pt & 127, lane, x, t, src, tgt, time_w, time_b);
    }
    gsync();

    // ================= S3: U table + cfg.y prefill + mega-IH GEMM =================
    for (int i = gtid; i < 129 * LL; i += nthr) {
        int r = i >> 7, l = i & 127;
        g_U[i] = Wk[r * LL + l];
    }
    for (int i = gtid; i < LL; i += nthr) g_U[141 * LL + i] = bk[i];
    for (int i = gtid; i < KCH * LL; i += nthr) {
        int k = i >> 7, l = i & 127;
        float a = 0.0f;
#pragma unroll 8
        for (int lp = 0; lp < LL; lp++)
            a = fmaf(g_R[k * LL + lp], __ldg(Wk + (DMSG + lp) * LL + l), a);
        g_U[(129 + k) * LL + l] = a;
    }
    for (int i = gtid; i < S_LEN * BSZ * KCH; i += nthr)
        g_cfgS[i].y = g_cg[i - (i / KCH) * KCH];
    if (sw < S_LEN * 192) gemmIH2(sw / 192, (sw % 192) * 2, lane, b_ih);
    gsync();

    // ================= S4: GRU chain (sw<2048) + Mq pack (others) =================
    if (sw < ND2) {
        int s = sw >> 7, c = sw & 127;
        int node = (c < 64) ? src[s * BSZ + c] : tgt[s * BSZ + (c - 64)];
        // build dmapP rows s+1..16 via atomicMax (max cell index = winner)
        for (int r = s + 1 + lane; r <= S_LEN; r += 32)
            atomicMax(&g_dmapP[r * NN + node], sw);
        // winner check: any later same-step cell with same node?
        bool conflict = false;
        for (int k = lane; k < 128; k += 32) {
            if (k > c) {
                int nd2 = (k < 64) ? src[s * BSZ + k] : tgt[s * BSZ + k - 64];
                conflict |= (nd2 == node);
            }
        }
        if (!__any_sync(0xffffffffu, conflict)) {
            // predecessor column: max cc < s*128 with same node
            int pc = -1;
            for (int cc = lane; cc < s * 128; cc += 32) {
                int s2 = cc >> 7, c2 = cc & 127;
                int nd2 = (c2 < 64) ? src[s2 * BSZ + c2] : tgt[s2 * BSZ + c2 - 64];
                if (nd2 == node) pc = cc;
            }
#pragma unroll
            for (int o = 16; o; o >>= 1) pc = max(pc, __shfl_xor_sync(0xffffffffu, pc, o));

            float* hb = s_hbuf + wid * 128;
            if (pc >= 0) {
                if (lane == 0) { while (atomicAdd(&g_flag[pc], 0) == 0) { } }
                __syncwarp();
                __threadfence();
#pragma unroll
                for (int k = 0; k < 4; k++)
                    hb[k * 32 + lane] = g_dmemT[(size_t)(k * 32 + lane) * ND2 + pc];
            } else {
#pragma unroll
                for (int k = 0; k < 4; k++) hb[k * 32 + lane] = 0.0f;
            }
            __syncwarp();

            float hh[12];
            if (pc >= 0) {
                const float4* hb4 = (const float4*)hb;
#pragma unroll
                for (int k = 0; k < 12; k++) {
                    const float4* wr = (const float4*)(W_hh + (size_t)(lane + 32 * k) * 128);
                    float4 a = {0, 0, 0, 0};
#pragma unroll 8
                    for (int q = 0; q < 32; q++) {
                        float4 w = __ldg(wr + q);
                        float4 xh = hb4[q];
                        a.x = fmaf(w.x, xh.x, a.x);
                        a.y = fmaf(w.y, xh.y, a.y);
                        a.z = fmaf(w.z, xh.z, a.z);
                        a.w = fmaf(w.w, xh.w, a.w);
                    }
                    hh[k] = (a.x + a.y) + (a.z + a.w);
                }
            } else {
#pragma unroll
                for (int k = 0; k < 12; k++) hh[k] = 0.0f;
            }

            const float* gIH = g_gIH + (size_t)s * 384 * 128;
            float md = 0.0f;
#pragma unroll
            for (int kk = 0; kk < 4; kk++) {
                int j = lane + 32 * kk;
                float IHr = gIH[(size_t)j * 128 + c];
                float IHz = gIH[(size_t)(128 + j) * 128 + c];
                float IHn = gIH[(size_t)(256 + j) * 128 + c];
                float r = 1.0f / (1.0f + __expf(-(IHr + hh[kk] + __ldg(b_hh + j))));
                float z = 1.0f / (1.0f + __expf(-(IHz + hh[kk + 4] + __ldg(b_hh + 128 + j))));
                float n = tanhf(fmaf(r, hh[kk + 8] + __ldg(b_hh + 256 + j), IHn));
                float v = fmaf(z, hb[j] - n, n);
                g_dmemT[(size_t)j * ND2 + sw] = v;
                md = fmaf(v, g_cv[1 + j], md);
            }
#pragma unroll
            for (int o = 16; o; o >>= 1) md += __shfl_xor_sync(0xffffffffu, md, o);
            if (lane == 0) g_memdotC[sw] = md;
            __threadfence();
            __syncwarp();
            if (lane == 0) atomicExch(&g_flag[sw], 1);
        }
    } else {
        // Mq pack on non-chain warps
        for (int mtask = sw - ND2; mtask < NROW * 130; mtask += NWARP - ND2) {
            int r = mtask / 130, c = mtask - r * 130;
            float a = 0.0f;
            if (c < 128) {
                const float* v = Wq + (1 + c) * LL;
#pragma unroll
                for (int ch = 0; ch < 4; ch++)
                    a = fmaf(g_U[r * LL + ch * 32 + lane], __ldg(v + ch * 32 + lane), a);
            } else if (c == 128) {
#pragma unroll
                for (int ch = 0; ch < 4; ch++)
                    a = fmaf(g_U[r * LL + ch * 32 + lane], __ldg(Wq + ch * 32 + lane), a);
            } else {
#pragma unroll
                for (int ch = 0; ch < 4; ch++) {
                    int l = ch * 32 + lane;
                    a = fmaf(g_U[r * LL + l], g_vENC[l] + __ldg(bq + l), a);
                }
            }
#pragma unroll
            for (int o = 16; o; o >>= 1) a += __shfl_xor_sync(0xffffffffu, a, o);
            if (lane == 0) {
                a *= SCALE;
                if (c < 128) g_Mq[r * LL + c] = a;
                else if (c == 128) g_Mqx[r] = a;
                else g_Mqc[r] = a;
            }
        }
    }
    gsync();

    float cv0 = g_cv[0];

    // ================= S5: mega-qck =================
    if (sw < S_LEN * BSZ) qck_task(sw >> 6, sw & 63, lane, x, tgt);
    gsync();

    // ================= S6: mega-sdot (static cnt = 128*(s+1)) =================
    for (int wt = sw; wt < S_LEN * 1024; wt += NWARP) {
        int s = wt >> 10;
        int rem = wt & 1023;
        int bg = rem & 15, gI = rem >> 4;
        int cnt = 128 * (s + 1);
        if (gI * 32 >= cnt) continue;
        int i = gI * 32 + lane;
        float ckr[4][4];
#pragma unroll
        for (int bb = 0; bb < 4; bb++)
#pragma unroll
            for (int j = 0; j < 4; j++)
                ckr[bb][j] = g_ckmS[(s * BSZ + bg * 4 + bb) * LL + j * 32 + lane];
        float acc[4] = {0.f, 0.f, 0.f, 0.f};
#pragma unroll
        for (int ch = 0; ch < 4; ch++) {
#pragma unroll 8
            for (int lo = 0; lo < 32; lo++) {
                float v = g_dmemT[(size_t)(ch * 32 + lo) * ND2 + i];
#pragma unroll
                for (int bb = 0; bb < 4; bb++)
                    acc[bb] = fmaf(__shfl_sync(0xffffffffu, ckr[bb][ch], lo), v, acc[bb]);
            }
        }
#pragma unroll
        for (int bb = 0; bb < 4; bb++)
            g_sdotS[(size_t)(s * BSZ + bg * 4 + bb) * ND2 + i] = acc[bb];
    }
    gsync();

    // ================= S7: mega-scores =================
    for (int wt = sw; wt < S_LEN * BSZ * NTILE; wt += NWARP) {
        int s = wt / (BSZ * NTILE);
        int rem = wt - s * (BSZ * NTILE);
        scores_task(s, rem & 63, rem >> 6, lane, x, t, mask, cv0);
    }
    gsync();

    // ================= S8: combine =================
    if (sw < S_LEN * BSZ) combine_warp(out, sw >> 6, sw & 63, lane);
}

// ---------------- host ----------------------------------------------------------------
extern "C" void kernel_launch(void* const* d_in, const int* in_sizes, int n_in,
                              void* d_out, int out_size) {
    const float* x       = (const float*)d_in[0];
    const float* t       = (const float*)d_in[1];
    const int*   src     = (const int*)d_in[2];
    const int*   tgt     = (const int*)d_in[3];
    const int*   mask    = (const int*)d_in[4];
    const float* time_w  = (const float*)d_in[5];
    const float* time_b  = (const float*)d_in[6];
    const float* W_ih    = (const float*)d_in[7];
    const float* W_hh    = (const float*)d_in[8];
    const float* b_ih    = (const float*)d_in[9];
    const float* b_hh    = (const float*)d_in[10];
    const float* Wq      = (const float*)d_in[11];
    const float* bq      = (const float*)d_in[12];
    const float* Wk      = (const float*)d_in[13];
    const float* bk      = (const float*)d_in[14];
    const float* Wv      = (const float*)d_in[15];
    const float* bv      = (const float*)d_in[16];
    const float* W_out   = (const float*)d_in[17];
    const float* b_out   = (const float*)d_in[18];

    k_persist<<<NBLK, NTHR>>>(x, t, src, tgt, mask, time_w, time_b,
                              W_ih, W_hh, b_ih, b_hh, Wq, bq, Wk, bk,
                              Wv, bv, W_out, b_out, (float*)d_out);
}

// round 17
// speedup vs baseline: 16.5011x; 1.2494x over previous
#include <cuda_runtime.h>
#include <math.h>

#define S_LEN 16
#define BSZ   64
#define NN    10000
#define LL    128
#define DMSG  129
#define DH    257
#define SCALE 0.08838834764831844f
#define NBLK  296
#define NTHR  512
#define NWARP (NBLK * 16)      // 4736
#define ND2   2048             // = S_LEN * 128, static column per (s,c)
#define KCH   12
#define NTILE 53
#define TSZ   192
#define NROW  142              // ck0(1) + ckm(128) + cf(12) + qbk(1)
#define PI_F  3.14159265358979f

// ---------------- f32x2 packed helpers ----------------------------------------------
__device__ __forceinline__ unsigned long long pk2(float lo, float hi) {
    unsigned long long r;
    asm("mov.b64 %0, {%1,%2};" : "=l"(r) : "f"(lo), "f"(hi));
    return r;
}
__device__ __forceinline__ void upk2(unsigned long long v, float& lo, float& hi) {
    asm("mov.b64 {%0,%1}, %2;" : "=f"(lo), "=f"(hi) : "l"(v));
}
#define FMA2(d, a, b, c) asm("fma.rn.f32x2 %0,%1,%2,%3;" : "=l"(d) : "l"(a), "l"(b), "l"(c))
#define ADD2(d, a, b)    asm("add.rn.f32x2 %0,%1,%2;"    : "=l"(d) : "l"(a), "l"(b))

// ---------------- device state ----------------------------------------------------
__device__ float g_Xc[S_LEN * 132 * 128];       // per-step msg (x, cos); pads zero
__device__ float g_GpIH[384 * 132];             // W_ih rows padded to 132
__device__ float g_gIH[S_LEN * 384 * 128];      // IH gemm out (b_ih folded)
__device__ float g_WhhT[128 * 384];             // W_hh transposed: [l][j]
__device__ float g_ck0S[S_LEN * BSZ];
__device__ float g_ckmS[S_LEN * BSZ * LL];
__device__ float2 g_cfgS[S_LEN * BSZ * KCH];    // (.x=cf, .y=cg)
__device__ float g_qbkS[S_LEN * BSZ];
__device__ int   g_dmapP[(S_LEN + 1) * NN];     // row r: latest column < r*128, else -1
__device__ int   g_flag[ND2];                   // column ready flags
__device__ float g_dmemT[LL * ND2];
__device__ float g_memdotC[ND2];
__device__ float2 g_sdotS2[S_LEN * BSZ * ND2];  // (.x = ckm.mem, .y = memdot)  16MB
__device__ float g_cosk[KCH * LL];
__device__ float g_Tm[KCH * KCH];
__device__ float g_R[KCH * LL];
__device__ float g_vENC[LL];
__device__ float g_U[NROW * LL];
__device__ float g_MqT[LL * 160];               // transposed Mq: [l][r] (pad 160)
__device__ float g_Mqx[NROW];
__device__ float g_Mqc[NROW];
__device__ float g_cg[KCH];
__device__ float4 g_partS[S_LEN * BSZ * NTILE];
__device__ float g_cv[DH];
__device__ float g_cvc;
__device__ float g_enc0[LL];
__device__ unsigned g_count;
__device__ volatile unsigned g_gen;

// ---------------- grid barrier -----------------------------------------------------
__device__ __forceinline__ void gsync() {
    __threadfence();
    __syncthreads();
    if (threadIdx.x == 0) {
        unsigned gen = g_gen;
        if (atomicAdd(&g_count, 1) == NBLK - 1) {
            g_count = 0;
            __threadfence();
            g_gen = gen + 1;
        } else {
            while (g_gen == gen) { }
            __threadfence();
        }
    }
    __syncthreads();
}

// ---------------- prep-cos: msg column for cell c of step sp (one warp) -------------
__device__ __forceinline__ void prep_cos(
        int sp, int c, int lane,
        const float* __restrict__ x, const float* __restrict__ t,
        const int* __restrict__ src, const int* __restrict__ tgt,
        const float* __restrict__ time_w, const float* __restrict__ time_b) {
    int b = c & 63, is_t = c >> 6;
    int node = (is_t ? tgt : src)[sp * BSZ + b];
    size_t base = (size_t)(sp * BSZ + b) * NN + node;
    float tv = __ldg(t + base);
    float* Xn = g_Xc + (size_t)sp * 132 * 128;
    if (lane == 0) Xn[c] = __ldg(x + base);
#pragma unroll
    for (int j = 0; j < 4; j++) {
        int l = j * 32 + lane;
        Xn[(1 + l) * 128 + c] = cosf(fmaf(tv, __ldg(time_w + l), __ldg(time_b + l)));
    }
}

// ---------------- lane-state softmax merge ------------------------------------------
__device__ __forceinline__ void merge_mzv(float& m, float& Z, float& V) {
#pragma unroll
    for (int o = 16; o; o >>= 1) {
        float om = __shfl_xor_sync(0xffffffffu, m, o);
        float oZ = __shfl_xor_sync(0xffffffffu, Z, o);
        float oV = __shfl_xor_sync(0xffffffffu, V, o);
        float M = fmaxf(m, om);
        float e1 = __expf(m - M), e2 = __expf(om - M);
        Z = fmaf(Z, e1, oZ * e2);
        V = fmaf(V, e1, oV * e2);
        m = M;
    }
}

// ---------------- combine NTILE partials for (cs, b) ---------------------------------
__device__ __forceinline__ void combine_warp(float* __restrict__ out, int cs, int b, int lane) {
    const float4* pp = g_partS + (cs * BSZ + b) * NTILE;
    float4 p0 = pp[lane];
    float4 p1 = (lane + 32 < NTILE) ? pp[32 + lane]
                                    : make_float4(-1e30f, 0.0f, 0.0f, 0.0f);
    float m = fmaxf(p0.x, p1.x);
    float e0 = __expf(p0.x - m), e1 = __expf(p1.x - m);
    float Z = fmaf(p0.y, e0, p1.y * e1);
    float V = fmaf(p0.z, e0, p1.z * e1);
    merge_mzv(m, Z, V);
    if (lane == 0) out[cs * BSZ + b] = V / Z + g_cvc;
}

// ---------------- IH GEMM: 2 rows x 128 cells per warp -------------------------------
__device__ __forceinline__ void gemmIH2(int sp, int j0, int lane,
                                        const float* __restrict__ b_ih) {
    const float4* gp0 = (const float4*)(g_GpIH + (j0 + 0) * 132);
    const float4* gp1 = (const float4*)(g_GpIH + (j0 + 1) * 132);
    const float4* xp  = ((const float4*)(g_Xc + (size_t)sp * 132 * 128)) + lane;
    float4 a0 = {0, 0, 0, 0}, a1 = {0, 0, 0, 0};
#pragma unroll 3
    for (int q = 0; q < 33; q++) {
        float4 w0 = __ldg(gp0 + q);
        float4 w1 = __ldg(gp1 + q);
        float4 x0 = __ldg(xp + (4 * q + 0) * 32);
        float4 x1 = __ldg(xp + (4 * q + 1) * 32);
        float4 x2 = __ldg(xp + (4 * q + 2) * 32);
        float4 x3 = __ldg(xp + (4 * q + 3) * 32);
#define F4(acc, ws) \
        acc.x = fmaf(ws.x, x0.x, acc.x); acc.y = fmaf(ws.x, x0.y, acc.y); \
        acc.z = fmaf(ws.x, x0.z, acc.z); acc.w = fmaf(ws.x, x0.w, acc.w); \
        acc.x = fmaf(ws.y, x1.x, acc.x); acc.y = fmaf(ws.y, x1.y, acc.y); \
        acc.z = fmaf(ws.y, x1.z, acc.z); acc.w = fmaf(ws.y, x1.w, acc.w); \
        acc.x = fmaf(ws.z, x2.x, acc.x); acc.y = fmaf(ws.z, x2.y, acc.y); \
        acc.z = fmaf(ws.z, x2.z, acc.z); acc.w = fmaf(ws.z, x2.w, acc.w); \
        acc.x = fmaf(ws.w, x3.x, acc.x); acc.y = fmaf(ws.w, x3.y, acc.y); \
        acc.z = fmaf(ws.w, x3.z, acc.z); acc.w = fmaf(ws.w, x3.w, acc.w);
        F4(a0, w0) F4(a1, w1)
#undef F4
    }
    float bi0 = __ldg(b_ih + j0), bi1 = __ldg(b_ih + j0 + 1);
    a0.x += bi0; a0.y += bi0; a0.z += bi0; a0.w += bi0;
    a1.x += bi1; a1.y += bi1; a1.z += bi1; a1.w += bi1;
    float* dst = g_gIH + ((size_t)sp * 384) * 128;
    ((float4*)(dst + (j0 + 0) * 128))[lane] = a0;
    ((float4*)(dst + (j0 + 1) * 128))[lane] = a1;
}

// ---------------- mega-qck: one warp per (s, b); MqT, lane-per-row -------------------
__device__ __forceinline__ void qck_task(
        int s, int b, int lane, float* hb,
        const float* __restrict__ x, const int* __restrict__ tgt) {
    int node = tgt[s * BSZ + b];
    int di = g_dmapP[(s + 1) * NN + node];     // tgt always updated at step s
#pragma unroll
    for (int k = 0; k < 4; k++)
        hb[k * 32 + lane] = __ldg(g_dmemT + (size_t)(k * 32 + lane) * ND2 + di);
    __syncwarp();
    float xt = __ldg(x + (size_t)(s * BSZ + b) * NN + node);
    float acc[5] = {0.f, 0.f, 0.f, 0.f, 0.f};
#pragma unroll 4
    for (int l = 0; l < 128; l++) {
        float hl = hb[l];
        const float* mt = g_MqT + l * 160 + lane;
#pragma unroll
        for (int k = 0; k < 5; k++)
            acc[k] = fmaf(__ldg(mt + 32 * k), hl, acc[k]);
    }
    int sb = s * BSZ + b;
#pragma unroll
    for (int k = 0; k < 5; k++) {
        int r = lane + 32 * k;
        if (r < NROW) {
            float val = fmaf(g_Mqx[r], xt, acc[k]) + g_Mqc[r];
            if (r == 0) g_ck0S[sb] = val;
            else if (r < 129) g_ckmS[sb * LL + r - 1] = val;
            else if (r < 141) g_cfgS[sb * KCH + r - 129].x = val;
            else g_qbkS[sb] = val;
        }
    }
}

// ---------------- scores: f32x2 Clenshaw, software-pipelined loads --------------------
__device__ __forceinline__ void scores_task(
        int s, int b, int tile, int lane,
        const float* __restrict__ x, const float* __restrict__ t,
        const int* __restrict__ mask, float cv0) {
    int n0 = tile * TSZ;
    int sb = s * BSZ + b;
    size_t base = (size_t)sb * NN;
    const unsigned long long* cfg = (const unsigned long long*)(g_cfgS + sb * KCH);
    float qbk = g_qbkS[sb];
    float ck0 = g_ck0S[sb];
    const int* dmapS = g_dmapP + (s + 1) * NN;
    const float2* sdot2 = g_sdotS2 + (size_t)sb * ND2;
    const unsigned long long NEG2 = 0x8000000080000000ULL;

    // prefetch iteration 0
    int nn = n0 + lane;
    bool pred = nn < NN;
    int n = pred ? nn : (NN - 1);
    float tv = __ldg(t + base + n);
    int   mk = __ldg(mask + base + n);
    float xv = __ldg(x + base + n);
    int   dm = __ldg(dmapS + n);

    float m = -1e30f, Z = 0.0f, V = 0.0f;
#pragma unroll
    for (int it = 0; it < TSZ / 32; it++) {
        float tvN; int mkN; float xvN; int dmN; bool predN = false;
        if (it + 1 < TSZ / 32) {
            int nn2 = n0 + (it + 1) * 32 + lane;
            predN = nn2 < NN;
            int n2 = predN ? nn2 : (NN - 1);
            tvN = __ldg(t + base + n2);
            mkN = __ldg(mask + base + n2);
            xvN = __ldg(x + base + n2);
            dmN = __ldg(dmapS + n2);
        }
        float2 sm = (dm >= 0) ? __ldg(sdot2 + dm) : make_float2(0.0f, 0.0f);

        float u = 2.0f * tv - 1.0f;
        unsigned long long u2p = pk2(u + u, u + u);
        unsigned long long b1 = 0ULL, mb2 = 0ULL;
#pragma unroll
        for (int j = KCH - 1; j >= 1; j--) {
            unsigned long long cj = __ldg(cfg + j);
            unsigned long long tmp, nb;
            FMA2(tmp, u2p, b1, cj);
            ADD2(nb, tmp, mb2);
            mb2 = b1 ^ NEG2;
            b1 = nb;
        }
        unsigned long long up = pk2(u, u);
        unsigned long long fin;
        FMA2(fin, up, b1, mb2);
        unsigned long long c0 = __ldg(cfg);
        ADD2(fin, fin, c0);
        float f, g;
        upk2(fin, f, g);

        float sc = qbk + fmaf(ck0, xv, f) + sm.x;
        sc = mk ? sc : -1e9f;
        sc = pred ? sc : -3.0e38f;
        float val = fmaf(cv0, xv, sm.y) + g;

        float M = fmaxf(m, sc);
        float eo = __expf(m - M);
        float en = __expf(sc - M);
        Z = fmaf(Z, eo, en);
        V = fmaf(V, eo, en * val);
        m = M;

        tv = tvN; mk = mkN; xv = xvN; dm = dmN; pred = predN;
    }
    merge_mzv(m, Z, V);
    if (lane == 0) g_partS[sb * NTILE + tile] = make_float4(m, Z, V, 0.0f);
}

// ---------------- the persistent kernel ----------------------------------------------
__global__ void __launch_bounds__(NTHR, 2) k_persist(
        const float* __restrict__ x, const float* __restrict__ t,
        const int* __restrict__ src, const int* __restrict__ tgt,
        const int* __restrict__ mask,
        const float* __restrict__ time_w, const float* __restrict__ time_b,
        const float* __restrict__ W_ih, const float* __restrict__ W_hh,
        const float* __restrict__ b_ih, const float* __restrict__ b_hh,
        const float* __restrict__ Wq, const float* __restrict__ bq,
        const float* __restrict__ Wk, const float* __restrict__ bk,
        const float* __restrict__ Wv, const float* __restrict__ bv,
        const float* __restrict__ W_out, const float* __restrict__ b_out,
        float* __restrict__ out) {
    __shared__ float s_hbuf[16 * 128];   // per-warp h staging (8KB)

    int tid = threadIdx.x;
    int lane = tid & 31, wid = tid >> 5;
    int gw = blockIdx.x * 16 + wid;
    int gtid = blockIdx.x * NTHR + tid;
    const int nthr = NBLK * NTHR;
    int sw = blockIdx.x + wid * NBLK;

    // ================= S1 =================
    for (int i = gtid; i < S_LEN * 132 * 128; i += nthr) g_Xc[i] = 0.0f;
    for (int i = gtid; i < 384 * 132; i += nthr) {
        int j = i / 132, d = i - j * 132;
        g_GpIH[i] = (d < DMSG) ? W_ih[j * DMSG + d] : 0.0f;
    }
    for (int i = gtid; i < 384 * 128; i += nthr) {
        int j = i >> 7, l = i & 127;
        g_WhhT[l * 384 + j] = W_hh[i];
    }
    for (int i = gtid; i < (S_LEN + 1) * NN; i += nthr) g_dmapP[i] = -1;
    for (int i = gtid; i < ND2; i += nthr) g_flag[i] = 0;
    for (int d = gw; d < DH; d += NWARP) {
        float a = 0.0f;
        const float* wr = Wv + d * LL;
#pragma unroll
        for (int ch = 0; ch < 4; ch++)
            a = fmaf(__ldg(wr + ch * 32 + lane), __ldg(W_out + ch * 32 + lane), a);
#pragma unroll
        for (int o = 16; o; o >>= 1) a += __shfl_xor_sync(0xffffffffu, a, o);
        if (lane == 0) g_cv[d] = a;
    }
    if (gw == 300) {
        float a = 0.0f;
#pragma unroll
        for (int ch = 0; ch < 4; ch++)
            a = fmaf(__ldg(bv + ch * 32 + lane), __ldg(W_out + ch * 32 + lane), a);
#pragma unroll
        for (int o = 16; o; o >>= 1) a += __shfl_xor_sync(0xffffffffu, a, o);
        if (lane == 0) g_cvc = a + b_out[0];
    }
    for (int i = gtid; i < LL; i += nthr) g_enc0[i] = cosf(time_b[i]);
    for (int i = gtid; i < KCH * LL; i += nthr) {
        int k = i >> 7, l = i & 127;
        float tk = 0.5f + 0.5f * cosf(PI_F * (k + 0.5f) / KCH);
        g_cosk[i] = cosf(fmaf(tk, time_w[l], time_b[l]));
    }
    for (int i = gtid; i < KCH * KCH; i += nthr) {
        int j = i / KCH, k = i - j * KCH;
        float w = (j == 0) ? (1.0f / KCH) : (2.0f / KCH);
        g_Tm[i] = w * cosf(j * PI_F * (k + 0.5f) / KCH);
    }
    gsync();

    // ================= S2: R, vENC, cg fit, prep-cos (all steps) =================
    if (gtid < KCH * LL) {
        int k = gtid >> 7, l = gtid & 127;
        float a = 0.0f;
#pragma unroll
        for (int kk = 0; kk < KCH; kk++)
            a = fmaf(g_Tm[k * KCH + kk], g_cosk[kk * LL + l], a);
        g_R[gtid] = a;
    } else if (gtid < KCH * LL + LL) {
        int l = gtid - KCH * LL;
        float a = 0.0f;
#pragma unroll 8
        for (int j = 0; j < LL; j++)
            a = fmaf(__ldg(Wq + (DMSG + j) * LL + l), g_enc0[j], a);
        g_vENC[l] = a;
    }
    if (gw == 296) {
        float gv = 0.0f;
        if (lane < KCH)
            for (int l = 0; l < LL; l++)
                gv = fmaf(g_cv[1 + LL + l], g_cosk[lane * LL + l], gv);
        float c = 0.0f;
#pragma unroll
        for (int k = 0; k < KCH; k++) {
            float gk = __shfl_sync(0xffffffffu, gv, k);
            if (lane < KCH) c = fmaf(g_Tm[lane * KCH + k], gk, c);
        }
        if (lane < KCH) g_cg[lane] = c;
    }
    {   // prep-cos for ALL steps
        int pt = sw - 512;
        if (pt >= 0 && pt < S_LEN * 128)
            prep_cos(pt >> 7, pt & 127, lane, x, t, src, tgt, time_w, time_b);
    }
    gsync();

    // ================= S3: U table + cfg.y prefill + mega-IH GEMM =================
    for (int i = gtid; i < 129 * LL; i += nthr) {
        int r = i >> 7, l = i & 127;
        g_U[i] = Wk[r * LL + l];
    }
    for (int i = gtid; i < LL; i += nthr) g_U[141 * LL + i] = bk[i];
    for (int i = gtid; i < KCH * LL; i += nthr) {
        int k = i >> 7, l = i & 127;
        float a = 0.0f;
#pragma unroll 8
        for (int lp = 0; lp < LL; lp++)
            a = fmaf(g_R[k * LL + lp], __ldg(Wk + (DMSG + lp) * LL + l), a);
        g_U[(129 + k) * LL + l] = a;
    }
    for (int i = gtid; i < S_LEN * BSZ * KCH; i += nthr)
        g_cfgS[i].y = g_cg[i - (i / KCH) * KCH];
    if (sw < S_LEN * 192) gemmIH2(sw / 192, (sw % 192) * 2, lane, b_ih);
    gsync();

    // ================= S4: GRU chain (sw<2048) + MqT pack (others) =================
    if (sw < ND2) {
        int s = sw >> 7, c = sw & 127;
        int node = (c < 64) ? src[s * BSZ + c] : tgt[s * BSZ + (c - 64)];
        for (int r = s + 1 + lane; r <= S_LEN; r += 32)
            atomicMax(&g_dmapP[r * NN + node], sw);
        bool conflict = false;
        for (int k = lane; k < 128; k += 32) {
            if (k > c) {
                int nd2 = (k < 64) ? src[s * BSZ + k] : tgt[s * BSZ + k - 64];
                conflict |= (nd2 == node);
            }
        }
        if (!__any_sync(0xffffffffu, conflict)) {
            int pc = -1;
            for (int cc = lane; cc < s * 128; cc += 32) {
                int s2 = cc >> 7, c2 = cc & 127;
                int nd2 = (c2 < 64) ? src[s2 * BSZ + c2] : tgt[s2 * BSZ + c2 - 64];
                if (nd2 == node) pc = cc;
            }
#pragma unroll
            for (int o = 16; o; o >>= 1) pc = max(pc, __shfl_xor_sync(0xffffffffu, pc, o));

            float* hb = s_hbuf + wid * 128;
            if (pc >= 0) {
                if (lane == 0) { while (atomicAdd(&g_flag[pc], 0) == 0) { } }
                __syncwarp();
                __threadfence();
#pragma unroll
                for (int k = 0; k < 4; k++)
                    hb[k * 32 + lane] = g_dmemT[(size_t)(k * 32 + lane) * ND2 + pc];
            } else {
#pragma unroll
                for (int k = 0; k < 4; k++) hb[k * 32 + lane] = 0.0f;
            }
            __syncwarp();

            float hh[12] = {0, 0, 0, 0, 0, 0, 0, 0, 0, 0, 0, 0};
            if (pc >= 0) {
                // coalesced: lanes read consecutive j = lane + 32k in WhhT[l][.]
#pragma unroll 4
                for (int l = 0; l < 128; l++) {
                    float hl = hb[l];
                    const float* wt = g_WhhT + l * 384 + lane;
#pragma unroll
                    for (int k = 0; k < 12; k++)
                        hh[k] = fmaf(__ldg(wt + 32 * k), hl, hh[k]);
                }
            }

            const float* gIH = g_gIH + (size_t)s * 384 * 128;
            float md = 0.0f;
#pragma unroll
            for (int kk = 0; kk < 4; kk++) {
                int j = lane + 32 * kk;
                float IHr = gIH[(size_t)j * 128 + c];
                float IHz = gIH[(size_t)(128 + j) * 128 + c];
                float IHn = gIH[(size_t)(256 + j) * 128 + c];
                float r = 1.0f / (1.0f + __expf(-(IHr + hh[kk] + __ldg(b_hh + j))));
                float z = 1.0f / (1.0f + __expf(-(IHz + hh[kk + 4] + __ldg(b_hh + 128 + j))));
                float n = tanhf(fmaf(r, hh[kk + 8] + __ldg(b_hh + 256 + j), IHn));
                float v = fmaf(z, hb[j] - n, n);
                g_dmemT[(size_t)j * ND2 + sw] = v;
                md = fmaf(v, g_cv[1 + j], md);
            }
#pragma unroll
            for (int o = 16; o; o >>= 1) md += __shfl_xor_sync(0xffffffffu, md, o);
            if (lane == 0) g_memdotC[sw] = md;
            __threadfence();
            __syncwarp();
            if (lane == 0) atomicExch(&g_flag[sw], 1);
        }
    } else {
        // MqT pack on non-chain warps
        for (int mtask = sw - ND2; mtask < NROW * 130; mtask += NWARP - ND2) {
            int r = mtask / 130, c = mtask - r * 130;
            float a = 0.0f;
            if (c < 128) {
                const float* v = Wq + (1 + c) * LL;
#pragma unroll
                for (int ch = 0; ch < 4; ch++)
                    a = fmaf(g_U[r * LL + ch * 32 + lane], __ldg(v + ch * 32 + lane), a);
            } else if (c == 128) {
#pragma unroll
                for (int ch = 0; ch < 4; ch++)
                    a = fmaf(g_U[r * LL + ch * 32 + lane], __ldg(Wq + ch * 32 + lane), a);
            } else {
#pragma unroll
                for (int ch = 0; ch < 4; ch++) {
                    int l = ch * 32 + lane;
                    a = fmaf(g_U[r * LL + l], g_vENC[l] + __ldg(bq + l), a);
                }
            }
#pragma unroll
            for (int o = 16; o; o >>= 1) a += __shfl_xor_sync(0xffffffffu, a, o);
            if (lane == 0) {
                a *= SCALE;
                if (c < 128) g_MqT[c * 160 + r] = a;
                else if (c == 128) g_Mqx[r] = a;
                else g_Mqc[r] = a;
            }
        }
    }
    gsync();

    float cv0 = g_cv[0];

    // ================= S5: mega-qck =================
    if (sw < S_LEN * BSZ) qck_task(sw >> 6, sw & 63, lane, s_hbuf + wid * 128, x, tgt);
    gsync();

    // ================= S6: mega-sdot (static cnt = 128*(s+1)), packed float2 =========
    for (int wt = sw; wt < S_LEN * 1024; wt += NWARP) {
        int s = wt >> 10;
        int rem = wt & 1023;
        int bg = rem & 15, gI = rem >> 4;
        int cnt = 128 * (s + 1);
        if (gI * 32 >= cnt) continue;
        int i = gI * 32 + lane;
        float mdv = g_memdotC[i];
        float ckr[4][4];
#pragma unroll
        for (int bb = 0; bb < 4; bb++)
#pragma unroll
            for (int j = 0; j < 4; j++)
                ckr[bb][j] = g_ckmS[(s * BSZ + bg * 4 + bb) * LL + j * 32 + lane];
        float acc[4] = {0.f, 0.f, 0.f, 0.f};
#pragma unroll
        for (int ch = 0; ch < 4; ch++) {
#pragma unroll 8
            for (int lo = 0; lo < 32; lo++) {
                float v = g_dmemT[(size_t)(ch * 32 + lo) * ND2 + i];
#pragma unroll
                for (int bb = 0; bb < 4; bb++)
                    acc[bb] = fmaf(__shfl_sync(0xffffffffu, ckr[bb][ch], lo), v, acc[bb]);
            }
        }
#pragma unroll
        for (int bb = 0; bb < 4; bb++)
            g_sdotS2[(size_t)(s * BSZ + bg * 4 + bb) * ND2 + i] = make_float2(acc[bb], mdv);
    }
    gsync();

    // ================= S7: mega-scores =================
    for (int wt = sw; wt < S_LEN * BSZ * NTILE; wt += NWARP) {
        int s = wt / (BSZ * NTILE);
        int rem = wt - s * (BSZ * NTILE);
        scores_task(s, rem & 63, rem >> 6, lane, x, t, mask, cv0);
    }
    gsync();

    // ================= S8: combine =================
    if (sw < S_LEN * BSZ) combine_warp(out, sw >> 6, sw & 63, lane);
}

// ---------------- host ----------------------------------------------------------------
extern "C" void kernel_launch(void* const* d_in, const int* in_sizes, int n_in,
                              void* d_out, int out_size) {
    const float* x       = (const float*)d_in[0];
    const float* t       = (const float*)d_in[1];
    const int*   src     = (const int*)d_in[2];
    const int*   tgt     = (const int*)d_in[3];
    const int*   mask    = (const int*)d_in[4];
    const float* time_w  = (const float*)d_in[5];
    const float* time_b  = (const float*)d_in[6];
    const float* W_ih    = (const float*)d_in[7];
    const float* W_hh    = (const float*)d_in[8];
    const float* b_ih    = (const float*)d_in[9];
    const float* b_hh    = (const float*)d_in[10];
    const float* Wq      = (const float*)d_in[11];
    const float* bq      = (const float*)d_in[12];
    const float* Wk      = (const float*)d_in[13];
    const float* bk      = (const float*)d_in[14];
    const float* Wv      = (const float*)d_in[15];
    const float* bv      = (const float*)d_in[16];
    const float* W_out   = (const float*)d_in[17];
    const float* b_out   = (const float*)d_in[18];

    k_persist<<<NBLK, NTHR>>>(x, t, src, tgt, mask, time_w, time_b,
                              W_ih, W_hh, b_ih, b_hh, Wq, bq, Wk, bk,
                              Wv, bv, W_out, b_out, (float*)d_out);
}